// round 3
// baseline (speedup 1.0000x reference)
#include <cuda_runtime.h>
#include <math.h>
#include <stdint.h>

typedef unsigned long long u64;

#define Bn 16
#define Cn 64
#define Hn 128
#define Wn 128
#define HWn (Hn*Wn)
#define IMG (Cn*HWn)

#define TH 8
#define TW 16
#define PR 10                    // u64 pairs per smem row (k=0..9)
#define CIN_PAIRS (10*PR)        // 100 u64 per channel (10 rows)
#define WCHUNK 32
#define SIN_B  (Cn*CIN_PAIRS*8)            // 51200 B
#define SWD_B  (WCHUNK*9*Cn*8)             // 147456 B
#define SMEM_CONV (SIN_B + SWD_B + Cn*8 + 2*Cn*4)

// scratch: per-layer post-ReLU features (also the concat inputs)
__device__ float g_feat[4][Bn*IMG];
__device__ float g_md[4][Cn];
__device__ float g_ms[4][Cn];

// ---------------- f32x2 packed-math helpers (sm_100+) ----------------------
__device__ __forceinline__ u64 dup2(float x){
    u64 r; asm("mov.b64 %0,{%1,%1};" : "=l"(r) : "f"(x)); return r;
}
__device__ __forceinline__ u64 pack2(float lo, float hi){
    u64 r; asm("mov.b64 %0,{%1,%2};" : "=l"(r) : "f"(lo), "f"(hi)); return r;
}
__device__ __forceinline__ void unpk(u64 v, float& a, float& b){
    asm("mov.b64 {%0,%1},%2;" : "=f"(a), "=f"(b) : "l"(v));
}
__device__ __forceinline__ u64 ffma2(u64 a, u64 b, u64 c){
    u64 d; asm("fma.rn.f32x2 %0,%1,%2,%3;" : "=l"(d) : "l"(a), "l"(b), "l"(c)); return d;
}
__device__ __forceinline__ u64 fmul2(u64 a, u64 b){
    u64 d; asm("mul.rn.f32x2 %0,%1,%2;" : "=l"(d) : "l"(a), "l"(b)); return d;
}
__device__ __forceinline__ u64 fadd2(u64 a, u64 b){
    u64 d; asm("add.rn.f32x2 %0,%1,%2;" : "=l"(d) : "l"(a), "l"(b)); return d;
}
__device__ __forceinline__ void ldsw(u64&a, u64&b, uint32_t addr){
    asm volatile("ld.shared.v2.u64 {%0,%1},[%2];" : "=l"(a),"=l"(b) : "r"(addr));
}
__device__ __forceinline__ u64 ldsu64(uint32_t addr){
    u64 r; asm volatile("ld.shared.b64 %0,[%1];" : "=l"(r) : "r"(addr)); return r;
}

// ---------------------------------------------------------------------------
// Gumbel-softmax channel mask
// ---------------------------------------------------------------------------
__global__ void mask_kernel(const float* __restrict__ gum,
                            const float* __restrict__ par,
                            float* __restrict__ out_tail)
{
    int c = threadIdx.x;
    if (c >= Cn) return;
#pragma unroll
    for (int l = 0; l < 4; ++l) {
        int i0 = c*8 + l*2;
        float g0 = -logf(-logf(gum[i0]));
        float g1 = -logf(-logf(gum[i0+1]));
        float l0 = par[i0]   + g0;
        float l1 = par[i0+1] + g1;
        float e  = expf(l1 - l0);
        float m0 = 1.0f/(1.0f+e);      // dense gate
        float m1 = e/(1.0f+e);         // sparse gate
        g_md[l][c] = m0;
        g_ms[l][c] = m1;
        out_tail[i0]   = m0;
        out_tail[i0+1] = m1;
    }
}

// ---------------------------------------------------------------------------
// 3x3 conv, pad 1, fused gating + ReLU, fully packed f32x2 (pixel pairs x,x+8).
//  DUAL=false (layer 0):  out = relu( F * (m_s[o]*spa + m_d[o]) )
//  DUAL=true  (layer>=1): out = relu( D * m_d[o]*(1-spa) + F * spa )
//    per-ci partial p = sum_kk w*in;  F += p;  D += m_d[ci]*p.
// Input smem pair-interleaved: s_in[c][r][k] = {in[x=k-1], in[x=k+7]} (u64).
// Weights pre-duplicated in smem as {w,w}. No per-iteration MOVs.
// Block: 64 och x 8x16 px. 512 thr: thread = 2 och x 4 pixel-pairs (8 px).
// ---------------------------------------------------------------------------
template<bool DUAL>
__global__ void __launch_bounds__(512, 1)
conv_kernel(const float* __restrict__ x0, const float* __restrict__ w,
            const float* __restrict__ spa, int layer)
{
    extern __shared__ char smraw[];
    u64*   s_in  = (u64*)smraw;                 // [c][10][PR]
    u64*   s_wd  = s_in + Cn*CIN_PAIRS;         // [(ci*9+kk)][o] dup'd
    u64*   s_md2 = s_wd + WCHUNK*9*Cn;          // [64] dup'd m_d
    float* s_md  = (float*)(s_md2 + Cn);
    float* s_ms  = s_md + Cn;

    const float* in  = (layer == 0) ? x0 : g_feat[layer-1];
    float*       out = g_feat[layer];

    const int b   = blockIdx.z;
    const int ty0 = blockIdx.y * TH;
    const int tx0 = blockIdx.x * TW;
    const int tid = threadIdx.x;

    if (tid < Cn) {
        float md = g_md[layer][tid];
        s_md[tid]  = md;
        s_ms[tid]  = g_ms[layer][tid];
        s_md2[tid] = dup2(md);
    }

    // stage input tile + halo, pair-interleaved {x, x+8}
    const float* inb = in + b*IMG;
#pragma unroll 1
    for (int idx = tid; idx < Cn*10*PR; idx += 512) {
        int c   = idx / 100;
        int rem = idx - c*100;
        int r   = rem / PR;
        int k   = rem - r*PR;
        int y  = ty0 - 1 + r;
        int xl = tx0 - 1 + k;
        int xh = xl + 8;
        float vl = 0.f, vh = 0.f;
        if ((unsigned)y < Hn) {
            const float* row = inb + (c*Hn + y)*Wn;
            if ((unsigned)xl < Wn) vl = row[xl];
            if ((unsigned)xh < Wn) vh = row[xh];
        }
        s_in[c*CIN_PAIRS + r*PR + k] = pack2(vl, vh);
    }

    const int og    = tid >> 4;          // 0..31  -> 2 och each
    const int pg    = tid & 15;
    const int py    = pg >> 1;           // 0..7
    const int pairb = (pg & 1) << 2;     // 0 or 4
    const int o0    = og << 1;

    const uint32_t in_sh  = (uint32_t)__cvta_generic_to_shared(s_in)
                          + (uint32_t)(py*PR + pairb)*8u;
    const uint32_t wd_sh  = (uint32_t)__cvta_generic_to_shared(s_wd)
                          + (uint32_t)o0*8u;
    const uint32_t md2_sh = (uint32_t)__cvta_generic_to_shared(s_md2);

    u64 accF[2][4], accD[2][4];
#pragma unroll
    for (int u = 0; u < 2; ++u)
#pragma unroll
        for (int j = 0; j < 4; ++j) { accF[u][j] = 0ull; if (DUAL) accD[u][j] = 0ull; }

    for (int cc0 = 0; cc0 < Cn; cc0 += WCHUNK) {
        __syncthreads();
        // stage dup'd weights: s_wd[(ci*9+kk)*64 + o] = {w,w}, w = w[o][cc0+ci][kk]
#pragma unroll 1
        for (int idx = tid; idx < WCHUNK*9*Cn; idx += 512) {
            int o = idx & 63;
            int r = idx >> 6;            // ci*9+kk
            s_wd[r*Cn + o] = dup2(w[o*(Cn*9) + cc0*9 + r]);
        }
        __syncthreads();

        uint32_t a_in = in_sh + (uint32_t)cc0*(CIN_PAIRS*8);
        uint32_t a_w  = wd_sh;
#pragma unroll 1
        for (int ci = 0; ci < WCHUNK; ++ci) {
            u64 p0_[4], p1_[4];
#pragma unroll
            for (int ky = 0; ky < 3; ++ky) {
                u64 P[6];
                ldsw(P[0], P[1], a_in + ky*(PR*8));
                ldsw(P[2], P[3], a_in + ky*(PR*8) + 16);
                ldsw(P[4], P[5], a_in + ky*(PR*8) + 32);
#pragma unroll
                for (int kx = 0; kx < 3; ++kx) {
                    u64 w0, w1;
                    ldsw(w0, w1, a_w + (ky*3 + kx)*(Cn*8));
                    if (DUAL) {
                        if (ky == 0 && kx == 0) {
#pragma unroll
                            for (int j = 0; j < 4; ++j) {
                                p0_[j] = fmul2(w0, P[j]);
                                p1_[j] = fmul2(w1, P[j]);
                            }
                        } else {
#pragma unroll
                            for (int j = 0; j < 4; ++j) {
                                p0_[j] = ffma2(w0, P[kx+j], p0_[j]);
                                p1_[j] = ffma2(w1, P[kx+j], p1_[j]);
                            }
                        }
                    } else {
#pragma unroll
                        for (int j = 0; j < 4; ++j) {
                            accF[0][j] = ffma2(w0, P[kx+j], accF[0][j]);
                            accF[1][j] = ffma2(w1, P[kx+j], accF[1][j]);
                        }
                    }
                }
            }
            if (DUAL) {
                u64 md2 = ldsu64(md2_sh + (uint32_t)(cc0+ci)*8u);
#pragma unroll
                for (int j = 0; j < 4; ++j) {
                    accF[0][j] = fadd2(accF[0][j], p0_[j]);
                    accD[0][j] = ffma2(md2, p0_[j], accD[0][j]);
                    accF[1][j] = fadd2(accF[1][j], p1_[j]);
                    accD[1][j] = ffma2(md2, p1_[j], accD[1][j]);
                }
            }
            a_in += CIN_PAIRS*8;
            a_w  += 9*Cn*8;
        }
    }

    // fused gating + ReLU epilogue (pairs = pixels x, x+8)
    const int y  = ty0 + py;
    const int xb = tx0 + pairb;
    const float4 splo = *(const float4*)(spa + b*HWn + y*Wn + xb);
    const float4 sphi = *(const float4*)(spa + b*HWn + y*Wn + xb + 8);
    const float spl[4] = {splo.x, splo.y, splo.z, splo.w};
    const float sph[4] = {sphi.x, sphi.y, sphi.z, sphi.w};
    float* outb = out + b*IMG + y*Wn + xb;

#pragma unroll
    for (int u = 0; u < 2; ++u) {
        const int o = o0 + u;
        const float md = s_md[o], ms = s_ms[o];
        float flo[4], fhi[4], dlo[4], dhi[4], rlo[4], rhi[4];
#pragma unroll
        for (int j = 0; j < 4; ++j) {
            unpk(accF[u][j], flo[j], fhi[j]);
            if (DUAL) unpk(accD[u][j], dlo[j], dhi[j]);
        }
#pragma unroll
        for (int j = 0; j < 4; ++j) {
            if (!DUAL) {
                rlo[j] = fmaxf(flo[j] * (ms*spl[j] + md), 0.f);
                rhi[j] = fmaxf(fhi[j] * (ms*sph[j] + md), 0.f);
            } else {
                rlo[j] = fmaxf(dlo[j]*md*(1.f - spl[j]) + flo[j]*spl[j], 0.f);
                rhi[j] = fmaxf(dhi[j]*md*(1.f - sph[j]) + fhi[j]*sph[j], 0.f);
            }
        }
        *(float4*)(outb + o*HWn)     = make_float4(rlo[0], rlo[1], rlo[2], rlo[3]);
        *(float4*)(outb + o*HWn + 8) = make_float4(rhi[0], rhi[1], rhi[2], rhi[3]);
    }
}

// ---------------------------------------------------------------------------
// Final 1x1 conv over the concat, pixel-paired f32x2.
// Block: 64 o x 256 px. 256 thr: thread = 8 o x 4 pixel-pairs (8 px).
// ---------------------------------------------------------------------------
__global__ void __launch_bounds__(256)
final_kernel(const float* __restrict__ wc, const float* __restrict__ bc,
             float* __restrict__ outp)
{
    __shared__ u64   s_wcd[16*64];   // [kk][o] dup'd
    __shared__ float s_cat[16*256];  // [kk][px]

    const int blk = blockIdx.x;
    const int b   = blk >> 6;
    const int p0  = (blk & 63) * 256;
    const int tid = threadIdx.x;
    const int og  = tid >> 5;        // 0..7
    const int pg  = tid & 31;
    const int o0  = og << 3;

    const uint32_t wsh = (uint32_t)__cvta_generic_to_shared(s_wcd) + (uint32_t)o0*8u;
    const uint32_t csh = (uint32_t)__cvta_generic_to_shared(s_cat) + (uint32_t)pg*8u;

    u64 acc[8][4];
#pragma unroll
    for (int u = 0; u < 8; ++u)
#pragma unroll
        for (int j = 0; j < 4; ++j) acc[u][j] = 0ull;

    for (int k0 = 0; k0 < 256; k0 += 16) {
        __syncthreads();
        for (int idx = tid; idx < 16*64; idx += 256) {
            int kk = idx >> 6, o = idx & 63;
            s_wcd[kk*64 + o] = dup2(wc[o*256 + k0 + kk]);
        }
        const float* src = g_feat[k0 >> 6] + (b*Cn + (k0 & 63))*HWn + p0;
        for (int idx = tid; idx < 16*256; idx += 256) {
            int kk = idx >> 8, px = idx & 255;
            s_cat[kk*256 + px] = src[kk*HWn + px];
        }
        __syncthreads();
#pragma unroll
        for (int kk = 0; kk < 16; ++kk) {
            u64 wv[8];
            ldsw(wv[0], wv[1], wsh + kk*512);
            ldsw(wv[2], wv[3], wsh + kk*512 + 16);
            ldsw(wv[4], wv[5], wsh + kk*512 + 32);
            ldsw(wv[6], wv[7], wsh + kk*512 + 48);
            u64 cv[4];
#pragma unroll
            for (int j = 0; j < 4; ++j)
                cv[j] = ldsu64(csh + kk*1024 + j*256);
#pragma unroll
            for (int u = 0; u < 8; ++u)
#pragma unroll
                for (int j = 0; j < 4; ++j)
                    acc[u][j] = ffma2(wv[u], cv[j], acc[u][j]);
        }
    }

#pragma unroll
    for (int u = 0; u < 8; ++u) {
        const int o = o0 + u;
        const u64 b2 = dup2(bc[o]);
        float* q = outp + (b*Cn + o)*HWn + p0;
#pragma unroll
        for (int j = 0; j < 4; ++j)
            *(u64*)(q + 2*(pg + 32*j)) = fadd2(acc[u][j], b2);
    }
}

// ---------------------------------------------------------------------------
extern "C" void kernel_launch(void* const* d_in, const int* in_sizes, int n_in,
                              void* d_out, int out_size)
{
    const float* x0  = (const float*)d_in[0];
    const float* spa = (const float*)d_in[1];
    const float* gum = (const float*)d_in[2];
    const float* par = (const float*)d_in[3];
    const float* w0  = (const float*)d_in[4];
    const float* w1  = (const float*)d_in[5];
    const float* w2  = (const float*)d_in[6];
    const float* w3  = (const float*)d_in[7];
    const float* wc  = (const float*)d_in[8];
    const float* bc  = (const float*)d_in[9];

    float* outp = (float*)d_out;
    float* tail = outp + (out_size - 512);   // ch_mask (1,64,4,2) after main out

    cudaFuncSetAttribute(conv_kernel<false>,
                         cudaFuncAttributeMaxDynamicSharedMemorySize, SMEM_CONV);
    cudaFuncSetAttribute(conv_kernel<true>,
                         cudaFuncAttributeMaxDynamicSharedMemorySize, SMEM_CONV);

    mask_kernel<<<1, 64>>>(gum, par, tail);

    dim3 grid(Wn/TW, Hn/TH, Bn);   // 8 x 16 x 16 = 2048 blocks
    conv_kernel<false><<<grid, 512, SMEM_CONV>>>(x0, w0, spa, 0);
    conv_kernel<true ><<<grid, 512, SMEM_CONV>>>(x0, w1, spa, 1);
    conv_kernel<true ><<<grid, 512, SMEM_CONV>>>(x0, w2, spa, 2);
    conv_kernel<true ><<<grid, 512, SMEM_CONV>>>(x0, w3, spa, 3);

    final_kernel<<<Bn*64, 256>>>(wc, bc, outp);
}

// round 4
// speedup vs baseline: 1.1799x; 1.1799x over previous
#include <cuda_runtime.h>
#include <math.h>
#include <stdint.h>

typedef unsigned long long u64;

#define Bn 16
#define Cn 64
#define Hn 128
#define Wn 128
#define HWn (Hn*Wn)
#define IMG (Cn*HWn)

#define TH 8
#define TW 8
#define KP 6                     // pair-cols per row (k = 0..5)
#define CIN_PAIRS (10*KP)        // 60 u64 per channel (10 rows)
#define WCHUNK 16
#define WP 66                    // padded o-stride in u64 (16B aligned)
#define SIN_B  (Cn*CIN_PAIRS*8)            // 30720 B
#define SWD_B  (WCHUNK*9*WP*8)             // 76032 B
#define SMEM_CONV (SIN_B + SWD_B + Cn*8 + 2*Cn*4)

// scratch: per-layer post-ReLU features (also the concat inputs)
__device__ float g_feat[4][Bn*IMG];
__device__ float g_md[4][Cn];
__device__ float g_ms[4][Cn];

// ---------------- f32x2 packed-math helpers (sm_100+) ----------------------
__device__ __forceinline__ u64 dup2(float x){
    u64 r; asm("mov.b64 %0,{%1,%1};" : "=l"(r) : "f"(x)); return r;
}
__device__ __forceinline__ u64 pack2(float lo, float hi){
    u64 r; asm("mov.b64 %0,{%1,%2};" : "=l"(r) : "f"(lo), "f"(hi)); return r;
}
__device__ __forceinline__ void unpk(u64 v, float& a, float& b){
    asm("mov.b64 {%0,%1},%2;" : "=f"(a), "=f"(b) : "l"(v));
}
__device__ __forceinline__ u64 ffma2(u64 a, u64 b, u64 c){
    u64 d; asm("fma.rn.f32x2 %0,%1,%2,%3;" : "=l"(d) : "l"(a), "l"(b), "l"(c)); return d;
}
__device__ __forceinline__ u64 fmul2(u64 a, u64 b){
    u64 d; asm("mul.rn.f32x2 %0,%1,%2;" : "=l"(d) : "l"(a), "l"(b)); return d;
}
__device__ __forceinline__ u64 fadd2(u64 a, u64 b){
    u64 d; asm("add.rn.f32x2 %0,%1,%2;" : "=l"(d) : "l"(a), "l"(b)); return d;
}
__device__ __forceinline__ void ldsw(u64&a, u64&b, uint32_t addr){
    asm volatile("ld.shared.v2.u64 {%0,%1},[%2];" : "=l"(a),"=l"(b) : "r"(addr));
}
__device__ __forceinline__ u64 ldsu64(uint32_t addr){
    u64 r; asm volatile("ld.shared.b64 %0,[%1];" : "=l"(r) : "r"(addr)); return r;
}

// ---------------------------------------------------------------------------
// Gumbel-softmax channel mask
// ---------------------------------------------------------------------------
__global__ void mask_kernel(const float* __restrict__ gum,
                            const float* __restrict__ par,
                            float* __restrict__ out_tail)
{
    int c = threadIdx.x;
    if (c >= Cn) return;
#pragma unroll
    for (int l = 0; l < 4; ++l) {
        int i0 = c*8 + l*2;
        float g0 = -logf(-logf(gum[i0]));
        float g1 = -logf(-logf(gum[i0+1]));
        float l0 = par[i0]   + g0;
        float l1 = par[i0+1] + g1;
        float e  = expf(l1 - l0);
        float m0 = 1.0f/(1.0f+e);      // dense gate
        float m1 = e/(1.0f+e);         // sparse gate
        g_md[l][c] = m0;
        g_ms[l][c] = m1;
        out_tail[i0]   = m0;
        out_tail[i0+1] = m1;
    }
}

// ---------------------------------------------------------------------------
// 3x3 conv, pad 1, fused gating + ReLU, f32x2 pixel pairs {x, x+4}.
//  DUAL=false (layer 0):  out = relu( F * (m_s[o]*spa + m_d[o]) )
//  DUAL=true  (layer>=1): out = relu( D * m_d[o]*(1-spa) + F * spa )
//    per-ci partial p = sum_kk w*in;  F += p;  D += m_d[ci]*p.
// Input smem: s_in[c][r][k] = {in[x0-1+k], in[x0+3+k]}, r=0..9, k=0..5.
// Weights pre-duplicated {w,w} in smem, padded stride WP.
// Block: 64 och x 8x8 px, 256 threads: thread = 2 och x 1 row (4 pairs).
// ---------------------------------------------------------------------------
template<bool DUAL>
__global__ void __launch_bounds__(256, 2)
conv_kernel(const float* __restrict__ x0, const float* __restrict__ w,
            const float* __restrict__ spa, int layer)
{
    extern __shared__ char smraw[];
    u64*   s_in  = (u64*)smraw;                 // [c][10][KP]
    u64*   s_wd  = s_in + Cn*CIN_PAIRS;         // [(ci*9+kk)][WP] dup'd
    u64*   s_md2 = s_wd + WCHUNK*9*WP;          // [64] dup'd m_d
    float* s_md  = (float*)(s_md2 + Cn);
    float* s_ms  = s_md + Cn;

    const float* in  = (layer == 0) ? x0 : g_feat[layer-1];
    float*       out = g_feat[layer];

    const int b   = blockIdx.z;
    const int ty0 = blockIdx.y * TH;
    const int tx0 = blockIdx.x * TW;
    const int tid = threadIdx.x;

    if (tid < Cn) {
        float md = g_md[layer][tid];
        s_md[tid]  = md;
        s_ms[tid]  = g_ms[layer][tid];
        s_md2[tid] = dup2(md);
    }

    // stage input tile + halo, pair-interleaved {x, x+4}
    const float* inb = in + b*IMG;
#pragma unroll 1
    for (int idx = tid; idx < Cn*10*KP; idx += 256) {
        int c   = idx / (10*KP);
        int rem = idx - c*(10*KP);
        int r   = rem / KP;
        int k   = rem - r*KP;
        int y  = ty0 - 1 + r;
        int xl = tx0 - 1 + k;
        int xh = xl + 4;
        float vl = 0.f, vh = 0.f;
        if ((unsigned)y < Hn) {
            const float* row = inb + (c*Hn + y)*Wn;
            if ((unsigned)xl < Wn) vl = row[xl];
            if ((unsigned)xh < Wn) vh = row[xh];
        }
        s_in[c*CIN_PAIRS + r*KP + k] = pack2(vl, vh);
    }

    const int og = tid >> 3;           // 0..31 -> och {2og, 2og+1}
    const int py = tid & 7;            // row within tile
    const int o0 = og << 1;

    const uint32_t in_sh  = (uint32_t)__cvta_generic_to_shared(s_in)
                          + (uint32_t)(py*KP)*8u;
    const uint32_t wd_sh  = (uint32_t)__cvta_generic_to_shared(s_wd)
                          + (uint32_t)o0*8u;
    const uint32_t md2_sh = (uint32_t)__cvta_generic_to_shared(s_md2);

    u64 accF[2][4], accD[2][4];
#pragma unroll
    for (int u = 0; u < 2; ++u)
#pragma unroll
        for (int j = 0; j < 4; ++j) { accF[u][j] = 0ull; if (DUAL) accD[u][j] = 0ull; }

    for (int cc0 = 0; cc0 < Cn; cc0 += WCHUNK) {
        __syncthreads();
        // stage dup'd weights: s_wd[r*WP + o] = {w,w}, w = w[o][cc0+ci][kk], r=ci*9+kk
        // (r-major per thread -> coalesced LDG runs of 144 floats)
#pragma unroll 1
        for (int idx = tid; idx < WCHUNK*9*Cn; idx += 256) {
            int o = idx / (WCHUNK*9);
            int r = idx - o*(WCHUNK*9);
            s_wd[r*WP + o] = dup2(w[o*(Cn*9) + cc0*9 + r]);
        }
        __syncthreads();

        uint32_t a_in = in_sh + (uint32_t)cc0*(CIN_PAIRS*8);
        uint32_t a_w  = wd_sh;
#pragma unroll 1
        for (int ci = 0; ci < WCHUNK; ++ci) {
            u64 p0_[4], p1_[4];
#pragma unroll
            for (int ky = 0; ky < 3; ++ky) {
                u64 P[6];
                ldsw(P[0], P[1], a_in + ky*(KP*8));
                ldsw(P[2], P[3], a_in + ky*(KP*8) + 16);
                ldsw(P[4], P[5], a_in + ky*(KP*8) + 32);
#pragma unroll
                for (int kx = 0; kx < 3; ++kx) {
                    u64 w0, w1;
                    ldsw(w0, w1, a_w + (ky*3 + kx)*(WP*8));
                    if (DUAL) {
                        if (ky == 0 && kx == 0) {
#pragma unroll
                            for (int j = 0; j < 4; ++j) {
                                p0_[j] = fmul2(w0, P[j]);
                                p1_[j] = fmul2(w1, P[j]);
                            }
                        } else {
#pragma unroll
                            for (int j = 0; j < 4; ++j) {
                                p0_[j] = ffma2(w0, P[kx+j], p0_[j]);
                                p1_[j] = ffma2(w1, P[kx+j], p1_[j]);
                            }
                        }
                    } else {
#pragma unroll
                        for (int j = 0; j < 4; ++j) {
                            accF[0][j] = ffma2(w0, P[kx+j], accF[0][j]);
                            accF[1][j] = ffma2(w1, P[kx+j], accF[1][j]);
                        }
                    }
                }
            }
            if (DUAL) {
                u64 md2 = ldsu64(md2_sh + (uint32_t)(cc0+ci)*8u);
#pragma unroll
                for (int j = 0; j < 4; ++j) {
                    accF[0][j] = fadd2(accF[0][j], p0_[j]);
                    accD[0][j] = ffma2(md2, p0_[j], accD[0][j]);
                    accF[1][j] = fadd2(accF[1][j], p1_[j]);
                    accD[1][j] = ffma2(md2, p1_[j], accD[1][j]);
                }
            }
            a_in += CIN_PAIRS*8;
            a_w  += 9*WP*8;
        }
    }

    // fused gating + ReLU epilogue (pairs: lo = x0+j, hi = x0+j+4)
    const int y = ty0 + py;
    const float4 splo = *(const float4*)(spa + b*HWn + y*Wn + tx0);
    const float4 sphi = *(const float4*)(spa + b*HWn + y*Wn + tx0 + 4);
    const float spl[4] = {splo.x, splo.y, splo.z, splo.w};
    const float sph[4] = {sphi.x, sphi.y, sphi.z, sphi.w};
    float* outb = out + b*IMG + y*Wn + tx0;

#pragma unroll
    for (int u = 0; u < 2; ++u) {
        const int o = o0 + u;
        const float md = s_md[o], ms = s_ms[o];
        float flo[4], fhi[4], dlo[4], dhi[4], rlo[4], rhi[4];
#pragma unroll
        for (int j = 0; j < 4; ++j) {
            unpk(accF[u][j], flo[j], fhi[j]);
            if (DUAL) unpk(accD[u][j], dlo[j], dhi[j]);
        }
#pragma unroll
        for (int j = 0; j < 4; ++j) {
            if (!DUAL) {
                rlo[j] = fmaxf(flo[j] * (ms*spl[j] + md), 0.f);
                rhi[j] = fmaxf(fhi[j] * (ms*sph[j] + md), 0.f);
            } else {
                rlo[j] = fmaxf(dlo[j]*md*(1.f - spl[j]) + flo[j]*spl[j], 0.f);
                rhi[j] = fmaxf(dhi[j]*md*(1.f - sph[j]) + fhi[j]*sph[j], 0.f);
            }
        }
        *(float4*)(outb + o*HWn)     = make_float4(rlo[0], rlo[1], rlo[2], rlo[3]);
        *(float4*)(outb + o*HWn + 4) = make_float4(rhi[0], rhi[1], rhi[2], rhi[3]);
    }
}

// ---------------------------------------------------------------------------
// Final 1x1 conv over the concat, pixel-paired f32x2.
// Block: 64 o x 256 px. 256 thr: thread = 8 o x 4 pixel-pairs (8 px).
// ---------------------------------------------------------------------------
__global__ void __launch_bounds__(256)
final_kernel(const float* __restrict__ wc, const float* __restrict__ bc,
             float* __restrict__ outp)
{
    __shared__ u64   s_wcd[16*64];   // [kk][o] dup'd
    __shared__ float s_cat[16*256];  // [kk][px]

    const int blk = blockIdx.x;
    const int b   = blk >> 6;
    const int p0  = (blk & 63) * 256;
    const int tid = threadIdx.x;
    const int og  = tid >> 5;        // 0..7
    const int pg  = tid & 31;
    const int o0  = og << 3;

    const uint32_t wsh = (uint32_t)__cvta_generic_to_shared(s_wcd) + (uint32_t)o0*8u;
    const uint32_t csh = (uint32_t)__cvta_generic_to_shared(s_cat) + (uint32_t)pg*8u;

    u64 acc[8][4];
#pragma unroll
    for (int u = 0; u < 8; ++u)
#pragma unroll
        for (int j = 0; j < 4; ++j) acc[u][j] = 0ull;

    for (int k0 = 0; k0 < 256; k0 += 16) {
        __syncthreads();
        for (int idx = tid; idx < 16*64; idx += 256) {
            int kk = idx >> 6, o = idx & 63;
            s_wcd[kk*64 + o] = dup2(wc[o*256 + k0 + kk]);
        }
        const float* src = g_feat[k0 >> 6] + (b*Cn + (k0 & 63))*HWn + p0;
        for (int idx = tid; idx < 16*256; idx += 256) {
            int kk = idx >> 8, px = idx & 255;
            s_cat[kk*256 + px] = src[kk*HWn + px];
        }
        __syncthreads();
#pragma unroll
        for (int kk = 0; kk < 16; ++kk) {
            u64 wv[8];
            ldsw(wv[0], wv[1], wsh + kk*512);
            ldsw(wv[2], wv[3], wsh + kk*512 + 16);
            ldsw(wv[4], wv[5], wsh + kk*512 + 32);
            ldsw(wv[6], wv[7], wsh + kk*512 + 48);
            u64 cv[4];
#pragma unroll
            for (int j = 0; j < 4; ++j)
                cv[j] = ldsu64(csh + kk*1024 + j*256);
#pragma unroll
            for (int u = 0; u < 8; ++u)
#pragma unroll
                for (int j = 0; j < 4; ++j)
                    acc[u][j] = ffma2(wv[u], cv[j], acc[u][j]);
        }
    }

#pragma unroll
    for (int u = 0; u < 8; ++u) {
        const int o = o0 + u;
        const u64 b2 = dup2(bc[o]);
        float* q = outp + (b*Cn + o)*HWn + p0;
#pragma unroll
        for (int j = 0; j < 4; ++j)
            *(u64*)(q + 2*(pg + 32*j)) = fadd2(acc[u][j], b2);
    }
}

// ---------------------------------------------------------------------------
extern "C" void kernel_launch(void* const* d_in, const int* in_sizes, int n_in,
                              void* d_out, int out_size)
{
    const float* x0  = (const float*)d_in[0];
    const float* spa = (const float*)d_in[1];
    const float* gum = (const float*)d_in[2];
    const float* par = (const float*)d_in[3];
    const float* w0  = (const float*)d_in[4];
    const float* w1  = (const float*)d_in[5];
    const float* w2  = (const float*)d_in[6];
    const float* w3  = (const float*)d_in[7];
    const float* wc  = (const float*)d_in[8];
    const float* bc  = (const float*)d_in[9];

    float* outp = (float*)d_out;
    float* tail = outp + (out_size - 512);   // ch_mask (1,64,4,2) after main out

    cudaFuncSetAttribute(conv_kernel<false>,
                         cudaFuncAttributeMaxDynamicSharedMemorySize, SMEM_CONV);
    cudaFuncSetAttribute(conv_kernel<true>,
                         cudaFuncAttributeMaxDynamicSharedMemorySize, SMEM_CONV);

    mask_kernel<<<1, 64>>>(gum, par, tail);

    dim3 grid(Wn/TW, Hn/TH, Bn);   // 16 x 16 x 16 = 4096 blocks
    conv_kernel<false><<<grid, 256, SMEM_CONV>>>(x0, w0, spa, 0);
    conv_kernel<true ><<<grid, 256, SMEM_CONV>>>(x0, w1, spa, 1);
    conv_kernel<true ><<<grid, 256, SMEM_CONV>>>(x0, w2, spa, 2);
    conv_kernel<true ><<<grid, 256, SMEM_CONV>>>(x0, w3, spa, 3);

    final_kernel<<<Bn*64, 256>>>(wc, bc, outp);
}

// round 5
// speedup vs baseline: 1.1807x; 1.0007x over previous
#include <cuda_runtime.h>
#include <math.h>
#include <stdint.h>

typedef unsigned long long u64;

#define Bn 16
#define Cn 64
#define Hn 128
#define Wn 128
#define HWn (Hn*Wn)
#define IMG (Cn*HWn)

#define TH 8
#define TW 8
#define KP 6                     // pair-cols per row (k = 0..5)
#define CIN_PAIRS (10*KP)        // 60 u64 per channel (10 rows)
#define WCHUNK 16
#define WP 66                    // padded o-stride in u64 (16B aligned)
#define SIN_B  (Cn*CIN_PAIRS*8)            // 30720 B
#define SWD_B  (WCHUNK*9*WP*8)             // 76032 B
#define SMEM_CONV (SIN_B + SWD_B + Cn*8 + 2*Cn*4)

// scratch: per-layer post-ReLU features (also the concat inputs)
__device__ float g_feat[4][Bn*IMG];
__device__ float g_md[4][Cn];
__device__ float g_ms[4][Cn];

// ---------------- f32x2 packed-math helpers (sm_100+) ----------------------
__device__ __forceinline__ u64 dup2(float x){
    u64 r; asm("mov.b64 %0,{%1,%1};" : "=l"(r) : "f"(x)); return r;
}
__device__ __forceinline__ u64 pack2(float lo, float hi){
    u64 r; asm("mov.b64 %0,{%1,%2};" : "=l"(r) : "f"(lo), "f"(hi)); return r;
}
__device__ __forceinline__ void unpk(u64 v, float& a, float& b){
    asm("mov.b64 {%0,%1},%2;" : "=f"(a), "=f"(b) : "l"(v));
}
__device__ __forceinline__ u64 ffma2(u64 a, u64 b, u64 c){
    u64 d; asm("fma.rn.f32x2 %0,%1,%2,%3;" : "=l"(d) : "l"(a), "l"(b), "l"(c)); return d;
}
__device__ __forceinline__ u64 fmul2(u64 a, u64 b){
    u64 d; asm("mul.rn.f32x2 %0,%1,%2;" : "=l"(d) : "l"(a), "l"(b)); return d;
}
__device__ __forceinline__ u64 fadd2(u64 a, u64 b){
    u64 d; asm("add.rn.f32x2 %0,%1,%2;" : "=l"(d) : "l"(a), "l"(b)); return d;
}
__device__ __forceinline__ void ldsw(u64&a, u64&b, uint32_t addr){
    asm volatile("ld.shared.v2.u64 {%0,%1},[%2];" : "=l"(a),"=l"(b) : "r"(addr));
}
__device__ __forceinline__ u64 ldsu64(uint32_t addr){
    u64 r; asm volatile("ld.shared.b64 %0,[%1];" : "=l"(r) : "r"(addr)); return r;
}

// ---------------------------------------------------------------------------
// Gumbel-softmax channel mask
// ---------------------------------------------------------------------------
__global__ void mask_kernel(const float* __restrict__ gum,
                            const float* __restrict__ par,
                            float* __restrict__ out_tail)
{
    int c = threadIdx.x;
    if (c >= Cn) return;
#pragma unroll
    for (int l = 0; l < 4; ++l) {
        int i0 = c*8 + l*2;
        float g0 = -logf(-logf(gum[i0]));
        float g1 = -logf(-logf(gum[i0+1]));
        float l0 = par[i0]   + g0;
        float l1 = par[i0+1] + g1;
        float e  = expf(l1 - l0);
        float m0 = 1.0f/(1.0f+e);      // dense gate
        float m1 = e/(1.0f+e);         // sparse gate
        g_md[l][c] = m0;
        g_ms[l][c] = m1;
        out_tail[i0]   = m0;
        out_tail[i0+1] = m1;
    }
}

// ---------------------------------------------------------------------------
// 3x3 conv, pad 1, fused gating + ReLU, f32x2 pixel pairs {x, x+4}.
//  DUAL=false (layer 0):  out = relu( F * (m_s[o]*spa + m_d[o]) )
//  DUAL=true  (layer>=1): out = relu( D * m_d[o]*(1-spa) + F * spa )
//    per-ci partial p = sum_kk w*in;  F += p;  D += m_d[ci]*p.
// Input smem: s_in[c][r][k] = {in[x0-1+k], in[x0+3+k]}, r=0..9, k=0..5.
// Weights pre-duplicated {w,w} in smem, padded stride WP.
// Block: 64 och x 8x8 px, 256 threads: thread = 2 och x 1 row (4 pairs).
// ---------------------------------------------------------------------------
template<bool DUAL>
__global__ void __launch_bounds__(256, 2)
conv_kernel(const float* __restrict__ x0, const float* __restrict__ w,
            const float* __restrict__ spa, int layer)
{
    extern __shared__ char smraw[];
    u64*   s_in  = (u64*)smraw;                 // [c][10][KP]
    u64*   s_wd  = s_in + Cn*CIN_PAIRS;         // [(ci*9+kk)][WP] dup'd
    u64*   s_md2 = s_wd + WCHUNK*9*WP;          // [64] dup'd m_d
    float* s_md  = (float*)(s_md2 + Cn);
    float* s_ms  = s_md + Cn;

    const float* in  = (layer == 0) ? x0 : g_feat[layer-1];
    float*       out = g_feat[layer];

    const int b   = blockIdx.z;
    const int ty0 = blockIdx.y * TH;
    const int tx0 = blockIdx.x * TW;
    const int tid = threadIdx.x;

    if (tid < Cn) {
        float md = g_md[layer][tid];
        s_md[tid]  = md;
        s_ms[tid]  = g_ms[layer][tid];
        s_md2[tid] = dup2(md);
    }

    // stage input tile + halo, pair-interleaved {x, x+4}
    const float* inb = in + b*IMG;
#pragma unroll 1
    for (int idx = tid; idx < Cn*10*KP; idx += 256) {
        int c   = idx / (10*KP);
        int rem = idx - c*(10*KP);
        int r   = rem / KP;
        int k   = rem - r*KP;
        int y  = ty0 - 1 + r;
        int xl = tx0 - 1 + k;
        int xh = xl + 4;
        float vl = 0.f, vh = 0.f;
        if ((unsigned)y < Hn) {
            const float* row = inb + (c*Hn + y)*Wn;
            if ((unsigned)xl < Wn) vl = row[xl];
            if ((unsigned)xh < Wn) vh = row[xh];
        }
        s_in[c*CIN_PAIRS + r*KP + k] = pack2(vl, vh);
    }

    const int og = tid >> 3;           // 0..31 -> och {2og, 2og+1}
    const int py = tid & 7;            // row within tile
    const int o0 = og << 1;

    const uint32_t in_sh  = (uint32_t)__cvta_generic_to_shared(s_in)
                          + (uint32_t)(py*KP)*8u;
    const uint32_t wd_sh  = (uint32_t)__cvta_generic_to_shared(s_wd)
                          + (uint32_t)o0*8u;
    const uint32_t md2_sh = (uint32_t)__cvta_generic_to_shared(s_md2);

    u64 accF[2][4], accD[2][4];
#pragma unroll
    for (int u = 0; u < 2; ++u)
#pragma unroll
        for (int j = 0; j < 4; ++j) { accF[u][j] = 0ull; if (DUAL) accD[u][j] = 0ull; }

    for (int cc0 = 0; cc0 < Cn; cc0 += WCHUNK) {
        __syncthreads();
        // stage dup'd weights: s_wd[r*WP + o] = {w,w}, w = w[o][cc0+ci][kk], r=ci*9+kk
        // (r-major per thread -> coalesced LDG runs of 144 floats)
#pragma unroll 1
        for (int idx = tid; idx < WCHUNK*9*Cn; idx += 256) {
            int o = idx / (WCHUNK*9);
            int r = idx - o*(WCHUNK*9);
            s_wd[r*WP + o] = dup2(w[o*(Cn*9) + cc0*9 + r]);
        }
        __syncthreads();

        uint32_t a_in = in_sh + (uint32_t)cc0*(CIN_PAIRS*8);
        uint32_t a_w  = wd_sh;
#pragma unroll 1
        for (int ci = 0; ci < WCHUNK; ++ci) {
            u64 p0_[4], p1_[4];
#pragma unroll
            for (int ky = 0; ky < 3; ++ky) {
                u64 P[6];
                ldsw(P[0], P[1], a_in + ky*(KP*8));
                ldsw(P[2], P[3], a_in + ky*(KP*8) + 16);
                ldsw(P[4], P[5], a_in + ky*(KP*8) + 32);
#pragma unroll
                for (int kx = 0; kx < 3; ++kx) {
                    u64 w0, w1;
                    ldsw(w0, w1, a_w + (ky*3 + kx)*(WP*8));
                    if (DUAL) {
                        if (ky == 0 && kx == 0) {
#pragma unroll
                            for (int j = 0; j < 4; ++j) {
                                p0_[j] = fmul2(w0, P[j]);
                                p1_[j] = fmul2(w1, P[j]);
                            }
                        } else {
#pragma unroll
                            for (int j = 0; j < 4; ++j) {
                                p0_[j] = ffma2(w0, P[kx+j], p0_[j]);
                                p1_[j] = ffma2(w1, P[kx+j], p1_[j]);
                            }
                        }
                    } else {
#pragma unroll
                        for (int j = 0; j < 4; ++j) {
                            accF[0][j] = ffma2(w0, P[kx+j], accF[0][j]);
                            accF[1][j] = ffma2(w1, P[kx+j], accF[1][j]);
                        }
                    }
                }
            }
            if (DUAL) {
                u64 md2 = ldsu64(md2_sh + (uint32_t)(cc0+ci)*8u);
#pragma unroll
                for (int j = 0; j < 4; ++j) {
                    accF[0][j] = fadd2(accF[0][j], p0_[j]);
                    accD[0][j] = ffma2(md2, p0_[j], accD[0][j]);
                    accF[1][j] = fadd2(accF[1][j], p1_[j]);
                    accD[1][j] = ffma2(md2, p1_[j], accD[1][j]);
                }
            }
            a_in += CIN_PAIRS*8;
            a_w  += 9*WP*8;
        }
    }

    // fused gating + ReLU epilogue (pairs: lo = x0+j, hi = x0+j+4)
    const int y = ty0 + py;
    const float4 splo = *(const float4*)(spa + b*HWn + y*Wn + tx0);
    const float4 sphi = *(const float4*)(spa + b*HWn + y*Wn + tx0 + 4);
    const float spl[4] = {splo.x, splo.y, splo.z, splo.w};
    const float sph[4] = {sphi.x, sphi.y, sphi.z, sphi.w};
    float* outb = out + b*IMG + y*Wn + tx0;

#pragma unroll
    for (int u = 0; u < 2; ++u) {
        const int o = o0 + u;
        const float md = s_md[o], ms = s_ms[o];
        float flo[4], fhi[4], dlo[4], dhi[4], rlo[4], rhi[4];
#pragma unroll
        for (int j = 0; j < 4; ++j) {
            unpk(accF[u][j], flo[j], fhi[j]);
            if (DUAL) unpk(accD[u][j], dlo[j], dhi[j]);
        }
#pragma unroll
        for (int j = 0; j < 4; ++j) {
            if (!DUAL) {
                rlo[j] = fmaxf(flo[j] * (ms*spl[j] + md), 0.f);
                rhi[j] = fmaxf(fhi[j] * (ms*sph[j] + md), 0.f);
            } else {
                rlo[j] = fmaxf(dlo[j]*md*(1.f - spl[j]) + flo[j]*spl[j], 0.f);
                rhi[j] = fmaxf(dhi[j]*md*(1.f - sph[j]) + fhi[j]*sph[j], 0.f);
            }
        }
        *(float4*)(outb + o*HWn)     = make_float4(rlo[0], rlo[1], rlo[2], rlo[3]);
        *(float4*)(outb + o*HWn + 4) = make_float4(rhi[0], rhi[1], rhi[2], rhi[3]);
    }
}

// ---------------------------------------------------------------------------
// Final 1x1 conv over the concat, pixel-paired f32x2.
// Block: 64 o x 256 px. 256 thr: thread = 8 o x 4 pixel-pairs (8 px).
// ---------------------------------------------------------------------------
__global__ void __launch_bounds__(256)
final_kernel(const float* __restrict__ wc, const float* __restrict__ bc,
             float* __restrict__ outp)
{
    __shared__ u64   s_wcd[16*64];   // [kk][o] dup'd
    __shared__ float s_cat[16*256];  // [kk][px]

    const int blk = blockIdx.x;
    const int b   = blk >> 6;
    const int p0  = (blk & 63) * 256;
    const int tid = threadIdx.x;
    const int og  = tid >> 5;        // 0..7
    const int pg  = tid & 31;
    const int o0  = og << 3;

    const uint32_t wsh = (uint32_t)__cvta_generic_to_shared(s_wcd) + (uint32_t)o0*8u;
    const uint32_t csh = (uint32_t)__cvta_generic_to_shared(s_cat) + (uint32_t)pg*8u;

    u64 acc[8][4];
#pragma unroll
    for (int u = 0; u < 8; ++u)
#pragma unroll
        for (int j = 0; j < 4; ++j) acc[u][j] = 0ull;

    for (int k0 = 0; k0 < 256; k0 += 16) {
        __syncthreads();
        for (int idx = tid; idx < 16*64; idx += 256) {
            int kk = idx >> 6, o = idx & 63;
            s_wcd[kk*64 + o] = dup2(wc[o*256 + k0 + kk]);
        }
        const float* src = g_feat[k0 >> 6] + (b*Cn + (k0 & 63))*HWn + p0;
        for (int idx = tid; idx < 16*256; idx += 256) {
            int kk = idx >> 8, px = idx & 255;
            s_cat[kk*256 + px] = src[kk*HWn + px];
        }
        __syncthreads();
#pragma unroll
        for (int kk = 0; kk < 16; ++kk) {
            u64 wv[8];
            ldsw(wv[0], wv[1], wsh + kk*512);
            ldsw(wv[2], wv[3], wsh + kk*512 + 16);
            ldsw(wv[4], wv[5], wsh + kk*512 + 32);
            ldsw(wv[6], wv[7], wsh + kk*512 + 48);
            u64 cv[4];
#pragma unroll
            for (int j = 0; j < 4; ++j)
                cv[j] = ldsu64(csh + kk*1024 + j*256);
#pragma unroll
            for (int u = 0; u < 8; ++u)
#pragma unroll
                for (int j = 0; j < 4; ++j)
                    acc[u][j] = ffma2(wv[u], cv[j], acc[u][j]);
        }
    }

#pragma unroll
    for (int u = 0; u < 8; ++u) {
        const int o = o0 + u;
        const u64 b2 = dup2(bc[o]);
        float* q = outp + (b*Cn + o)*HWn + p0;
#pragma unroll
        for (int j = 0; j < 4; ++j)
            *(u64*)(q + 2*(pg + 32*j)) = fadd2(acc[u][j], b2);
    }
}

// ---------------------------------------------------------------------------
extern "C" void kernel_launch(void* const* d_in, const int* in_sizes, int n_in,
                              void* d_out, int out_size)
{
    const float* x0  = (const float*)d_in[0];
    const float* spa = (const float*)d_in[1];
    const float* gum = (const float*)d_in[2];
    const float* par = (const float*)d_in[3];
    const float* w0  = (const float*)d_in[4];
    const float* w1  = (const float*)d_in[5];
    const float* w2  = (const float*)d_in[6];
    const float* w3  = (const float*)d_in[7];
    const float* wc  = (const float*)d_in[8];
    const float* bc  = (const float*)d_in[9];

    float* outp = (float*)d_out;
    float* tail = outp + (out_size - 512);   // ch_mask (1,64,4,2) after main out

    cudaFuncSetAttribute(conv_kernel<false>,
                         cudaFuncAttributeMaxDynamicSharedMemorySize, SMEM_CONV);
    cudaFuncSetAttribute(conv_kernel<true>,
                         cudaFuncAttributeMaxDynamicSharedMemorySize, SMEM_CONV);

    mask_kernel<<<1, 64>>>(gum, par, tail);

    dim3 grid(Wn/TW, Hn/TH, Bn);   // 16 x 16 x 16 = 4096 blocks
    conv_kernel<false><<<grid, 256, SMEM_CONV>>>(x0, w0, spa, 0);
    conv_kernel<true ><<<grid, 256, SMEM_CONV>>>(x0, w1, spa, 1);
    conv_kernel<true ><<<grid, 256, SMEM_CONV>>>(x0, w2, spa, 2);
    conv_kernel<true ><<<grid, 256, SMEM_CONV>>>(x0, w3, spa, 3);

    final_kernel<<<Bn*64, 256>>>(wc, bc, outp);
}

// round 7
// speedup vs baseline: 1.7531x; 1.4848x over previous
#include <cuda_runtime.h>
#include <cuda_bf16.h>
#include <math.h>
#include <stdint.h>

typedef unsigned long long u64;
typedef unsigned int u32;

#define Bn 16
#define Cn 64
#define Hn 128
#define Wn 128
#define HWn (Hn*Wn)
#define IMG (Cn*HWn)

// scratch
__device__ float g_feat[4][Bn*IMG];
__device__ float g_md[4][Cn];
__device__ float g_ms[4][Cn];
// split weights: [layer][tap][kind: 0=hi,1=lo,2=md*hi,3=md*lo][o*64+ci] bf16
__device__ __nv_bfloat16 g_wt[4][9][4][Cn*Cn];

// ---------------- smem layout for conv_mma (bytes) ---------------------------
// s_px[row 0..3][xp 0..129]: 272B per xp = 128B hi(64 bf16) + 128B lo + 16B pad
#define PX_XP_STRIDE 272
#define PX_ROW_STRIDE (130*PX_XP_STRIDE)       // 35360
#define OFF_PX 0
#define PX_BYTES (4*PX_ROW_STRIDE)             // 141440
// s_w[kind 0..3][o 0..63]: 144B per o (64 bf16 + pad); kind stride 9216
#define OFF_W  PX_BYTES
#define W_O_STRIDE 144
#define W_KIND_STRIDE (64*W_O_STRIDE)          // 9216
#define W_BYTES (4*W_KIND_STRIDE)              // 36864
#define OFF_MD (OFF_W + W_BYTES)               // 178304
#define OFF_MS (OFF_MD + 256)
#define SMEM_MMA (OFF_MS + 256)                // 178816

// ---------------- warp-mma helpers (baseline PTX, no 'a' features) -----------
__device__ __forceinline__ void mma16816(float* c, const u32* a, u32 b0, u32 b1){
    asm volatile(
        "mma.sync.aligned.m16n8k16.row.col.f32.bf16.bf16.f32 "
        "{%0,%1,%2,%3},{%4,%5,%6,%7},{%8,%9},{%0,%1,%2,%3};"
        : "+f"(c[0]),"+f"(c[1]),"+f"(c[2]),"+f"(c[3])
        : "r"(a[0]),"r"(a[1]),"r"(a[2]),"r"(a[3]), "r"(b0),"r"(b1));
}
__device__ __forceinline__ void ldmat4(u32* r, u32 addr){
    asm volatile("ldmatrix.sync.aligned.m8n8.x4.shared.b16 {%0,%1,%2,%3},[%4];"
                 : "=r"(r[0]),"=r"(r[1]),"=r"(r[2]),"=r"(r[3]) : "r"(addr));
}
__device__ __forceinline__ u32 ldsu32(u32 addr){
    u32 r; asm volatile("ld.shared.b32 %0,[%1];" : "=r"(r) : "r"(addr)); return r;
}

// ---------------- f32x2 helpers (final 1x1 kernel) ---------------------------
__device__ __forceinline__ u64 dup2(float x){
    u64 r; asm("mov.b64 %0,{%1,%1};" : "=l"(r) : "f"(x)); return r;
}
__device__ __forceinline__ u64 ffma2(u64 a, u64 b, u64 c){
    u64 d; asm("fma.rn.f32x2 %0,%1,%2,%3;" : "=l"(d) : "l"(a), "l"(b), "l"(c)); return d;
}
__device__ __forceinline__ u64 fadd2(u64 a, u64 b){
    u64 d; asm("add.rn.f32x2 %0,%1,%2;" : "=l"(d) : "l"(a), "l"(b)); return d;
}
__device__ __forceinline__ void ldsw(u64&a, u64&b, u32 addr){
    asm volatile("ld.shared.v2.u64 {%0,%1},[%2];" : "=l"(a),"=l"(b) : "r"(addr));
}
__device__ __forceinline__ u64 ldsu64(u32 addr){
    u64 r; asm volatile("ld.shared.b64 %0,[%1];" : "=l"(r) : "r"(addr)); return r;
}

// ---------------------------------------------------------------------------
// Gumbel-softmax channel mask
// ---------------------------------------------------------------------------
__global__ void mask_kernel(const float* __restrict__ gum,
                            const float* __restrict__ par,
                            float* __restrict__ out_tail)
{
    int c = threadIdx.x;
    if (c >= Cn) return;
#pragma unroll
    for (int l = 0; l < 4; ++l) {
        int i0 = c*8 + l*2;
        float g0 = -logf(-logf(gum[i0]));
        float g1 = -logf(-logf(gum[i0+1]));
        float l0 = par[i0]   + g0;
        float l1 = par[i0+1] + g1;
        float e  = expf(l1 - l0);
        float m0 = 1.0f/(1.0f+e);
        float m1 = e/(1.0f+e);
        g_md[l][c] = m0;
        g_ms[l][c] = m1;
        out_tail[i0]   = m0;
        out_tail[i0+1] = m1;
    }
}

// ---------------------------------------------------------------------------
// Weight prep: bf16 hi/lo splits of W and W*md_ci, layout [o][ci] per tap.
// ---------------------------------------------------------------------------
__global__ void prep_kernel(const float* __restrict__ w0, const float* __restrict__ w1,
                            const float* __restrict__ w2, const float* __restrict__ w3)
{
    int idx = blockIdx.x*256 + threadIdx.x;   // 4*9*4096 total
    if (idx >= 4*9*Cn*Cn) return;
    int l  = idx / (9*Cn*Cn);
    int r  = idx - l*(9*Cn*Cn);
    int t  = r / (Cn*Cn);
    int oc = r - t*(Cn*Cn);
    int o = oc >> 6, ci = oc & 63;
    const float* ws = (l==0) ? w0 : (l==1) ? w1 : (l==2) ? w2 : w3;
    float v  = ws[(o*Cn + ci)*9 + t];
    float vm = v * g_md[l][ci];
    __nv_bfloat16 h  = __float2bfloat16(v);
    __nv_bfloat16 lo = __float2bfloat16(v  - __bfloat162float(h));
    __nv_bfloat16 hm = __float2bfloat16(vm);
    __nv_bfloat16 lm = __float2bfloat16(vm - __bfloat162float(hm));
    g_wt[l][t][0][oc] = h;
    g_wt[l][t][1][oc] = lo;
    g_wt[l][t][2][oc] = hm;
    g_wt[l][t][3][oc] = lm;
}

// ---------------------------------------------------------------------------
// Warp-MMA conv layer (mma.sync m16n8k16 bf16, 3-term hi/lo split).
// CTA = (y-pair, b): M=256 px (16 warps x m16), N=64 och, K=64ci x 9 taps.
//  F = conv(fea, W); D = conv(fea, W*diag(md_ci))   [folded into B]
//  DUAL=false: out = relu( F * (ms_o*spa + md_o) )
//  DUAL=true : out = relu( D * md_o*(1-spa) + F*spa )
// ---------------------------------------------------------------------------
template<bool DUAL>
__global__ void __launch_bounds__(512, 1)
conv_mma(const float* __restrict__ x0, const float* __restrict__ spa, int layer)
{
    extern __shared__ __align__(128) char sm[];
    const u32 smb  = (u32)__cvta_generic_to_shared(sm);
    const int tid  = threadIdx.x;
    const int wid  = tid >> 5;
    const int lane = tid & 31;

    const int y0 = blockIdx.x * 2;
    const int b  = blockIdx.y;

    float* s_md = (float*)(sm + OFF_MD);
    float* s_ms = (float*)(sm + OFF_MS);
    if (tid < Cn) { s_md[tid] = g_md[layer][tid]; s_ms[tid] = g_ms[layer][tid]; }

    // ---- stage input: 4 halo rows (y0-1 .. y0+2), bf16 hi/lo, xp = x+1 ----
    const float* in  = (layer == 0) ? x0 : g_feat[layer-1];
    const float* inb = in + b*IMG;
#pragma unroll 1
    for (int idx = tid; idx < 4*Cn*130; idx += 512) {
        int r   = idx / (Cn*130);
        int rem = idx - r*(Cn*130);
        int ci  = rem / 130;
        int xp  = rem - ci*130;
        int yy = y0 - 1 + r;
        int x  = xp - 1;
        float v = 0.f;
        if ((unsigned)yy < Hn && (unsigned)x < Wn) v = inb[ci*HWn + yy*Wn + x];
        __nv_bfloat16 h = __float2bfloat16(v);
        __nv_bfloat16 l = __float2bfloat16(v - __bfloat162float(h));
        char* p = sm + OFF_PX + r*PX_ROW_STRIDE + xp*PX_XP_STRIDE + ci*2;
        *(__nv_bfloat16*)p         = h;
        *(__nv_bfloat16*)(p + 128) = l;
    }

    // warp -> m-tile: rows m0..m0+15 of the 256-px M; yrow selects output row
    const int mloc = (wid & 7) << 4;      // 0..112
    const int yrow = wid >> 3;            // 0 or 1
    const int y    = y0 + yrow;

    // ldmatrix lane offset: lanes 0-15 -> rows 0-15 (k-half 0), 16-31 -> +16B
    const u32 a_lane = (u32)((lane & 15)*PX_XP_STRIDE + ((lane >> 4) << 4));
    const int g  = lane >> 2;             // 0..7
    const int t4 = lane & 3;              // 0..3

    float accF[8][4], accD[8][4];
#pragma unroll
    for (int n = 0; n < 8; ++n)
#pragma unroll
        for (int j = 0; j < 4; ++j) { accF[n][j] = 0.f; if (DUAL) accD[n][j] = 0.f; }

    const int kinds = DUAL ? 4 : 2;
    const u32 wbase = smb + OFF_W + (u32)(g*W_O_STRIDE + t4*4);

#pragma unroll 1
    for (int t = 0; t < 9; ++t) {
        __syncthreads();   // previous tap's MMAs done reading s_w
        // stage this tap's weights: [kind][o][ci] bf16, padded o-stride
        {
            const u32* gw = (const u32*)(&g_wt[layer][t][0][0]);
#pragma unroll 1
            for (int idx = tid; idx < kinds*2048; idx += 512) {
                int kind = idx >> 11, i = idx & 2047;
                int o = i >> 5, cp = i & 31;
                *(u32*)(sm + OFF_W + kind*W_KIND_STRIDE + o*W_O_STRIDE + cp*4)
                    = gw[(idx >> 11)*2048 + i];
            }
        }
        __syncthreads();

        const int ky = t/3, kx = t - (t/3)*3;
        const u32 abase = smb + OFF_PX
                        + (u32)((ky + yrow)*PX_ROW_STRIDE)
                        + (u32)((kx + mloc)*PX_XP_STRIDE)
                        + a_lane;
#pragma unroll
        for (int kk = 0; kk < 4; ++kk) {
            u32 Ah[4], Al[4];
            ldmat4(Ah, abase + kk*32);
            ldmat4(Al, abase + kk*32 + 128);
            const u32 wk = wbase + (u32)(kk*32);
#pragma unroll
            for (int nt = 0; nt < 8; ++nt) {
                const u32 wo = wk + (u32)(nt*8*W_O_STRIDE);
                u32 bh0 = ldsu32(wo);
                u32 bh1 = ldsu32(wo + 16);
                u32 bl0 = ldsu32(wo + W_KIND_STRIDE);
                u32 bl1 = ldsu32(wo + W_KIND_STRIDE + 16);
                mma16816(accF[nt], Ah, bh0, bh1);
                mma16816(accF[nt], Ah, bl0, bl1);
                mma16816(accF[nt], Al, bh0, bh1);
                if (DUAL) {
                    u32 bmh0 = ldsu32(wo + 2*W_KIND_STRIDE);
                    u32 bmh1 = ldsu32(wo + 2*W_KIND_STRIDE + 16);
                    u32 bml0 = ldsu32(wo + 3*W_KIND_STRIDE);
                    u32 bml1 = ldsu32(wo + 3*W_KIND_STRIDE + 16);
                    mma16816(accD[nt], Ah, bmh0, bmh1);
                    mma16816(accD[nt], Ah, bml0, bml1);
                    mma16816(accD[nt], Al, bmh0, bmh1);
                }
            }
        }
    }

    // ---- fused gate + ReLU epilogue ----
    const int xA = mloc + g;          // c0/c1 pixel
    const int xB = xA + 8;            // c2/c3 pixel
    const float spA = spa[b*HWn + y*Wn + xA];
    const float spB = spa[b*HWn + y*Wn + xB];
    float* ob = g_feat[layer] + b*IMG + y*Wn;

#pragma unroll
    for (int nt = 0; nt < 8; ++nt) {
        const int o0 = nt*8 + 2*t4, o1 = o0 + 1;
        float r0, r1, r2, r3;
        if (!DUAL) {
            r0 = accF[nt][0] * (s_ms[o0]*spA + s_md[o0]);
            r1 = accF[nt][1] * (s_ms[o1]*spA + s_md[o1]);
            r2 = accF[nt][2] * (s_ms[o0]*spB + s_md[o0]);
            r3 = accF[nt][3] * (s_ms[o1]*spB + s_md[o1]);
        } else {
            r0 = accD[nt][0]*s_md[o0]*(1.f-spA) + accF[nt][0]*spA;
            r1 = accD[nt][1]*s_md[o1]*(1.f-spA) + accF[nt][1]*spA;
            r2 = accD[nt][2]*s_md[o0]*(1.f-spB) + accF[nt][2]*spB;
            r3 = accD[nt][3]*s_md[o1]*(1.f-spB) + accF[nt][3]*spB;
        }
        ob[o0*HWn + xA] = fmaxf(r0, 0.f);
        ob[o1*HWn + xA] = fmaxf(r1, 0.f);
        ob[o0*HWn + xB] = fmaxf(r2, 0.f);
        ob[o1*HWn + xB] = fmaxf(r3, 0.f);
    }
}

// ---------------------------------------------------------------------------
// Final 1x1 conv over the concat, pixel-paired f32x2.
// ---------------------------------------------------------------------------
__global__ void __launch_bounds__(256)
final_kernel(const float* __restrict__ wc, const float* __restrict__ bc,
             float* __restrict__ outp)
{
    __shared__ u64   s_wcd[16*64];   // [kk][o] dup'd
    __shared__ float s_cat[16*256];  // [kk][px]

    const int blk = blockIdx.x;
    const int b   = blk >> 6;
    const int p0  = (blk & 63) * 256;
    const int tid = threadIdx.x;
    const int og  = tid >> 5;
    const int pg  = tid & 31;
    const int o0  = og << 3;

    const u32 wsh = (u32)__cvta_generic_to_shared(s_wcd) + (u32)o0*8u;
    const u32 csh = (u32)__cvta_generic_to_shared(s_cat) + (u32)pg*8u;

    u64 acc[8][4];
#pragma unroll
    for (int u = 0; u < 8; ++u)
#pragma unroll
        for (int j = 0; j < 4; ++j) acc[u][j] = 0ull;

    for (int k0 = 0; k0 < 256; k0 += 16) {
        __syncthreads();
        for (int idx = tid; idx < 16*64; idx += 256) {
            int kk = idx >> 6, o = idx & 63;
            s_wcd[kk*64 + o] = dup2(wc[o*256 + k0 + kk]);
        }
        const float* src = g_feat[k0 >> 6] + (b*Cn + (k0 & 63))*HWn + p0;
        for (int idx = tid; idx < 16*256; idx += 256) {
            int kk = idx >> 8, px = idx & 255;
            s_cat[kk*256 + px] = src[kk*HWn + px];
        }
        __syncthreads();
#pragma unroll
        for (int kk = 0; kk < 16; ++kk) {
            u64 wv[8];
            ldsw(wv[0], wv[1], wsh + kk*512);
            ldsw(wv[2], wv[3], wsh + kk*512 + 16);
            ldsw(wv[4], wv[5], wsh + kk*512 + 32);
            ldsw(wv[6], wv[7], wsh + kk*512 + 48);
            u64 cv[4];
#pragma unroll
            for (int j = 0; j < 4; ++j)
                cv[j] = ldsu64(csh + kk*1024 + j*256);
#pragma unroll
            for (int u = 0; u < 8; ++u)
#pragma unroll
                for (int j = 0; j < 4; ++j)
                    acc[u][j] = ffma2(wv[u], cv[j], acc[u][j]);
        }
    }

#pragma unroll
    for (int u = 0; u < 8; ++u) {
        const int o = o0 + u;
        const u64 b2 = dup2(bc[o]);
        float* q = outp + (b*Cn + o)*HWn + p0;
#pragma unroll
        for (int j = 0; j < 4; ++j)
            *(u64*)(q + 2*(pg + 32*j)) = fadd2(acc[u][j], b2);
    }
}

// ---------------------------------------------------------------------------
extern "C" void kernel_launch(void* const* d_in, const int* in_sizes, int n_in,
                              void* d_out, int out_size)
{
    const float* x0  = (const float*)d_in[0];
    const float* spa = (const float*)d_in[1];
    const float* gum = (const float*)d_in[2];
    const float* par = (const float*)d_in[3];
    const float* w0  = (const float*)d_in[4];
    const float* w1  = (const float*)d_in[5];
    const float* w2  = (const float*)d_in[6];
    const float* w3  = (const float*)d_in[7];
    const float* wc  = (const float*)d_in[8];
    const float* bc  = (const float*)d_in[9];

    float* outp = (float*)d_out;
    float* tail = outp + (out_size - 512);   // ch_mask (1,64,4,2) after main out

    cudaFuncSetAttribute(conv_mma<false>,
                         cudaFuncAttributeMaxDynamicSharedMemorySize, SMEM_MMA);
    cudaFuncSetAttribute(conv_mma<true>,
                         cudaFuncAttributeMaxDynamicSharedMemorySize, SMEM_MMA);

    mask_kernel<<<1, 64>>>(gum, par, tail);
    prep_kernel<<<(4*9*Cn*Cn + 255)/256, 256>>>(w0, w1, w2, w3);

    dim3 grid(Hn/2, Bn);    // (y-pair, batch) = 64 x 16 = 1024 CTAs
    conv_mma<false><<<grid, 512, SMEM_MMA>>>(x0, spa, 0);
    conv_mma<true ><<<grid, 512, SMEM_MMA>>>(x0, spa, 1);
    conv_mma<true ><<<grid, 512, SMEM_MMA>>>(x0, spa, 2);
    conv_mma<true ><<<grid, 512, SMEM_MMA>>>(x0, spa, 3);

    final_kernel<<<Bn*64, 256>>>(wc, bc, outp);
}

// round 8
// speedup vs baseline: 2.4443x; 1.3942x over previous
#include <cuda_runtime.h>
#include <cuda_bf16.h>
#include <math.h>
#include <stdint.h>

typedef unsigned long long u64;
typedef unsigned int u32;

#define Bn 16
#define Cn 64
#define Hn 128
#define Wn 128
#define HWn (Hn*Wn)
#define IMG (Cn*HWn)

// scratch
__device__ float g_feat[4][Bn*IMG];
__device__ float g_md[4][Cn];
__device__ float g_ms[4][Cn];
// split weights: [layer][tap][kind: 0=hi,1=lo,2=md*hi,3=md*lo][o*64+ci] bf16
__device__ __nv_bfloat16 g_wt[4][9][4][Cn*Cn];

// ---------------- smem layout for conv_mma (bytes) ---------------------------
#define PX_XP_STRIDE 272
#define PX_ROW_STRIDE (130*PX_XP_STRIDE)       // 35360
#define OFF_PX 0
#define PX_BYTES (4*PX_ROW_STRIDE)             // 141440
// weights double-buffered: [buf][kind][o], 144B per o
#define OFF_W  PX_BYTES
#define W_O_STRIDE 144
#define W_KIND_STRIDE (64*W_O_STRIDE)          // 9216
#define W_BUF_STRIDE (4*W_KIND_STRIDE)         // 36864
#define OFF_MD (OFF_W + 2*W_BUF_STRIDE)        // 215168
#define OFF_MS (OFF_MD + 256)
#define SMEM_MMA (OFF_MS + 256)                // 215680

// ---------------- warp-mma helpers (baseline PTX, no 'a' features) -----------
__device__ __forceinline__ void mma16816(float* c, const u32* a, u32 b0, u32 b1){
    asm volatile(
        "mma.sync.aligned.m16n8k16.row.col.f32.bf16.bf16.f32 "
        "{%0,%1,%2,%3},{%4,%5,%6,%7},{%8,%9},{%0,%1,%2,%3};"
        : "+f"(c[0]),"+f"(c[1]),"+f"(c[2]),"+f"(c[3])
        : "r"(a[0]),"r"(a[1]),"r"(a[2]),"r"(a[3]), "r"(b0),"r"(b1));
}
__device__ __forceinline__ void ldmat4(u32* r, u32 addr){
    asm volatile("ldmatrix.sync.aligned.m8n8.x4.shared.b16 {%0,%1,%2,%3},[%4];"
                 : "=r"(r[0]),"=r"(r[1]),"=r"(r[2]),"=r"(r[3]) : "r"(addr));
}
__device__ __forceinline__ void cp16(u32 dst, const void* src){
    asm volatile("cp.async.cg.shared.global [%0], [%1], 16;"
                 :: "r"(dst), "l"(src) : "memory");
}
__device__ __forceinline__ void cp_commit(){
    asm volatile("cp.async.commit_group;" ::: "memory");
}
template<int N>
__device__ __forceinline__ void cp_wait(){
    asm volatile("cp.async.wait_group %0;" :: "n"(N) : "memory");
}

// ---------------- f32x2 helpers (final 1x1 kernel) ---------------------------
__device__ __forceinline__ u64 dup2(float x){
    u64 r; asm("mov.b64 %0,{%1,%1};" : "=l"(r) : "f"(x)); return r;
}
__device__ __forceinline__ u64 ffma2(u64 a, u64 b, u64 c){
    u64 d; asm("fma.rn.f32x2 %0,%1,%2,%3;" : "=l"(d) : "l"(a), "l"(b), "l"(c)); return d;
}
__device__ __forceinline__ u64 fadd2(u64 a, u64 b){
    u64 d; asm("add.rn.f32x2 %0,%1,%2;" : "=l"(d) : "l"(a), "l"(b)); return d;
}
__device__ __forceinline__ void ldsw(u64&a, u64&b, u32 addr){
    asm volatile("ld.shared.v2.u64 {%0,%1},[%2];" : "=l"(a),"=l"(b) : "r"(addr));
}
__device__ __forceinline__ u64 ldsu64(u32 addr){
    u64 r; asm volatile("ld.shared.b64 %0,[%1];" : "=l"(r) : "r"(addr)); return r;
}

// ---------------------------------------------------------------------------
// Gumbel-softmax channel mask
// ---------------------------------------------------------------------------
__global__ void mask_kernel(const float* __restrict__ gum,
                            const float* __restrict__ par,
                            float* __restrict__ out_tail)
{
    int c = threadIdx.x;
    if (c >= Cn) return;
#pragma unroll
    for (int l = 0; l < 4; ++l) {
        int i0 = c*8 + l*2;
        float g0 = -logf(-logf(gum[i0]));
        float g1 = -logf(-logf(gum[i0+1]));
        float l0 = par[i0]   + g0;
        float l1 = par[i0+1] + g1;
        float e  = expf(l1 - l0);
        float m0 = 1.0f/(1.0f+e);
        float m1 = e/(1.0f+e);
        g_md[l][c] = m0;
        g_ms[l][c] = m1;
        out_tail[i0]   = m0;
        out_tail[i0+1] = m1;
    }
}

// ---------------------------------------------------------------------------
// Weight prep: bf16 hi/lo splits of W and W*md_ci, layout [o][ci] per tap.
// ---------------------------------------------------------------------------
__global__ void prep_kernel(const float* __restrict__ w0, const float* __restrict__ w1,
                            const float* __restrict__ w2, const float* __restrict__ w3)
{
    int idx = blockIdx.x*256 + threadIdx.x;   // 4*9*4096 total
    if (idx >= 4*9*Cn*Cn) return;
    int l  = idx / (9*Cn*Cn);
    int r  = idx - l*(9*Cn*Cn);
    int t  = r / (Cn*Cn);
    int oc = r - t*(Cn*Cn);
    int o = oc >> 6, ci = oc & 63;
    const float* ws = (l==0) ? w0 : (l==1) ? w1 : (l==2) ? w2 : w3;
    float v  = ws[(o*Cn + ci)*9 + t];
    float vm = v * g_md[l][ci];
    __nv_bfloat16 h  = __float2bfloat16(v);
    __nv_bfloat16 lo = __float2bfloat16(v  - __bfloat162float(h));
    __nv_bfloat16 hm = __float2bfloat16(vm);
    __nv_bfloat16 lm = __float2bfloat16(vm - __bfloat162float(hm));
    g_wt[l][t][0][oc] = h;
    g_wt[l][t][1][oc] = lo;
    g_wt[l][t][2][oc] = hm;
    g_wt[l][t][3][oc] = lm;
}

// ---------------------------------------------------------------------------
// Warp-MMA conv layer: mma.sync m16n8k16 bf16 3-term hi/lo split,
// ldmatrix B fragments, cp.async double-buffered per-tap weights.
// CTA = (y-pair, b): M=256 px (16 warps x m16), N=64 och, K=64ci x 9 taps.
//  DUAL=false: out = relu( F * (ms_o*spa + md_o) )
//  DUAL=true : out = relu( D * md_o*(1-spa) + F*spa ), D = A x (W*diag(md))
// ---------------------------------------------------------------------------
template<bool DUAL>
__global__ void __launch_bounds__(512, 1)
conv_mma(const float* __restrict__ x0, const float* __restrict__ spa, int layer)
{
    extern __shared__ __align__(128) char sm[];
    const u32 smb  = (u32)__cvta_generic_to_shared(sm);
    const int tid  = threadIdx.x;
    const int wid  = tid >> 5;
    const int lane = tid & 31;

    const int y0 = blockIdx.x * 2;
    const int b  = blockIdx.y;
    const int kinds = DUAL ? 4 : 2;

    float* s_md = (float*)(sm + OFF_MD);
    float* s_ms = (float*)(sm + OFF_MS);
    if (tid < Cn) { s_md[tid] = g_md[layer][tid]; s_ms[tid] = g_ms[layer][tid]; }

    // weight stager: tap t -> buffer bi (16B cp.async chunks)
    auto stageW = [&](int t, int bi){
        const char* src = (const char*)&g_wt[layer][t][0][0];
        const u32 dst0 = smb + OFF_W + (u32)bi*W_BUF_STRIDE;
        const int n16 = kinds * 512;             // kinds * 8KB / 16B
#pragma unroll 1
        for (int idx = tid; idx < n16; idx += 512) {
            int kind = idx >> 9, i = idx & 511;
            int o = i >> 3, seg = i & 7;
            cp16(dst0 + (u32)(kind*W_KIND_STRIDE + o*W_O_STRIDE + seg*16),
                 src + kind*8192 + o*128 + seg*16);
        }
        cp_commit();
    };

    // ---- stage input: 4 halo rows (y0-1 .. y0+2), bf16 hi/lo, xp = x+1 ----
    const float* in  = (layer == 0) ? x0 : g_feat[layer-1];
    const float* inb = in + b*IMG;
    stageW(0, 0);
#pragma unroll 1
    for (int idx = tid; idx < 4*Cn*130; idx += 512) {
        int r   = idx / (Cn*130);
        int rem = idx - r*(Cn*130);
        int ci  = rem / 130;
        int xp  = rem - ci*130;
        int yy = y0 - 1 + r;
        int x  = xp - 1;
        float v = 0.f;
        if ((unsigned)yy < Hn && (unsigned)x < Wn) v = inb[ci*HWn + yy*Wn + x];
        __nv_bfloat16 h = __float2bfloat16(v);
        __nv_bfloat16 l = __float2bfloat16(v - __bfloat162float(h));
        char* p = sm + OFF_PX + r*PX_ROW_STRIDE + xp*PX_XP_STRIDE + ci*2;
        *(__nv_bfloat16*)p         = h;
        *(__nv_bfloat16*)(p + 128) = l;
    }

    const int mloc = (wid & 7) << 4;      // 0..112
    const int yrow = wid >> 3;            // 0 or 1
    const int y    = y0 + yrow;

    // A ldmatrix lane offset (rows 0-15 = k-lo 16B, rows 16-31 = k-hi)
    const u32 a_lane = (u32)((lane & 15)*PX_XP_STRIDE + ((lane >> 4) << 4));
    // B ldmatrix lane offset: grp0 = nt0 k-lo, grp1 = nt0 k-hi, grp2/3 = nt1
    const int lrow = lane & 7, lgrp = lane >> 3;
    const u32 b_lane = (u32)(((lgrp >> 1)*8 + lrow)*W_O_STRIDE + (lgrp & 1)*16);

    float accF[8][4], accD[8][4];
#pragma unroll
    for (int n = 0; n < 8; ++n)
#pragma unroll
        for (int j = 0; j < 4; ++j) { accF[n][j] = 0.f; if (DUAL) accD[n][j] = 0.f; }

#pragma unroll 1
    for (int t = 0; t < 9; ++t) {
        const int bi = t & 1;
        if (t < 8) stageW(t+1, bi^1);
        if (t < 8) cp_wait<1>(); else cp_wait<0>();
        __syncthreads();

        const int ky = t/3, kx = t - (t/3)*3;
        const u32 abase = smb + OFF_PX
                        + (u32)((ky + yrow)*PX_ROW_STRIDE)
                        + (u32)((kx + mloc)*PX_XP_STRIDE)
                        + a_lane;
        const u32 wbase = smb + OFF_W + (u32)bi*W_BUF_STRIDE + b_lane;

#pragma unroll
        for (int kk = 0; kk < 4; ++kk) {
            u32 Ah[4], Al[4];
            ldmat4(Ah, abase + kk*32);
            ldmat4(Al, abase + kk*32 + 128);
#pragma unroll
            for (int ntp = 0; ntp < 4; ++ntp) {
                const u32 wb = wbase + (u32)(ntp*16*W_O_STRIDE + kk*32);
                u32 Bh[4], Bl[4];
                ldmat4(Bh, wb);
                ldmat4(Bl, wb + W_KIND_STRIDE);
                const int n0 = ntp*2, n1 = n0 + 1;
                mma16816(accF[n0], Ah, Bh[0], Bh[1]);
                mma16816(accF[n0], Ah, Bl[0], Bl[1]);
                mma16816(accF[n0], Al, Bh[0], Bh[1]);
                mma16816(accF[n1], Ah, Bh[2], Bh[3]);
                mma16816(accF[n1], Ah, Bl[2], Bl[3]);
                mma16816(accF[n1], Al, Bh[2], Bh[3]);
                if (DUAL) {
                    u32 Bmh[4], Bml[4];
                    ldmat4(Bmh, wb + 2*W_KIND_STRIDE);
                    ldmat4(Bml, wb + 3*W_KIND_STRIDE);
                    mma16816(accD[n0], Ah, Bmh[0], Bmh[1]);
                    mma16816(accD[n0], Ah, Bml[0], Bml[1]);
                    mma16816(accD[n0], Al, Bmh[0], Bmh[1]);
                    mma16816(accD[n1], Ah, Bmh[2], Bmh[3]);
                    mma16816(accD[n1], Ah, Bml[2], Bml[3]);
                    mma16816(accD[n1], Al, Bmh[2], Bmh[3]);
                }
            }
        }
        __syncthreads();
    }

    // ---- fused gate + ReLU epilogue ----
    const int g  = lane >> 2;
    const int t4 = lane & 3;
    const int xA = mloc + g;
    const int xB = xA + 8;
    const float spA = spa[b*HWn + y*Wn + xA];
    const float spB = spa[b*HWn + y*Wn + xB];
    float* ob = g_feat[layer] + b*IMG + y*Wn;

#pragma unroll
    for (int nt = 0; nt < 8; ++nt) {
        const int o0 = nt*8 + 2*t4, o1 = o0 + 1;
        float r0, r1, r2, r3;
        if (!DUAL) {
            r0 = accF[nt][0] * (s_ms[o0]*spA + s_md[o0]);
            r1 = accF[nt][1] * (s_ms[o1]*spA + s_md[o1]);
            r2 = accF[nt][2] * (s_ms[o0]*spB + s_md[o0]);
            r3 = accF[nt][3] * (s_ms[o1]*spB + s_md[o1]);
        } else {
            r0 = accD[nt][0]*s_md[o0]*(1.f-spA) + accF[nt][0]*spA;
            r1 = accD[nt][1]*s_md[o1]*(1.f-spA) + accF[nt][1]*spA;
            r2 = accD[nt][2]*s_md[o0]*(1.f-spB) + accF[nt][2]*spB;
            r3 = accD[nt][3]*s_md[o1]*(1.f-spB) + accF[nt][3]*spB;
        }
        ob[o0*HWn + xA] = fmaxf(r0, 0.f);
        ob[o1*HWn + xA] = fmaxf(r1, 0.f);
        ob[o0*HWn + xB] = fmaxf(r2, 0.f);
        ob[o1*HWn + xB] = fmaxf(r3, 0.f);
    }
}

// ---------------------------------------------------------------------------
// Final 1x1 conv over the concat, pixel-paired f32x2, cp.async-prefetched cat.
// ---------------------------------------------------------------------------
__global__ void __launch_bounds__(256)
final_kernel(const float* __restrict__ wc, const float* __restrict__ bc,
             float* __restrict__ outp)
{
    __shared__ u64 s_wcd[16*64];                     // [kk][o] dup'd
    __shared__ __align__(16) float s_cat[2][16*256]; // [buf][kk][px]

    const int blk = blockIdx.x;
    const int b   = blk >> 6;
    const int p0  = (blk & 63) * 256;
    const int tid = threadIdx.x;
    const int og  = tid >> 5;
    const int pg  = tid & 31;
    const int o0  = og << 3;

    const u32 wsh  = (u32)__cvta_generic_to_shared(s_wcd) + (u32)o0*8u;
    const u32 cat0 = (u32)__cvta_generic_to_shared(&s_cat[0][0]);

    auto stage_cat = [&](int k0, int bufi){
        const float* src = g_feat[k0 >> 6] + (b*Cn + (k0 & 63))*HWn + p0;
        const u32 dst = cat0 + (u32)bufi*16384;
#pragma unroll
        for (int it = 0; it < 4; ++it) {
            int idx = tid + it*256;           // 1024 x 16B
            int kk = idx >> 6, c4 = idx & 63;
            cp16(dst + (u32)(kk*1024 + c4*16), src + kk*HWn + c4*4);
        }
        cp_commit();
    };

    u64 acc[8][4];
#pragma unroll
    for (int u = 0; u < 8; ++u)
#pragma unroll
        for (int j = 0; j < 4; ++j) acc[u][j] = 0ull;

    stage_cat(0, 0);
    for (int k0 = 0; k0 < 256; k0 += 16) {
        const int bufi = (k0 >> 4) & 1;
        __syncthreads();                      // prior reads of s_wcd/s_cat done
        if (k0 < 240) stage_cat(k0 + 16, bufi^1);
        for (int idx = tid; idx < 16*64; idx += 256) {
            int kk = idx >> 6, o = idx & 63;
            s_wcd[kk*64 + o] = dup2(wc[o*256 + k0 + kk]);
        }
        if (k0 < 240) cp_wait<1>(); else cp_wait<0>();
        __syncthreads();

        const u32 csh = cat0 + (u32)bufi*16384 + (u32)pg*8u;
#pragma unroll
        for (int kk = 0; kk < 16; ++kk) {
            u64 wv[8];
            ldsw(wv[0], wv[1], wsh + kk*512);
            ldsw(wv[2], wv[3], wsh + kk*512 + 16);
            ldsw(wv[4], wv[5], wsh + kk*512 + 32);
            ldsw(wv[6], wv[7], wsh + kk*512 + 48);
            u64 cv[4];
#pragma unroll
            for (int j = 0; j < 4; ++j)
                cv[j] = ldsu64(csh + kk*1024 + j*256);
#pragma unroll
            for (int u = 0; u < 8; ++u)
#pragma unroll
                for (int j = 0; j < 4; ++j)
                    acc[u][j] = ffma2(wv[u], cv[j], acc[u][j]);
        }
    }

#pragma unroll
    for (int u = 0; u < 8; ++u) {
        const int o = o0 + u;
        const u64 b2 = dup2(bc[o]);
        float* q = outp + (b*Cn + o)*HWn + p0;
#pragma unroll
        for (int j = 0; j < 4; ++j)
            *(u64*)(q + 2*(pg + 32*j)) = fadd2(acc[u][j], b2);
    }
}

// ---------------------------------------------------------------------------
extern "C" void kernel_launch(void* const* d_in, const int* in_sizes, int n_in,
                              void* d_out, int out_size)
{
    const float* x0  = (const float*)d_in[0];
    const float* spa = (const float*)d_in[1];
    const float* gum = (const float*)d_in[2];
    const float* par = (const float*)d_in[3];
    const float* w0  = (const float*)d_in[4];
    const float* w1  = (const float*)d_in[5];
    const float* w2  = (const float*)d_in[6];
    const float* w3  = (const float*)d_in[7];
    const float* wc  = (const float*)d_in[8];
    const float* bc  = (const float*)d_in[9];

    float* outp = (float*)d_out;
    float* tail = outp + (out_size - 512);   // ch_mask (1,64,4,2) after main out

    cudaFuncSetAttribute(conv_mma<false>,
                         cudaFuncAttributeMaxDynamicSharedMemorySize, SMEM_MMA);
    cudaFuncSetAttribute(conv_mma<true>,
                         cudaFuncAttributeMaxDynamicSharedMemorySize, SMEM_MMA);

    mask_kernel<<<1, 64>>>(gum, par, tail);
    prep_kernel<<<(4*9*Cn*Cn + 255)/256, 256>>>(w0, w1, w2, w3);

    dim3 grid(Hn/2, Bn);    // (y-pair, batch) = 64 x 16 = 1024 CTAs
    conv_mma<false><<<grid, 512, SMEM_MMA>>>(x0, spa, 0);
    conv_mma<true ><<<grid, 512, SMEM_MMA>>>(x0, spa, 1);
    conv_mma<true ><<<grid, 512, SMEM_MMA>>>(x0, spa, 2);
    conv_mma<true ><<<grid, 512, SMEM_MMA>>>(x0, spa, 3);

    final_kernel<<<Bn*64, 256>>>(wc, bc, outp);
}

// round 9
// speedup vs baseline: 2.4633x; 1.0078x over previous
#include <cuda_runtime.h>
#include <cuda_bf16.h>
#include <math.h>
#include <stdint.h>

typedef unsigned long long u64;
typedef unsigned int u32;

#define Bn 16
#define Cn 64
#define Hn 128
#define Wn 128
#define HWn (Hn*Wn)
#define IMG (Cn*HWn)

// scratch
__device__ float g_feat[4][Bn*IMG];
__device__ float g_md[4][Cn];
__device__ float g_ms[4][Cn];
// split weights: [layer][tap][kind: 0=hi,1=lo,2=md*hi,3=md*lo][o*64+ci] bf16
__device__ __nv_bfloat16 g_wt[4][9][4][Cn*Cn];

// ---------------- smem layout for conv_mma (bytes) ---------------------------
#define PX_XP_STRIDE 272
#define PX_ROW_STRIDE (130*PX_XP_STRIDE)       // 35360
#define OFF_PX 0
#define PX_BYTES (4*PX_ROW_STRIDE)             // 141440
// weights double-buffered: [buf][kind][o], 144B per o
#define OFF_W  PX_BYTES
#define W_O_STRIDE 144
#define W_KIND_STRIDE (64*W_O_STRIDE)          // 9216
#define W_BUF_STRIDE (4*W_KIND_STRIDE)         // 36864
#define OFF_MD (OFF_W + 2*W_BUF_STRIDE)        // 215168
#define OFF_MS (OFF_MD + 256)
#define SMEM_MMA (OFF_MS + 256)                // 215680

// ---------------- warp-mma helpers (baseline PTX, no 'a' features) -----------
// NOTE: non-volatile on purpose — pure register op, let the scheduler reorder.
__device__ __forceinline__ void mma16816(float* c, const u32* a, u32 b0, u32 b1){
    asm("mma.sync.aligned.m16n8k16.row.col.f32.bf16.bf16.f32 "
        "{%0,%1,%2,%3},{%4,%5,%6,%7},{%8,%9},{%0,%1,%2,%3};"
        : "+f"(c[0]),"+f"(c[1]),"+f"(c[2]),"+f"(c[3])
        : "r"(a[0]),"r"(a[1]),"r"(a[2]),"r"(a[3]), "r"(b0),"r"(b1));
}
__device__ __forceinline__ void ldmat4(u32* r, u32 addr){
    asm volatile("ldmatrix.sync.aligned.m8n8.x4.shared.b16 {%0,%1,%2,%3},[%4];"
                 : "=r"(r[0]),"=r"(r[1]),"=r"(r[2]),"=r"(r[3]) : "r"(addr));
}
__device__ __forceinline__ void cp16(u32 dst, const void* src){
    asm volatile("cp.async.cg.shared.global [%0], [%1], 16;"
                 :: "r"(dst), "l"(src) : "memory");
}
__device__ __forceinline__ void cp_commit(){
    asm volatile("cp.async.commit_group;" ::: "memory");
}
template<int N>
__device__ __forceinline__ void cp_wait(){
    asm volatile("cp.async.wait_group %0;" :: "n"(N) : "memory");
}

// ---------------- f32x2 helpers (final 1x1 kernel) ---------------------------
__device__ __forceinline__ u64 dup2(float x){
    u64 r; asm("mov.b64 %0,{%1,%1};" : "=l"(r) : "f"(x)); return r;
}
__device__ __forceinline__ u64 ffma2(u64 a, u64 b, u64 c){
    u64 d; asm("fma.rn.f32x2 %0,%1,%2,%3;" : "=l"(d) : "l"(a), "l"(b), "l"(c)); return d;
}
__device__ __forceinline__ u64 fadd2(u64 a, u64 b){
    u64 d; asm("add.rn.f32x2 %0,%1,%2;" : "=l"(d) : "l"(a), "l"(b)); return d;
}
__device__ __forceinline__ void ldsw(u64&a, u64&b, u32 addr){
    asm volatile("ld.shared.v2.u64 {%0,%1},[%2];" : "=l"(a),"=l"(b) : "r"(addr));
}
__device__ __forceinline__ u64 ldsu64(u32 addr){
    u64 r; asm volatile("ld.shared.b64 %0,[%1];" : "=l"(r) : "r"(addr)); return r;
}

// ---------------------------------------------------------------------------
// Gumbel-softmax channel mask
// ---------------------------------------------------------------------------
__global__ void mask_kernel(const float* __restrict__ gum,
                            const float* __restrict__ par,
                            float* __restrict__ out_tail)
{
    int c = threadIdx.x;
    if (c >= Cn) return;
#pragma unroll
    for (int l = 0; l < 4; ++l) {
        int i0 = c*8 + l*2;
        float g0 = -logf(-logf(gum[i0]));
        float g1 = -logf(-logf(gum[i0+1]));
        float l0 = par[i0]   + g0;
        float l1 = par[i0+1] + g1;
        float e  = expf(l1 - l0);
        float m0 = 1.0f/(1.0f+e);
        float m1 = e/(1.0f+e);
        g_md[l][c] = m0;
        g_ms[l][c] = m1;
        out_tail[i0]   = m0;
        out_tail[i0+1] = m1;
    }
}

// ---------------------------------------------------------------------------
// Weight prep: bf16 hi/lo splits of W and W*md_ci, layout [o][ci] per tap.
// ---------------------------------------------------------------------------
__global__ void prep_kernel(const float* __restrict__ w0, const float* __restrict__ w1,
                            const float* __restrict__ w2, const float* __restrict__ w3)
{
    int idx = blockIdx.x*256 + threadIdx.x;   // 4*9*4096 total
    if (idx >= 4*9*Cn*Cn) return;
    int l  = idx / (9*Cn*Cn);
    int r  = idx - l*(9*Cn*Cn);
    int t  = r / (Cn*Cn);
    int oc = r - t*(Cn*Cn);
    int o = oc >> 6, ci = oc & 63;
    const float* ws = (l==0) ? w0 : (l==1) ? w1 : (l==2) ? w2 : w3;
    float v  = ws[(o*Cn + ci)*9 + t];
    float vm = v * g_md[l][ci];
    __nv_bfloat16 h  = __float2bfloat16(v);
    __nv_bfloat16 lo = __float2bfloat16(v  - __bfloat162float(h));
    __nv_bfloat16 hm = __float2bfloat16(vm);
    __nv_bfloat16 lm = __float2bfloat16(vm - __bfloat162float(hm));
    g_wt[l][t][0][oc] = h;
    g_wt[l][t][1][oc] = lo;
    g_wt[l][t][2][oc] = hm;
    g_wt[l][t][3][oc] = lm;
}

// ---------------------------------------------------------------------------
// Warp-MMA conv layer: mma.sync m16n8k16 bf16 3-term hi/lo split,
// ldmatrix B fragments, cp.async double-buffered per-tap weights,
// accumulator-chain-interleaved MMA emission (same-acc distance = 4).
// CTA = (y-pair, b): M=256 px (16 warps x m16), N=64 och, K=64ci x 9 taps.
//  DUAL=false: out = relu( F * (ms_o*spa + md_o) )
//  DUAL=true : out = relu( D * md_o*(1-spa) + F*spa ), D = A x (W*diag(md))
// ---------------------------------------------------------------------------
template<bool DUAL>
__global__ void __launch_bounds__(512, 1)
conv_mma(const float* __restrict__ x0, const float* __restrict__ spa, int layer)
{
    extern __shared__ __align__(128) char sm[];
    const u32 smb  = (u32)__cvta_generic_to_shared(sm);
    const int tid  = threadIdx.x;
    const int wid  = tid >> 5;
    const int lane = tid & 31;

    const int y0 = blockIdx.x * 2;
    const int b  = blockIdx.y;
    const int kinds = DUAL ? 4 : 2;

    float* s_md = (float*)(sm + OFF_MD);
    float* s_ms = (float*)(sm + OFF_MS);
    if (tid < Cn) { s_md[tid] = g_md[layer][tid]; s_ms[tid] = g_ms[layer][tid]; }

    // weight stager: tap t -> buffer bi (16B cp.async chunks)
    auto stageW = [&](int t, int bi){
        const char* src = (const char*)&g_wt[layer][t][0][0];
        const u32 dst0 = smb + OFF_W + (u32)bi*W_BUF_STRIDE;
        const int n16 = kinds * 512;             // kinds * 8KB / 16B
#pragma unroll 1
        for (int idx = tid; idx < n16; idx += 512) {
            int kind = idx >> 9, i = idx & 511;
            int o = i >> 3, seg = i & 7;
            cp16(dst0 + (u32)(kind*W_KIND_STRIDE + o*W_O_STRIDE + seg*16),
                 src + kind*8192 + o*128 + seg*16);
        }
        cp_commit();
    };

    // ---- stage input: 4 halo rows (y0-1 .. y0+2), bf16 hi/lo, xp = x+1 ----
    const float* in  = (layer == 0) ? x0 : g_feat[layer-1];
    const float* inb = in + b*IMG;
    stageW(0, 0);
#pragma unroll 1
    for (int idx = tid; idx < 4*Cn*130; idx += 512) {
        int r   = idx / (Cn*130);
        int rem = idx - r*(Cn*130);
        int ci  = rem / 130;
        int xp  = rem - ci*130;
        int yy = y0 - 1 + r;
        int x  = xp - 1;
        float v = 0.f;
        if ((unsigned)yy < Hn && (unsigned)x < Wn) v = inb[ci*HWn + yy*Wn + x];
        __nv_bfloat16 h = __float2bfloat16(v);
        __nv_bfloat16 l = __float2bfloat16(v - __bfloat162float(h));
        char* p = sm + OFF_PX + r*PX_ROW_STRIDE + xp*PX_XP_STRIDE + ci*2;
        *(__nv_bfloat16*)p         = h;
        *(__nv_bfloat16*)(p + 128) = l;
    }

    const int mloc = (wid & 7) << 4;      // 0..112
    const int yrow = wid >> 3;            // 0 or 1
    const int y    = y0 + yrow;

    // A ldmatrix lane offset (rows 0-15 = k-lo 16B, rows 16-31 = k-hi)
    const u32 a_lane = (u32)((lane & 15)*PX_XP_STRIDE + ((lane >> 4) << 4));
    // B ldmatrix lane offset: grp0 = nt0 k-lo, grp1 = nt0 k-hi, grp2/3 = nt1
    const int lrow = lane & 7, lgrp = lane >> 3;
    const u32 b_lane = (u32)(((lgrp >> 1)*8 + lrow)*W_O_STRIDE + (lgrp & 1)*16);

    float accF[8][4], accD[8][4];
#pragma unroll
    for (int n = 0; n < 8; ++n)
#pragma unroll
        for (int j = 0; j < 4; ++j) { accF[n][j] = 0.f; if (DUAL) accD[n][j] = 0.f; }

#pragma unroll 1
    for (int t = 0; t < 9; ++t) {
        const int bi = t & 1;
        if (t < 8) stageW(t+1, bi^1);
        if (t < 8) cp_wait<1>(); else cp_wait<0>();
        __syncthreads();

        const int ky = t/3, kx = t - (t/3)*3;
        const u32 abase = smb + OFF_PX
                        + (u32)((ky + yrow)*PX_ROW_STRIDE)
                        + (u32)((kx + mloc)*PX_XP_STRIDE)
                        + a_lane;
        const u32 wbase = smb + OFF_W + (u32)bi*W_BUF_STRIDE + b_lane;

#pragma unroll
        for (int kk = 0; kk < 4; ++kk) {
            u32 Ah[4], Al[4];
            ldmat4(Ah, abase + kk*32);
            ldmat4(Al, abase + kk*32 + 128);
            if (DUAL) {
                // one ntp at a time: 4 chains (Fn0,Fn1,Dn0,Dn1), distance 4
#pragma unroll
                for (int ntp = 0; ntp < 4; ++ntp) {
                    const u32 wb = wbase + (u32)(ntp*16*W_O_STRIDE + kk*32);
                    u32 Bh[4], Bl[4], Bmh[4], Bml[4];
                    ldmat4(Bh,  wb);
                    ldmat4(Bl,  wb + W_KIND_STRIDE);
                    ldmat4(Bmh, wb + 2*W_KIND_STRIDE);
                    ldmat4(Bml, wb + 3*W_KIND_STRIDE);
                    const int n0 = ntp*2, n1 = n0 + 1;
                    mma16816(accF[n0], Ah, Bh[0],  Bh[1]);
                    mma16816(accF[n1], Ah, Bh[2],  Bh[3]);
                    mma16816(accD[n0], Ah, Bmh[0], Bmh[1]);
                    mma16816(accD[n1], Ah, Bmh[2], Bmh[3]);
                    mma16816(accF[n0], Al, Bh[0],  Bh[1]);
                    mma16816(accF[n1], Al, Bh[2],  Bh[3]);
                    mma16816(accD[n0], Al, Bmh[0], Bmh[1]);
                    mma16816(accD[n1], Al, Bmh[2], Bmh[3]);
                    mma16816(accF[n0], Ah, Bl[0],  Bl[1]);
                    mma16816(accF[n1], Ah, Bl[2],  Bl[3]);
                    mma16816(accD[n0], Ah, Bml[0], Bml[1]);
                    mma16816(accD[n1], Ah, Bml[2], Bml[3]);
                }
            } else {
                // two ntp at a time: 4 chains (Fn0..Fn3), distance 4
#pragma unroll
                for (int np = 0; np < 2; ++np) {
                    const u32 wb0 = wbase + (u32)((np*2  )*16*W_O_STRIDE + kk*32);
                    const u32 wb1 = wbase + (u32)((np*2+1)*16*W_O_STRIDE + kk*32);
                    u32 B0h[4], B0l[4], B1h[4], B1l[4];
                    ldmat4(B0h, wb0);
                    ldmat4(B0l, wb0 + W_KIND_STRIDE);
                    ldmat4(B1h, wb1);
                    ldmat4(B1l, wb1 + W_KIND_STRIDE);
                    const int n0 = np*4;
                    mma16816(accF[n0  ], Ah, B0h[0], B0h[1]);
                    mma16816(accF[n0+1], Ah, B0h[2], B0h[3]);
                    mma16816(accF[n0+2], Ah, B1h[0], B1h[1]);
                    mma16816(accF[n0+3], Ah, B1h[2], B1h[3]);
                    mma16816(accF[n0  ], Al, B0h[0], B0h[1]);
                    mma16816(accF[n0+1], Al, B0h[2], B0h[3]);
                    mma16816(accF[n0+2], Al, B1h[0], B1h[1]);
                    mma16816(accF[n0+3], Al, B1h[2], B1h[3]);
                    mma16816(accF[n0  ], Ah, B0l[0], B0l[1]);
                    mma16816(accF[n0+1], Ah, B0l[2], B0l[3]);
                    mma16816(accF[n0+2], Ah, B1l[0], B1l[1]);
                    mma16816(accF[n0+3], Ah, B1l[2], B1l[3]);
                }
            }
        }
        __syncthreads();
    }

    // ---- fused gate + ReLU epilogue ----
    const int g  = lane >> 2;
    const int t4 = lane & 3;
    const int xA = mloc + g;
    const int xB = xA + 8;
    const float spA = spa[b*HWn + y*Wn + xA];
    const float spB = spa[b*HWn + y*Wn + xB];
    float* ob = g_feat[layer] + b*IMG + y*Wn;

#pragma unroll
    for (int nt = 0; nt < 8; ++nt) {
        const int o0 = nt*8 + 2*t4, o1 = o0 + 1;
        float r0, r1, r2, r3;
        if (!DUAL) {
            r0 = accF[nt][0] * (s_ms[o0]*spA + s_md[o0]);
            r1 = accF[nt][1] * (s_ms[o1]*spA + s_md[o1]);
            r2 = accF[nt][2] * (s_ms[o0]*spB + s_md[o0]);
            r3 = accF[nt][3] * (s_ms[o1]*spB + s_md[o1]);
        } else {
            r0 = accD[nt][0]*s_md[o0]*(1.f-spA) + accF[nt][0]*spA;
            r1 = accD[nt][1]*s_md[o1]*(1.f-spA) + accF[nt][1]*spA;
            r2 = accD[nt][2]*s_md[o0]*(1.f-spB) + accF[nt][2]*spB;
            r3 = accD[nt][3]*s_md[o1]*(1.f-spB) + accF[nt][3]*spB;
        }
        ob[o0*HWn + xA] = fmaxf(r0, 0.f);
        ob[o1*HWn + xA] = fmaxf(r1, 0.f);
        ob[o0*HWn + xB] = fmaxf(r2, 0.f);
        ob[o1*HWn + xB] = fmaxf(r3, 0.f);
    }
}

// ---------------------------------------------------------------------------
// Final 1x1 conv over the concat, pixel-paired f32x2, cp.async-prefetched cat.
// ---------------------------------------------------------------------------
__global__ void __launch_bounds__(256)
final_kernel(const float* __restrict__ wc, const float* __restrict__ bc,
             float* __restrict__ outp)
{
    __shared__ u64 s_wcd[16*64];                     // [kk][o] dup'd
    __shared__ __align__(16) float s_cat[2][16*256]; // [buf][kk][px]

    const int blk = blockIdx.x;
    const int b   = blk >> 6;
    const int p0  = (blk & 63) * 256;
    const int tid = threadIdx.x;
    const int og  = tid >> 5;
    const int pg  = tid & 31;
    const int o0  = og << 3;

    const u32 wsh  = (u32)__cvta_generic_to_shared(s_wcd) + (u32)o0*8u;
    const u32 cat0 = (u32)__cvta_generic_to_shared(&s_cat[0][0]);

    auto stage_cat = [&](int k0, int bufi){
        const float* src = g_feat[k0 >> 6] + (b*Cn + (k0 & 63))*HWn + p0;
        const u32 dst = cat0 + (u32)bufi*16384;
#pragma unroll
        for (int it = 0; it < 4; ++it) {
            int idx = tid + it*256;           // 1024 x 16B
            int kk = idx >> 6, c4 = idx & 63;
            cp16(dst + (u32)(kk*1024 + c4*16), src + kk*HWn + c4*4);
        }
        cp_commit();
    };

    u64 acc[8][4];
#pragma unroll
    for (int u = 0; u < 8; ++u)
#pragma unroll
        for (int j = 0; j < 4; ++j) acc[u][j] = 0ull;

    stage_cat(0, 0);
    for (int k0 = 0; k0 < 256; k0 += 16) {
        const int bufi = (k0 >> 4) & 1;
        __syncthreads();                      // prior reads of s_wcd/s_cat done
        if (k0 < 240) stage_cat(k0 + 16, bufi^1);
        for (int idx = tid; idx < 16*64; idx += 256) {
            int kk = idx >> 6, o = idx & 63;
            s_wcd[kk*64 + o] = dup2(wc[o*256 + k0 + kk]);
        }
        if (k0 < 240) cp_wait<1>(); else cp_wait<0>();
        __syncthreads();

        const u32 csh = cat0 + (u32)bufi*16384 + (u32)pg*8u;
#pragma unroll
        for (int kk = 0; kk < 16; ++kk) {
            u64 wv[8];
            ldsw(wv[0], wv[1], wsh + kk*512);
            ldsw(wv[2], wv[3], wsh + kk*512 + 16);
            ldsw(wv[4], wv[5], wsh + kk*512 + 32);
            ldsw(wv[6], wv[7], wsh + kk*512 + 48);
            u64 cv[4];
#pragma unroll
            for (int j = 0; j < 4; ++j)
                cv[j] = ldsu64(csh + kk*1024 + j*256);
#pragma unroll
            for (int u = 0; u < 8; ++u)
#pragma unroll
                for (int j = 0; j < 4; ++j)
                    acc[u][j] = ffma2(wv[u], cv[j], acc[u][j]);
        }
    }

#pragma unroll
    for (int u = 0; u < 8; ++u) {
        const int o = o0 + u;
        const u64 b2 = dup2(bc[o]);
        float* q = outp + (b*Cn + o)*HWn + p0;
#pragma unroll
        for (int j = 0; j < 4; ++j)
            *(u64*)(q + 2*(pg + 32*j)) = fadd2(acc[u][j], b2);
    }
}

// ---------------------------------------------------------------------------
extern "C" void kernel_launch(void* const* d_in, const int* in_sizes, int n_in,
                              void* d_out, int out_size)
{
    const float* x0  = (const float*)d_in[0];
    const float* spa = (const float*)d_in[1];
    const float* gum = (const float*)d_in[2];
    const float* par = (const float*)d_in[3];
    const float* w0  = (const float*)d_in[4];
    const float* w1  = (const float*)d_in[5];
    const float* w2  = (const float*)d_in[6];
    const float* w3  = (const float*)d_in[7];
    const float* wc  = (const float*)d_in[8];
    const float* bc  = (const float*)d_in[9];

    float* outp = (float*)d_out;
    float* tail = outp + (out_size - 512);   // ch_mask (1,64,4,2) after main out

    cudaFuncSetAttribute(conv_mma<false>,
                         cudaFuncAttributeMaxDynamicSharedMemorySize, SMEM_MMA);
    cudaFuncSetAttribute(conv_mma<true>,
                         cudaFuncAttributeMaxDynamicSharedMemorySize, SMEM_MMA);

    mask_kernel<<<1, 64>>>(gum, par, tail);
    prep_kernel<<<(4*9*Cn*Cn + 255)/256, 256>>>(w0, w1, w2, w3);

    dim3 grid(Hn/2, Bn);    // (y-pair, batch) = 64 x 16 = 1024 CTAs
    conv_mma<false><<<grid, 512, SMEM_MMA>>>(x0, spa, 0);
    conv_mma<true ><<<grid, 512, SMEM_MMA>>>(x0, spa, 1);
    conv_mma<true ><<<grid, 512, SMEM_MMA>>>(x0, spa, 2);
    conv_mma<true ><<<grid, 512, SMEM_MMA>>>(x0, spa, 3);

    final_kernel<<<Bn*64, 256>>>(wc, bc, outp);
}

// round 10
// speedup vs baseline: 2.4758x; 1.0051x over previous
#include <cuda_runtime.h>
#include <cuda_bf16.h>
#include <math.h>
#include <stdint.h>

typedef unsigned long long u64;
typedef unsigned int u32;

#define Bn 16
#define Cn 64
#define Hn 128
#define Wn 128
#define HWn (Hn*Wn)
#define IMG (Cn*HWn)

// scratch
__device__ float g_feat[4][Bn*IMG];
__device__ float g_md[4][Cn];
__device__ float g_ms[4][Cn];
// split weights: [layer][tap][kind: 0=hi,1=lo,2=md*hi,3=md*lo][o*64+ci] bf16
__device__ __nv_bfloat16 g_wt[4][9][4][Cn*Cn];

// ---------------- smem layout for conv_mma (bytes) ---------------------------
#define PX_XP_STRIDE 272
#define PX_ROW_STRIDE (130*PX_XP_STRIDE)       // 35360
#define OFF_PX 0
#define PX_BYTES (4*PX_ROW_STRIDE)             // 141440
// weights double-buffered: [buf][kind][o], 144B per o
#define OFF_W  PX_BYTES
#define W_O_STRIDE 144
#define W_KIND_STRIDE (64*W_O_STRIDE)          // 9216
#define W_BUF_STRIDE (4*W_KIND_STRIDE)         // 36864
#define OFF_MD (OFF_W + 2*W_BUF_STRIDE)        // 215168
#define OFF_MS (OFF_MD + 256)
#define SMEM_MMA (OFF_MS + 256)                // 215680

// ---------------- warp-mma helpers (baseline PTX, no 'a' features) -----------
// non-volatile: pure register op, let ptxas schedule freely
__device__ __forceinline__ void mma16816(float* c, const u32* a, u32 b0, u32 b1){
    asm("mma.sync.aligned.m16n8k16.row.col.f32.bf16.bf16.f32 "
        "{%0,%1,%2,%3},{%4,%5,%6,%7},{%8,%9},{%0,%1,%2,%3};"
        : "+f"(c[0]),"+f"(c[1]),"+f"(c[2]),"+f"(c[3])
        : "r"(a[0]),"r"(a[1]),"r"(a[2]),"r"(a[3]), "r"(b0),"r"(b1));
}
__device__ __forceinline__ void ldmat4(u32* r, u32 addr){
    asm volatile("ldmatrix.sync.aligned.m8n8.x4.shared.b16 {%0,%1,%2,%3},[%4];"
                 : "=r"(r[0]),"=r"(r[1]),"=r"(r[2]),"=r"(r[3]) : "r"(addr));
}
__device__ __forceinline__ void cp16(u32 dst, const void* src){
    asm volatile("cp.async.cg.shared.global [%0], [%1], 16;"
                 :: "r"(dst), "l"(src) : "memory");
}
__device__ __forceinline__ void cp_commit(){
    asm volatile("cp.async.commit_group;" ::: "memory");
}
template<int N>
__device__ __forceinline__ void cp_wait(){
    asm volatile("cp.async.wait_group %0;" :: "n"(N) : "memory");
}

// ---------------- f32x2 helpers (final 1x1 kernel) ---------------------------
__device__ __forceinline__ u64 dup2(float x){
    u64 r; asm("mov.b64 %0,{%1,%1};" : "=l"(r) : "f"(x)); return r;
}
__device__ __forceinline__ u64 ffma2(u64 a, u64 b, u64 c){
    u64 d; asm("fma.rn.f32x2 %0,%1,%2,%3;" : "=l"(d) : "l"(a), "l"(b), "l"(c)); return d;
}
__device__ __forceinline__ u64 fadd2(u64 a, u64 b){
    u64 d; asm("add.rn.f32x2 %0,%1,%2;" : "=l"(d) : "l"(a), "l"(b)); return d;
}
__device__ __forceinline__ void ldsw(u64&a, u64&b, u32 addr){
    asm volatile("ld.shared.v2.u64 {%0,%1},[%2];" : "=l"(a),"=l"(b) : "r"(addr));
}
__device__ __forceinline__ u64 ldsu64(u32 addr){
    u64 r; asm volatile("ld.shared.b64 %0,[%1];" : "=l"(r) : "r"(addr)); return r;
}

// ---------------------------------------------------------------------------
// Gumbel-softmax channel mask
// ---------------------------------------------------------------------------
__global__ void mask_kernel(const float* __restrict__ gum,
                            const float* __restrict__ par,
                            float* __restrict__ out_tail)
{
    int c = threadIdx.x;
    if (c >= Cn) return;
#pragma unroll
    for (int l = 0; l < 4; ++l) {
        int i0 = c*8 + l*2;
        float g0 = -logf(-logf(gum[i0]));
        float g1 = -logf(-logf(gum[i0+1]));
        float l0 = par[i0]   + g0;
        float l1 = par[i0+1] + g1;
        float e  = expf(l1 - l0);
        float m0 = 1.0f/(1.0f+e);
        float m1 = e/(1.0f+e);
        g_md[l][c] = m0;
        g_ms[l][c] = m1;
        out_tail[i0]   = m0;
        out_tail[i0+1] = m1;
    }
}

// ---------------------------------------------------------------------------
// Weight prep: bf16 hi/lo splits of W and W*md_ci, layout [o][ci] per tap.
// ---------------------------------------------------------------------------
__global__ void prep_kernel(const float* __restrict__ w0, const float* __restrict__ w1,
                            const float* __restrict__ w2, const float* __restrict__ w3)
{
    int idx = blockIdx.x*256 + threadIdx.x;   // 4*9*4096 total
    if (idx >= 4*9*Cn*Cn) return;
    int l  = idx / (9*Cn*Cn);
    int r  = idx - l*(9*Cn*Cn);
    int t  = r / (Cn*Cn);
    int oc = r - t*(Cn*Cn);
    int o = oc >> 6, ci = oc & 63;
    const float* ws = (l==0) ? w0 : (l==1) ? w1 : (l==2) ? w2 : w3;
    float v  = ws[(o*Cn + ci)*9 + t];
    float vm = v * g_md[l][ci];
    __nv_bfloat16 h  = __float2bfloat16(v);
    __nv_bfloat16 lo = __float2bfloat16(v  - __bfloat162float(h));
    __nv_bfloat16 hm = __float2bfloat16(vm);
    __nv_bfloat16 lm = __float2bfloat16(vm - __bfloat162float(hm));
    g_wt[l][t][0][oc] = h;
    g_wt[l][t][1][oc] = lo;
    g_wt[l][t][2][oc] = hm;
    g_wt[l][t][3][oc] = lm;
}

// ---------------------------------------------------------------------------
// Warp-MMA conv layer: mma.sync m16n8k16 bf16 3-term hi/lo split.
// Warp tile M32 x N32 (2 m16 A-tiles x 4 n8 B-tiles) -> B fragments reused
// across 2 M-tiles, cutting LDSM traffic 1.5x vs M16xN64 mapping.
// CTA = (y-pair, b): M=256 px, N=64 och, K=64ci x 9 taps.
//  DUAL=false: out = relu( F * (ms_o*spa + md_o) )
//  DUAL=true : out = relu( D * md_o*(1-spa) + F*spa ), D = A x (W*diag(md))
// ---------------------------------------------------------------------------
template<bool DUAL>
__global__ void __launch_bounds__(512, 1)
conv_mma(const float* __restrict__ x0, const float* __restrict__ spa, int layer)
{
    extern __shared__ __align__(128) char sm[];
    const u32 smb  = (u32)__cvta_generic_to_shared(sm);
    const int tid  = threadIdx.x;
    const int wid  = tid >> 5;
    const int lane = tid & 31;

    const int y0 = blockIdx.x * 2;
    const int b  = blockIdx.y;
    const int kinds = DUAL ? 4 : 2;

    float* s_md = (float*)(sm + OFF_MD);
    float* s_ms = (float*)(sm + OFF_MS);
    if (tid < Cn) { s_md[tid] = g_md[layer][tid]; s_ms[tid] = g_ms[layer][tid]; }

    // weight stager: tap t -> buffer bi (16B cp.async chunks)
    auto stageW = [&](int t, int bi){
        const char* src = (const char*)&g_wt[layer][t][0][0];
        const u32 dst0 = smb + OFF_W + (u32)bi*W_BUF_STRIDE;
        const int n16 = kinds * 512;             // kinds * 8KB / 16B
#pragma unroll 1
        for (int idx = tid; idx < n16; idx += 512) {
            int kind = idx >> 9, i = idx & 511;
            int o = i >> 3, seg = i & 7;
            cp16(dst0 + (u32)(kind*W_KIND_STRIDE + o*W_O_STRIDE + seg*16),
                 src + kind*8192 + o*128 + seg*16);
        }
        cp_commit();
    };

    // ---- stage input: 4 halo rows (y0-1 .. y0+2), bf16 hi/lo, xp = x+1 ----
    const float* in  = (layer == 0) ? x0 : g_feat[layer-1];
    const float* inb = in + b*IMG;
    stageW(0, 0);
#pragma unroll 1
    for (int idx = tid; idx < 4*Cn*130; idx += 512) {
        int r   = idx / (Cn*130);
        int rem = idx - r*(Cn*130);
        int ci  = rem / 130;
        int xp  = rem - ci*130;
        int yy = y0 - 1 + r;
        int x  = xp - 1;
        float v = 0.f;
        if ((unsigned)yy < Hn && (unsigned)x < Wn) v = inb[ci*HWn + yy*Wn + x];
        __nv_bfloat16 h = __float2bfloat16(v);
        __nv_bfloat16 l = __float2bfloat16(v - __bfloat162float(h));
        char* p = sm + OFF_PX + r*PX_ROW_STRIDE + xp*PX_XP_STRIDE + ci*2;
        *(__nv_bfloat16*)p         = h;
        *(__nv_bfloat16*)(p + 128) = l;
    }

    // warp tile: mq = M position (32 px), nq = N half (32 och)
    const int mq    = wid & 7;            // 0..7
    const int nq    = wid >> 3;           // 0 or 1
    const int yrow  = mq >> 2;            // 0 or 1
    const int xbase = (mq & 3) << 5;      // 0,32,64,96
    const int y     = y0 + yrow;
    const int obase = nq << 5;            // 0 or 32

    // A ldmatrix lane offset (rows 0-15 = k-lo 16B, rows 16-31 = k-hi)
    const u32 a_lane = (u32)((lane & 15)*PX_XP_STRIDE + ((lane >> 4) << 4));
    // B ldmatrix lane offset: grp0 = nt0 k-lo, grp1 = nt0 k-hi, grp2/3 = nt1
    const int lrow = lane & 7, lgrp = lane >> 3;
    const u32 b_lane = (u32)(((lgrp >> 1)*8 + lrow)*W_O_STRIDE + (lgrp & 1)*16);

    float accF[2][4][4], accD[2][4][4];
#pragma unroll
    for (int mt = 0; mt < 2; ++mt)
#pragma unroll
        for (int n = 0; n < 4; ++n)
#pragma unroll
            for (int j = 0; j < 4; ++j) {
                accF[mt][n][j] = 0.f;
                if (DUAL) accD[mt][n][j] = 0.f;
            }

#pragma unroll 1
    for (int t = 0; t < 9; ++t) {
        const int bi = t & 1;
        if (t < 8) stageW(t+1, bi^1);
        if (t < 8) cp_wait<1>(); else cp_wait<0>();
        __syncthreads();

        const int ky = t/3, kx = t - (t/3)*3;
        const u32 abase = smb + OFF_PX
                        + (u32)((ky + yrow)*PX_ROW_STRIDE)
                        + (u32)((kx + xbase)*PX_XP_STRIDE)
                        + a_lane;
        const u32 wbase = smb + OFF_W + (u32)bi*W_BUF_STRIDE
                        + (u32)(obase*W_O_STRIDE) + b_lane;

#pragma unroll
        for (int kk = 0; kk < 4; ++kk) {
            u32 Ah[2][4], Al[2][4];
            ldmat4(Ah[0], abase + kk*32);
            ldmat4(Al[0], abase + kk*32 + 128);
            ldmat4(Ah[1], abase + 16*PX_XP_STRIDE + kk*32);
            ldmat4(Al[1], abase + 16*PX_XP_STRIDE + kk*32 + 128);
#pragma unroll
            for (int ntp = 0; ntp < 2; ++ntp) {
                const u32 wb = wbase + (u32)(ntp*16*W_O_STRIDE + kk*32);
                const int n0 = ntp*2, n1 = n0 + 1;
                if (DUAL) {
                    u32 Bh[4], Bl[4], Bmh[4], Bml[4];
                    ldmat4(Bh,  wb);
                    ldmat4(Bl,  wb + W_KIND_STRIDE);
                    ldmat4(Bmh, wb + 2*W_KIND_STRIDE);
                    ldmat4(Bml, wb + 3*W_KIND_STRIDE);
                    // term Ah*Bh / Ah*Bmh (8 chains)
                    mma16816(accF[0][n0], Ah[0], Bh[0],  Bh[1]);
                    mma16816(accF[0][n1], Ah[0], Bh[2],  Bh[3]);
                    mma16816(accF[1][n0], Ah[1], Bh[0],  Bh[1]);
                    mma16816(accF[1][n1], Ah[1], Bh[2],  Bh[3]);
                    mma16816(accD[0][n0], Ah[0], Bmh[0], Bmh[1]);
                    mma16816(accD[0][n1], Ah[0], Bmh[2], Bmh[3]);
                    mma16816(accD[1][n0], Ah[1], Bmh[0], Bmh[1]);
                    mma16816(accD[1][n1], Ah[1], Bmh[2], Bmh[3]);
                    // term Al*Bh / Al*Bmh
                    mma16816(accF[0][n0], Al[0], Bh[0],  Bh[1]);
                    mma16816(accF[0][n1], Al[0], Bh[2],  Bh[3]);
                    mma16816(accF[1][n0], Al[1], Bh[0],  Bh[1]);
                    mma16816(accF[1][n1], Al[1], Bh[2],  Bh[3]);
                    mma16816(accD[0][n0], Al[0], Bmh[0], Bmh[1]);
                    mma16816(accD[0][n1], Al[0], Bmh[2], Bmh[3]);
                    mma16816(accD[1][n0], Al[1], Bmh[0], Bmh[1]);
                    mma16816(accD[1][n1], Al[1], Bmh[2], Bmh[3]);
                    // term Ah*Bl / Ah*Bml
                    mma16816(accF[0][n0], Ah[0], Bl[0],  Bl[1]);
                    mma16816(accF[0][n1], Ah[0], Bl[2],  Bl[3]);
                    mma16816(accF[1][n0], Ah[1], Bl[0],  Bl[1]);
                    mma16816(accF[1][n1], Ah[1], Bl[2],  Bl[3]);
                    mma16816(accD[0][n0], Ah[0], Bml[0], Bml[1]);
                    mma16816(accD[0][n1], Ah[0], Bml[2], Bml[3]);
                    mma16816(accD[1][n0], Ah[1], Bml[0], Bml[1]);
                    mma16816(accD[1][n1], Ah[1], Bml[2], Bml[3]);
                } else {
                    u32 Bh[4], Bl[4];
                    ldmat4(Bh, wb);
                    ldmat4(Bl, wb + W_KIND_STRIDE);
                    mma16816(accF[0][n0], Ah[0], Bh[0], Bh[1]);
                    mma16816(accF[0][n1], Ah[0], Bh[2], Bh[3]);
                    mma16816(accF[1][n0], Ah[1], Bh[0], Bh[1]);
                    mma16816(accF[1][n1], Ah[1], Bh[2], Bh[3]);
                    mma16816(accF[0][n0], Al[0], Bh[0], Bh[1]);
                    mma16816(accF[0][n1], Al[0], Bh[2], Bh[3]);
                    mma16816(accF[1][n0], Al[1], Bh[0], Bh[1]);
                    mma16816(accF[1][n1], Al[1], Bh[2], Bh[3]);
                    mma16816(accF[0][n0], Ah[0], Bl[0], Bl[1]);
                    mma16816(accF[0][n1], Ah[0], Bl[2], Bl[3]);
                    mma16816(accF[1][n0], Ah[1], Bl[0], Bl[1]);
                    mma16816(accF[1][n1], Ah[1], Bl[2], Bl[3]);
                }
            }
        }
        __syncthreads();
    }

    // ---- fused gate + ReLU epilogue ----
    const int g  = lane >> 2;
    const int t4 = lane & 3;
    float* ob = g_feat[layer] + b*IMG + y*Wn;

#pragma unroll
    for (int mt = 0; mt < 2; ++mt) {
        const int xA = xbase + mt*16 + g;
        const int xB = xA + 8;
        const float spA = spa[b*HWn + y*Wn + xA];
        const float spB = spa[b*HWn + y*Wn + xB];
#pragma unroll
        for (int nt = 0; nt < 4; ++nt) {
            const int o0 = obase + nt*8 + 2*t4, o1 = o0 + 1;
            float r0, r1, r2, r3;
            if (!DUAL) {
                r0 = accF[mt][nt][0] * (s_ms[o0]*spA + s_md[o0]);
                r1 = accF[mt][nt][1] * (s_ms[o1]*spA + s_md[o1]);
                r2 = accF[mt][nt][2] * (s_ms[o0]*spB + s_md[o0]);
                r3 = accF[mt][nt][3] * (s_ms[o1]*spB + s_md[o1]);
            } else {
                r0 = accD[mt][nt][0]*s_md[o0]*(1.f-spA) + accF[mt][nt][0]*spA;
                r1 = accD[mt][nt][1]*s_md[o1]*(1.f-spA) + accF[mt][nt][1]*spA;
                r2 = accD[mt][nt][2]*s_md[o0]*(1.f-spB) + accF[mt][nt][2]*spB;
                r3 = accD[mt][nt][3]*s_md[o1]*(1.f-spB) + accF[mt][nt][3]*spB;
            }
            ob[o0*HWn + xA] = fmaxf(r0, 0.f);
            ob[o1*HWn + xA] = fmaxf(r1, 0.f);
            ob[o0*HWn + xB] = fmaxf(r2, 0.f);
            ob[o1*HWn + xB] = fmaxf(r3, 0.f);
        }
    }
}

// ---------------------------------------------------------------------------
// Final 1x1 conv over the concat, pixel-paired f32x2, cp.async-prefetched cat.
// ---------------------------------------------------------------------------
__global__ void __launch_bounds__(256)
final_kernel(const float* __restrict__ wc, const float* __restrict__ bc,
             float* __restrict__ outp)
{
    __shared__ u64 s_wcd[16*64];                     // [kk][o] dup'd
    __shared__ __align__(16) float s_cat[2][16*256]; // [buf][kk][px]

    const int blk = blockIdx.x;
    const int b   = blk >> 6;
    const int p0  = (blk & 63) * 256;
    const int tid = threadIdx.x;
    const int og  = tid >> 5;
    const int pg  = tid & 31;
    const int o0  = og << 3;

    const u32 wsh  = (u32)__cvta_generic_to_shared(s_wcd) + (u32)o0*8u;
    const u32 cat0 = (u32)__cvta_generic_to_shared(&s_cat[0][0]);

    auto stage_cat = [&](int k0, int bufi){
        const float* src = g_feat[k0 >> 6] + (b*Cn + (k0 & 63))*HWn + p0;
        const u32 dst = cat0 + (u32)bufi*16384;
#pragma unroll
        for (int it = 0; it < 4; ++it) {
            int idx = tid + it*256;           // 1024 x 16B
            int kk = idx >> 6, c4 = idx & 63;
            cp16(dst + (u32)(kk*1024 + c4*16), src + kk*HWn + c4*4);
        }
        cp_commit();
    };

    u64 acc[8][4];
#pragma unroll
    for (int u = 0; u < 8; ++u)
#pragma unroll
        for (int j = 0; j < 4; ++j) acc[u][j] = 0ull;

    stage_cat(0, 0);
    for (int k0 = 0; k0 < 256; k0 += 16) {
        const int bufi = (k0 >> 4) & 1;
        __syncthreads();                      // prior reads of s_wcd/s_cat done
        if (k0 < 240) stage_cat(k0 + 16, bufi^1);
        for (int idx = tid; idx < 16*64; idx += 256) {
            int kk = idx >> 6, o = idx & 63;
            s_wcd[kk*64 + o] = dup2(wc[o*256 + k0 + kk]);
        }
        if (k0 < 240) cp_wait<1>(); else cp_wait<0>();
        __syncthreads();

        const u32 csh = cat0 + (u32)bufi*16384 + (u32)pg*8u;
#pragma unroll
        for (int kk = 0; kk < 16; ++kk) {
            u64 wv[8];
            ldsw(wv[0], wv[1], wsh + kk*512);
            ldsw(wv[2], wv[3], wsh + kk*512 + 16);
            ldsw(wv[4], wv[5], wsh + kk*512 + 32);
            ldsw(wv[6], wv[7], wsh + kk*512 + 48);
            u64 cv[4];
#pragma unroll
            for (int j = 0; j < 4; ++j)
                cv[j] = ldsu64(csh + kk*1024 + j*256);
#pragma unroll
            for (int u = 0; u < 8; ++u)
#pragma unroll
                for (int j = 0; j < 4; ++j)
                    acc[u][j] = ffma2(wv[u], cv[j], acc[u][j]);
        }
    }

#pragma unroll
    for (int u = 0; u < 8; ++u) {
        const int o = o0 + u;
        const u64 b2 = dup2(bc[o]);
        float* q = outp + (b*Cn + o)*HWn + p0;
#pragma unroll
        for (int j = 0; j < 4; ++j)
            *(u64*)(q + 2*(pg + 32*j)) = fadd2(acc[u][j], b2);
    }
}

// ---------------------------------------------------------------------------
extern "C" void kernel_launch(void* const* d_in, const int* in_sizes, int n_in,
                              void* d_out, int out_size)
{
    const float* x0  = (const float*)d_in[0];
    const float* spa = (const float*)d_in[1];
    const float* gum = (const float*)d_in[2];
    const float* par = (const float*)d_in[3];
    const float* w0  = (const float*)d_in[4];
    const float* w1  = (const float*)d_in[5];
    const float* w2  = (const float*)d_in[6];
    const float* w3  = (const float*)d_in[7];
    const float* wc  = (const float*)d_in[8];
    const float* bc  = (const float*)d_in[9];

    float* outp = (float*)d_out;
    float* tail = outp + (out_size - 512);   // ch_mask (1,64,4,2) after main out

    cudaFuncSetAttribute(conv_mma<false>,
                         cudaFuncAttributeMaxDynamicSharedMemorySize, SMEM_MMA);
    cudaFuncSetAttribute(conv_mma<true>,
                         cudaFuncAttributeMaxDynamicSharedMemorySize, SMEM_MMA);

    mask_kernel<<<1, 64>>>(gum, par, tail);
    prep_kernel<<<(4*9*Cn*Cn + 255)/256, 256>>>(w0, w1, w2, w3);

    dim3 grid(Hn/2, Bn);    // (y-pair, batch) = 64 x 16 = 1024 CTAs
    conv_mma<false><<<grid, 512, SMEM_MMA>>>(x0, spa, 0);
    conv_mma<true ><<<grid, 512, SMEM_MMA>>>(x0, spa, 1);
    conv_mma<true ><<<grid, 512, SMEM_MMA>>>(x0, spa, 2);
    conv_mma<true ><<<grid, 512, SMEM_MMA>>>(x0, spa, 3);

    final_kernel<<<Bn*64, 256>>>(wc, bc, outp);
}

// round 11
// speedup vs baseline: 2.9414x; 1.1881x over previous
#include <cuda_runtime.h>
#include <cuda_fp16.h>
#include <math.h>
#include <stdint.h>

typedef unsigned long long u64;
typedef unsigned int u32;

#define Bn 16
#define Cn 64
#define Hn 128
#define Wn 128
#define HWn (Hn*Wn)
#define IMG (Cn*HWn)

// scratch
__device__ float g_feat[4][Bn*IMG];
__device__ float g_md[4][Cn];
__device__ float g_ms[4][Cn];
// fp16 weights: [layer][tap][kind: 0=w, 1=w*md_ci][o*64+ci]
__device__ __half g_wt[4][9][2][Cn*Cn];

// ---------------- smem layout for conv_mma (bytes) ---------------------------
#define PX_XP_STRIDE 272
#define PX_ROW_STRIDE (130*PX_XP_STRIDE)       // 35360
#define OFF_PX 0
#define PX_BYTES (4*PX_ROW_STRIDE)             // 141440
// weights double-buffered: [buf][kind][o], 144B per o
#define OFF_W  PX_BYTES
#define W_O_STRIDE 144
#define W_KIND_STRIDE (64*W_O_STRIDE)          // 9216
#define W_BUF_STRIDE (2*W_KIND_STRIDE)         // 18432
#define OFF_MD (OFF_W + 2*W_BUF_STRIDE)        // 178304
#define OFF_MS (OFF_MD + 256)
#define SMEM_MMA (OFF_MS + 256)                // 178816

// ---------------- warp-mma helpers (baseline PTX, no 'a' features) -----------
// non-volatile: pure register op, let ptxas schedule freely
__device__ __forceinline__ void mma16816(float* c, const u32* a, u32 b0, u32 b1){
    asm("mma.sync.aligned.m16n8k16.row.col.f32.f16.f16.f32 "
        "{%0,%1,%2,%3},{%4,%5,%6,%7},{%8,%9},{%0,%1,%2,%3};"
        : "+f"(c[0]),"+f"(c[1]),"+f"(c[2]),"+f"(c[3])
        : "r"(a[0]),"r"(a[1]),"r"(a[2]),"r"(a[3]), "r"(b0),"r"(b1));
}
__device__ __forceinline__ void ldmat4(u32* r, u32 addr){
    asm volatile("ldmatrix.sync.aligned.m8n8.x4.shared.b16 {%0,%1,%2,%3},[%4];"
                 : "=r"(r[0]),"=r"(r[1]),"=r"(r[2]),"=r"(r[3]) : "r"(addr));
}
__device__ __forceinline__ void cp16(u32 dst, const void* src){
    asm volatile("cp.async.cg.shared.global [%0], [%1], 16;"
                 :: "r"(dst), "l"(src) : "memory");
}
__device__ __forceinline__ void cp_commit(){
    asm volatile("cp.async.commit_group;" ::: "memory");
}
template<int N>
__device__ __forceinline__ void cp_wait(){
    asm volatile("cp.async.wait_group %0;" :: "n"(N) : "memory");
}

// ---------------- f32x2 helpers (final 1x1 kernel) ---------------------------
__device__ __forceinline__ u64 dup2(float x){
    u64 r; asm("mov.b64 %0,{%1,%1};" : "=l"(r) : "f"(x)); return r;
}
__device__ __forceinline__ u64 ffma2(u64 a, u64 b, u64 c){
    u64 d; asm("fma.rn.f32x2 %0,%1,%2,%3;" : "=l"(d) : "l"(a), "l"(b), "l"(c)); return d;
}
__device__ __forceinline__ u64 fadd2(u64 a, u64 b){
    u64 d; asm("add.rn.f32x2 %0,%1,%2;" : "=l"(d) : "l"(a), "l"(b)); return d;
}
__device__ __forceinline__ void ldsw(u64&a, u64&b, u32 addr){
    asm volatile("ld.shared.v2.u64 {%0,%1},[%2];" : "=l"(a),"=l"(b) : "r"(addr));
}
__device__ __forceinline__ u64 ldsu64(u32 addr){
    u64 r; asm volatile("ld.shared.b64 %0,[%1];" : "=l"(r) : "r"(addr)); return r;
}

// ---------------------------------------------------------------------------
// Gumbel-softmax channel mask
// ---------------------------------------------------------------------------
__global__ void mask_kernel(const float* __restrict__ gum,
                            const float* __restrict__ par,
                            float* __restrict__ out_tail)
{
    int c = threadIdx.x;
    if (c >= Cn) return;
#pragma unroll
    for (int l = 0; l < 4; ++l) {
        int i0 = c*8 + l*2;
        float g0 = -logf(-logf(gum[i0]));
        float g1 = -logf(-logf(gum[i0+1]));
        float l0 = par[i0]   + g0;
        float l1 = par[i0+1] + g1;
        float e  = expf(l1 - l0);
        float m0 = 1.0f/(1.0f+e);
        float m1 = e/(1.0f+e);
        g_md[l][c] = m0;
        g_ms[l][c] = m1;
        out_tail[i0]   = m0;
        out_tail[i0+1] = m1;
    }
}

// ---------------------------------------------------------------------------
// Weight prep: fp16 W and W*md_ci, layout [o][ci] per tap.
// ---------------------------------------------------------------------------
__global__ void prep_kernel(const float* __restrict__ w0, const float* __restrict__ w1,
                            const float* __restrict__ w2, const float* __restrict__ w3)
{
    int idx = blockIdx.x*256 + threadIdx.x;   // 4*9*4096 total
    if (idx >= 4*9*Cn*Cn) return;
    int l  = idx / (9*Cn*Cn);
    int r  = idx - l*(9*Cn*Cn);
    int t  = r / (Cn*Cn);
    int oc = r - t*(Cn*Cn);
    int o = oc >> 6, ci = oc & 63;
    const float* ws = (l==0) ? w0 : (l==1) ? w1 : (l==2) ? w2 : w3;
    float v = ws[(o*Cn + ci)*9 + t];
    g_wt[l][t][0][oc] = __float2half(v);
    g_wt[l][t][1][oc] = __float2half(v * g_md[l][ci]);
}

// ---------------------------------------------------------------------------
// Warp-MMA conv layer: mma.sync m16n8k16 fp16, 2-term A hi/lo split
// (A = Ah + Al in fp16; B single fp16 -> 2 MMAs per accumulation vs 3).
// Warp tile M32 x N32. CTA = (y-pair, b): M=256 px, N=64, K=64ci x 9 taps.
//  DUAL=false: out = relu( F * (ms_o*spa + md_o) )
//  DUAL=true : out = relu( D * md_o*(1-spa) + F*spa ), D = A x (W*diag(md))
// ---------------------------------------------------------------------------
template<bool DUAL>
__global__ void __launch_bounds__(512, 1)
conv_mma(const float* __restrict__ x0, const float* __restrict__ spa, int layer)
{
    extern __shared__ __align__(128) char sm[];
    const u32 smb  = (u32)__cvta_generic_to_shared(sm);
    const int tid  = threadIdx.x;
    const int lane = tid & 31;
    const int wid  = tid >> 5;

    const int y0 = blockIdx.x * 2;
    const int b  = blockIdx.y;
    const int kinds = DUAL ? 2 : 1;

    float* s_md = (float*)(sm + OFF_MD);
    float* s_ms = (float*)(sm + OFF_MS);
    if (tid < Cn) { s_md[tid] = g_md[layer][tid]; s_ms[tid] = g_ms[layer][tid]; }

    // weight stager: tap t -> buffer bi (16B cp.async chunks)
    auto stageW = [&](int t, int bi){
        const char* src = (const char*)&g_wt[layer][t][0][0];
        const u32 dst0 = smb + OFF_W + (u32)bi*W_BUF_STRIDE;
        const int n16 = kinds * 512;             // kinds * 8KB / 16B
#pragma unroll 1
        for (int idx = tid; idx < n16; idx += 512) {
            int kind = idx >> 9, i = idx & 511;
            int o = i >> 3, seg = i & 7;
            cp16(dst0 + (u32)(kind*W_KIND_STRIDE + o*W_O_STRIDE + seg*16),
                 src + kind*8192 + o*128 + seg*16);
        }
        cp_commit();
    };

    // ---- stage input: 4 halo rows (y0-1 .. y0+2), fp16 hi/lo, xp = x+1 ----
    const float* in  = (layer == 0) ? x0 : g_feat[layer-1];
    const float* inb = in + b*IMG;
    stageW(0, 0);
#pragma unroll 1
    for (int idx = tid; idx < 4*Cn*130; idx += 512) {
        int r   = idx / (Cn*130);
        int rem = idx - r*(Cn*130);
        int ci  = rem / 130;
        int xp  = rem - ci*130;
        int yy = y0 - 1 + r;
        int x  = xp - 1;
        float v = 0.f;
        if ((unsigned)yy < Hn && (unsigned)x < Wn) v = inb[ci*HWn + yy*Wn + x];
        __half h = __float2half(v);
        __half l = __float2half(v - __half2float(h));
        char* p = sm + OFF_PX + r*PX_ROW_STRIDE + xp*PX_XP_STRIDE + ci*2;
        *(__half*)p         = h;
        *(__half*)(p + 128) = l;
    }

    // warp tile: mq = M position (32 px), nq = N half (32 och)
    const int mq    = wid & 7;            // 0..7
    const int nq    = wid >> 3;           // 0 or 1
    const int yrow  = mq >> 2;            // 0 or 1
    const int xbase = (mq & 3) << 5;      // 0,32,64,96
    const int y     = y0 + yrow;
    const int obase = nq << 5;            // 0 or 32

    // A ldmatrix lane offset (rows 0-15 = k-lo 16B, rows 16-31 = k-hi)
    const u32 a_lane = (u32)((lane & 15)*PX_XP_STRIDE + ((lane >> 4) << 4));
    // B ldmatrix lane offset: grp0 = nt0 k-lo, grp1 = nt0 k-hi, grp2/3 = nt1
    const int lrow = lane & 7, lgrp = lane >> 3;
    const u32 b_lane = (u32)(((lgrp >> 1)*8 + lrow)*W_O_STRIDE + (lgrp & 1)*16);

    float accF[2][4][4], accD[2][4][4];
#pragma unroll
    for (int mt = 0; mt < 2; ++mt)
#pragma unroll
        for (int n = 0; n < 4; ++n)
#pragma unroll
            for (int j = 0; j < 4; ++j) {
                accF[mt][n][j] = 0.f;
                if (DUAL) accD[mt][n][j] = 0.f;
            }

#pragma unroll 1
    for (int t = 0; t < 9; ++t) {
        const int bi = t & 1;
        if (t < 8) stageW(t+1, bi^1);
        if (t < 8) cp_wait<1>(); else cp_wait<0>();
        __syncthreads();

        const int ky = t/3, kx = t - (t/3)*3;
        const u32 abase = smb + OFF_PX
                        + (u32)((ky + yrow)*PX_ROW_STRIDE)
                        + (u32)((kx + xbase)*PX_XP_STRIDE)
                        + a_lane;
        const u32 wbase = smb + OFF_W + (u32)bi*W_BUF_STRIDE
                        + (u32)(obase*W_O_STRIDE) + b_lane;

#pragma unroll
        for (int kk = 0; kk < 4; ++kk) {
            u32 Ah[2][4], Al[2][4];
            ldmat4(Ah[0], abase + kk*32);
            ldmat4(Al[0], abase + kk*32 + 128);
            ldmat4(Ah[1], abase + 16*PX_XP_STRIDE + kk*32);
            ldmat4(Al[1], abase + 16*PX_XP_STRIDE + kk*32 + 128);
#pragma unroll
            for (int ntp = 0; ntp < 2; ++ntp) {
                const u32 wb = wbase + (u32)(ntp*16*W_O_STRIDE + kk*32);
                const int n0 = ntp*2, n1 = n0 + 1;
                if (DUAL) {
                    u32 Bh[4], Bm[4];
                    ldmat4(Bh, wb);
                    ldmat4(Bm, wb + W_KIND_STRIDE);
                    mma16816(accF[0][n0], Ah[0], Bh[0], Bh[1]);
                    mma16816(accF[0][n1], Ah[0], Bh[2], Bh[3]);
                    mma16816(accF[1][n0], Ah[1], Bh[0], Bh[1]);
                    mma16816(accF[1][n1], Ah[1], Bh[2], Bh[3]);
                    mma16816(accD[0][n0], Ah[0], Bm[0], Bm[1]);
                    mma16816(accD[0][n1], Ah[0], Bm[2], Bm[3]);
                    mma16816(accD[1][n0], Ah[1], Bm[0], Bm[1]);
                    mma16816(accD[1][n1], Ah[1], Bm[2], Bm[3]);
                    mma16816(accF[0][n0], Al[0], Bh[0], Bh[1]);
                    mma16816(accF[0][n1], Al[0], Bh[2], Bh[3]);
                    mma16816(accF[1][n0], Al[1], Bh[0], Bh[1]);
                    mma16816(accF[1][n1], Al[1], Bh[2], Bh[3]);
                    mma16816(accD[0][n0], Al[0], Bm[0], Bm[1]);
                    mma16816(accD[0][n1], Al[0], Bm[2], Bm[3]);
                    mma16816(accD[1][n0], Al[1], Bm[0], Bm[1]);
                    mma16816(accD[1][n1], Al[1], Bm[2], Bm[3]);
                } else {
                    u32 Bh[4];
                    ldmat4(Bh, wb);
                    mma16816(accF[0][n0], Ah[0], Bh[0], Bh[1]);
                    mma16816(accF[0][n1], Ah[0], Bh[2], Bh[3]);
                    mma16816(accF[1][n0], Ah[1], Bh[0], Bh[1]);
                    mma16816(accF[1][n1], Ah[1], Bh[2], Bh[3]);
                    mma16816(accF[0][n0], Al[0], Bh[0], Bh[1]);
                    mma16816(accF[0][n1], Al[0], Bh[2], Bh[3]);
                    mma16816(accF[1][n0], Al[1], Bh[0], Bh[1]);
                    mma16816(accF[1][n1], Al[1], Bh[2], Bh[3]);
                }
            }
        }
        __syncthreads();
    }

    // ---- fused gate + ReLU epilogue ----
    const int g  = lane >> 2;
    const int t4 = lane & 3;
    float* ob = g_feat[layer] + b*IMG + y*Wn;

#pragma unroll
    for (int mt = 0; mt < 2; ++mt) {
        const int xA = xbase + mt*16 + g;
        const int xB = xA + 8;
        const float spA = spa[b*HWn + y*Wn + xA];
        const float spB = spa[b*HWn + y*Wn + xB];
#pragma unroll
        for (int nt = 0; nt < 4; ++nt) {
            const int o0 = obase + nt*8 + 2*t4, o1 = o0 + 1;
            float r0, r1, r2, r3;
            if (!DUAL) {
                r0 = accF[mt][nt][0] * (s_ms[o0]*spA + s_md[o0]);
                r1 = accF[mt][nt][1] * (s_ms[o1]*spA + s_md[o1]);
                r2 = accF[mt][nt][2] * (s_ms[o0]*spB + s_md[o0]);
                r3 = accF[mt][nt][3] * (s_ms[o1]*spB + s_md[o1]);
            } else {
                r0 = accD[mt][nt][0]*s_md[o0]*(1.f-spA) + accF[mt][nt][0]*spA;
                r1 = accD[mt][nt][1]*s_md[o1]*(1.f-spA) + accF[mt][nt][1]*spA;
                r2 = accD[mt][nt][2]*s_md[o0]*(1.f-spB) + accF[mt][nt][2]*spB;
                r3 = accD[mt][nt][3]*s_md[o1]*(1.f-spB) + accF[mt][nt][3]*spB;
            }
            ob[o0*HWn + xA] = fmaxf(r0, 0.f);
            ob[o1*HWn + xA] = fmaxf(r1, 0.f);
            ob[o0*HWn + xB] = fmaxf(r2, 0.f);
            ob[o1*HWn + xB] = fmaxf(r3, 0.f);
        }
    }
}

// ---------------------------------------------------------------------------
// Final 1x1 conv over the concat, pixel-paired f32x2, cp.async-prefetched cat.
// ---------------------------------------------------------------------------
__global__ void __launch_bounds__(256)
final_kernel(const float* __restrict__ wc, const float* __restrict__ bc,
             float* __restrict__ outp)
{
    __shared__ u64 s_wcd[16*64];                     // [kk][o] dup'd
    __shared__ __align__(16) float s_cat[2][16*256]; // [buf][kk][px]

    const int blk = blockIdx.x;
    const int b   = blk >> 6;
    const int p0  = (blk & 63) * 256;
    const int tid = threadIdx.x;
    const int og  = tid >> 5;
    const int pg  = tid & 31;
    const int o0  = og << 3;

    const u32 wsh  = (u32)__cvta_generic_to_shared(s_wcd) + (u32)o0*8u;
    const u32 cat0 = (u32)__cvta_generic_to_shared(&s_cat[0][0]);

    auto stage_cat = [&](int k0, int bufi){
        const float* src = g_feat[k0 >> 6] + (b*Cn + (k0 & 63))*HWn + p0;
        const u32 dst = cat0 + (u32)bufi*16384;
#pragma unroll
        for (int it = 0; it < 4; ++it) {
            int idx = tid + it*256;           // 1024 x 16B
            int kk = idx >> 6, c4 = idx & 63;
            cp16(dst + (u32)(kk*1024 + c4*16), src + kk*HWn + c4*4);
        }
        cp_commit();
    };

    u64 acc[8][4];
#pragma unroll
    for (int u = 0; u < 8; ++u)
#pragma unroll
        for (int j = 0; j < 4; ++j) acc[u][j] = 0ull;

    stage_cat(0, 0);
    for (int k0 = 0; k0 < 256; k0 += 16) {
        const int bufi = (k0 >> 4) & 1;
        __syncthreads();                      // prior reads of s_wcd/s_cat done
        if (k0 < 240) stage_cat(k0 + 16, bufi^1);
        for (int idx = tid; idx < 16*64; idx += 256) {
            int kk = idx >> 6, o = idx & 63;
            s_wcd[kk*64 + o] = dup2(wc[o*256 + k0 + kk]);
        }
        if (k0 < 240) cp_wait<1>(); else cp_wait<0>();
        __syncthreads();

        const u32 csh = cat0 + (u32)bufi*16384 + (u32)pg*8u;
#pragma unroll
        for (int kk = 0; kk < 16; ++kk) {
            u64 wv[8];
            ldsw(wv[0], wv[1], wsh + kk*512);
            ldsw(wv[2], wv[3], wsh + kk*512 + 16);
            ldsw(wv[4], wv[5], wsh + kk*512 + 32);
            ldsw(wv[6], wv[7], wsh + kk*512 + 48);
            u64 cv[4];
#pragma unroll
            for (int j = 0; j < 4; ++j)
                cv[j] = ldsu64(csh + kk*1024 + j*256);
#pragma unroll
            for (int u = 0; u < 8; ++u)
#pragma unroll
                for (int j = 0; j < 4; ++j)
                    acc[u][j] = ffma2(wv[u], cv[j], acc[u][j]);
        }
    }

#pragma unroll
    for (int u = 0; u < 8; ++u) {
        const int o = o0 + u;
        const u64 b2 = dup2(bc[o]);
        float* q = outp + (b*Cn + o)*HWn + p0;
#pragma unroll
        for (int j = 0; j < 4; ++j)
            *(u64*)(q + 2*(pg + 32*j)) = fadd2(acc[u][j], b2);
    }
}

// ---------------------------------------------------------------------------
extern "C" void kernel_launch(void* const* d_in, const int* in_sizes, int n_in,
                              void* d_out, int out_size)
{
    const float* x0  = (const float*)d_in[0];
    const float* spa = (const float*)d_in[1];
    const float* gum = (const float*)d_in[2];
    const float* par = (const float*)d_in[3];
    const float* w0  = (const float*)d_in[4];
    const float* w1  = (const float*)d_in[5];
    const float* w2  = (const float*)d_in[6];
    const float* w3  = (const float*)d_in[7];
    const float* wc  = (const float*)d_in[8];
    const float* bc  = (const float*)d_in[9];

    float* outp = (float*)d_out;
    float* tail = outp + (out_size - 512);   // ch_mask (1,64,4,2) after main out

    cudaFuncSetAttribute(conv_mma<false>,
                         cudaFuncAttributeMaxDynamicSharedMemorySize, SMEM_MMA);
    cudaFuncSetAttribute(conv_mma<true>,
                         cudaFuncAttributeMaxDynamicSharedMemorySize, SMEM_MMA);

    mask_kernel<<<1, 64>>>(gum, par, tail);
    prep_kernel<<<(4*9*Cn*Cn + 255)/256, 256>>>(w0, w1, w2, w3);

    dim3 grid(Hn/2, Bn);    // (y-pair, batch) = 64 x 16 = 1024 CTAs
    conv_mma<false><<<grid, 512, SMEM_MMA>>>(x0, spa, 0);
    conv_mma<true ><<<grid, 512, SMEM_MMA>>>(x0, spa, 1);
    conv_mma<true ><<<grid, 512, SMEM_MMA>>>(x0, spa, 2);
    conv_mma<true ><<<grid, 512, SMEM_MMA>>>(x0, spa, 3);

    final_kernel<<<Bn*64, 256>>>(wc, bc, outp);
}

// round 12
// speedup vs baseline: 3.5780x; 1.2164x over previous
#include <cuda_runtime.h>
#include <cuda_fp16.h>
#include <math.h>
#include <stdint.h>

typedef unsigned long long u64;
typedef unsigned int u32;

#define Bn 16
#define Cn 64
#define Hn 128
#define Wn 128
#define HWn (Hn*Wn)
#define IMG (Cn*HWn)

// scratch
__device__ float g_feat[4][Bn*IMG];
__device__ float g_md[4][Cn];
__device__ float g_ms[4][Cn];
// fp16 weights: [layer][tap][kind: 0=w, 1=w*md_ci][o*64+ci]
__device__ __half g_wt[4][9][2][Cn*Cn];

// ---------------- smem layout for conv_mma (bytes) ---------------------------
// input: single fp16 plane, [row 0..3][xp 0..129][ci 0..63], 144B per xp
#define PX_XP_STRIDE 144
#define PX_ROW_STRIDE (130*PX_XP_STRIDE)       // 18720
#define OFF_PX 0
#define PX_BYTES (4*PX_ROW_STRIDE)             // 74880
// weights double-buffered per-ky: [buf][kx 0..2][kind 0..1][o], 144B per o
#define OFF_W  PX_BYTES
#define W_O_STRIDE 144
#define W_KIND_STRIDE (64*W_O_STRIDE)          // 9216
#define W_KX_STRIDE (2*W_KIND_STRIDE)          // 18432
#define W_BUF_STRIDE (3*W_KX_STRIDE)           // 55296
#define OFF_MD (OFF_W + 2*W_BUF_STRIDE)        // 185472
#define OFF_MS (OFF_MD + 256)
#define SMEM_MMA (OFF_MS + 256)                // 185984

// ---------------- warp-mma helpers (baseline PTX, no 'a' features) -----------
__device__ __forceinline__ void mma16816(float* c, const u32* a, u32 b0, u32 b1){
    asm("mma.sync.aligned.m16n8k16.row.col.f32.f16.f16.f32 "
        "{%0,%1,%2,%3},{%4,%5,%6,%7},{%8,%9},{%0,%1,%2,%3};"
        : "+f"(c[0]),"+f"(c[1]),"+f"(c[2]),"+f"(c[3])
        : "r"(a[0]),"r"(a[1]),"r"(a[2]),"r"(a[3]), "r"(b0),"r"(b1));
}
__device__ __forceinline__ void ldmat4(u32* r, u32 addr){
    asm volatile("ldmatrix.sync.aligned.m8n8.x4.shared.b16 {%0,%1,%2,%3},[%4];"
                 : "=r"(r[0]),"=r"(r[1]),"=r"(r[2]),"=r"(r[3]) : "r"(addr));
}
__device__ __forceinline__ void cp16(u32 dst, const void* src){
    asm volatile("cp.async.cg.shared.global [%0], [%1], 16;"
                 :: "r"(dst), "l"(src) : "memory");
}
__device__ __forceinline__ void cp_commit(){
    asm volatile("cp.async.commit_group;" ::: "memory");
}
template<int N>
__device__ __forceinline__ void cp_wait(){
    asm volatile("cp.async.wait_group %0;" :: "n"(N) : "memory");
}

// ---------------- f32x2 helpers (final 1x1 kernel) ---------------------------
__device__ __forceinline__ u64 dup2(float x){
    u64 r; asm("mov.b64 %0,{%1,%1};" : "=l"(r) : "f"(x)); return r;
}
__device__ __forceinline__ u64 ffma2(u64 a, u64 b, u64 c){
    u64 d; asm("fma.rn.f32x2 %0,%1,%2,%3;" : "=l"(d) : "l"(a), "l"(b), "l"(c)); return d;
}
__device__ __forceinline__ u64 fadd2(u64 a, u64 b){
    u64 d; asm("add.rn.f32x2 %0,%1,%2;" : "=l"(d) : "l"(a), "l"(b)); return d;
}
__device__ __forceinline__ void ldsw(u64&a, u64&b, u32 addr){
    asm volatile("ld.shared.v2.u64 {%0,%1},[%2];" : "=l"(a),"=l"(b) : "r"(addr));
}
__device__ __forceinline__ u64 ldsu64(u32 addr){
    u64 r; asm volatile("ld.shared.b64 %0,[%1];" : "=l"(r) : "r"(addr)); return r;
}

// ---------------------------------------------------------------------------
// Gumbel-softmax channel mask
// ---------------------------------------------------------------------------
__global__ void mask_kernel(const float* __restrict__ gum,
                            const float* __restrict__ par,
                            float* __restrict__ out_tail)
{
    int c = threadIdx.x;
    if (c >= Cn) return;
#pragma unroll
    for (int l = 0; l < 4; ++l) {
        int i0 = c*8 + l*2;
        float g0 = -logf(-logf(gum[i0]));
        float g1 = -logf(-logf(gum[i0+1]));
        float l0 = par[i0]   + g0;
        float l1 = par[i0+1] + g1;
        float e  = expf(l1 - l0);
        float m0 = 1.0f/(1.0f+e);
        float m1 = e/(1.0f+e);
        g_md[l][c] = m0;
        g_ms[l][c] = m1;
        out_tail[i0]   = m0;
        out_tail[i0+1] = m1;
    }
}

// ---------------------------------------------------------------------------
// Weight prep: fp16 W and W*md_ci, layout [o][ci] per tap.
// ---------------------------------------------------------------------------
__global__ void prep_kernel(const float* __restrict__ w0, const float* __restrict__ w1,
                            const float* __restrict__ w2, const float* __restrict__ w3)
{
    int idx = blockIdx.x*256 + threadIdx.x;   // 4*9*4096 total
    if (idx >= 4*9*Cn*Cn) return;
    int l  = idx / (9*Cn*Cn);
    int r  = idx - l*(9*Cn*Cn);
    int t  = r / (Cn*Cn);
    int oc = r - t*(Cn*Cn);
    int o = oc >> 6, ci = oc & 63;
    const float* ws = (l==0) ? w0 : (l==1) ? w1 : (l==2) ? w2 : w3;
    float v = ws[(o*Cn + ci)*9 + t];
    g_wt[l][t][0][oc] = __float2half(v);
    g_wt[l][t][1][oc] = __float2half(v * g_md[l][ci]);
}

// ---------------------------------------------------------------------------
// Warp-MMA conv layer: mma.sync m16n8k16 fp16 (single A plane).
// Per-ky weight staging (3 taps/stage, double-buffered) -> 6 syncs per CTA.
// Warp tile M32 x N32. CTA = (y-pair, b): M=256 px, N=64, K=64ci x 9 taps.
//  DUAL=false: out = relu( F * (ms_o*spa + md_o) )
//  DUAL=true : out = relu( D * md_o*(1-spa) + F*spa ), D = A x (W*diag(md))
// ---------------------------------------------------------------------------
template<bool DUAL>
__global__ void __launch_bounds__(512, 1)
conv_mma(const float* __restrict__ x0, const float* __restrict__ spa, int layer)
{
    extern __shared__ __align__(128) char sm[];
    const u32 smb  = (u32)__cvta_generic_to_shared(sm);
    const int tid  = threadIdx.x;
    const int lane = tid & 31;
    const int wid  = tid >> 5;

    const int y0 = blockIdx.x * 2;
    const int b  = blockIdx.y;
    const int kinds = DUAL ? 2 : 1;

    float* s_md = (float*)(sm + OFF_MD);
    float* s_ms = (float*)(sm + OFF_MS);
    if (tid < Cn) { s_md[tid] = g_md[layer][tid]; s_ms[tid] = g_ms[layer][tid]; }

    // weight stager: ky row (3 taps) -> buffer bi, 16B cp.async chunks
    auto stageW = [&](int ky, int bi){
        const u32 dst0 = smb + OFF_W + (u32)bi*W_BUF_STRIDE;
        const int n16 = 3 * kinds * 512;
#pragma unroll 1
        for (int idx = tid; idx < n16; idx += 512) {
            int kx   = idx / (kinds*512);
            int rem  = idx - kx*(kinds*512);
            int kind = rem >> 9, i = rem & 511;
            int o = i >> 3, seg = i & 7;
            cp16(dst0 + (u32)(kx*W_KX_STRIDE + kind*W_KIND_STRIDE
                              + o*W_O_STRIDE + seg*16),
                 (const char*)&g_wt[layer][3*ky+kx][kind][0] + o*128 + seg*16);
        }
        cp_commit();
    };

    // ---- stage input: 4 halo rows (y0-1 .. y0+2), single fp16 plane --------
    const float* in  = (layer == 0) ? x0 : g_feat[layer-1];
    const float* inb = in + b*IMG;
    stageW(0, 0);
#pragma unroll 1
    for (int idx = tid; idx < 4*Cn*130; idx += 512) {
        int r   = idx / (Cn*130);
        int rem = idx - r*(Cn*130);
        int ci  = rem / 130;
        int xp  = rem - ci*130;
        int yy = y0 - 1 + r;
        int x  = xp - 1;
        float v = 0.f;
        if ((unsigned)yy < Hn && (unsigned)x < Wn) v = inb[ci*HWn + yy*Wn + x];
        *(__half*)(sm + OFF_PX + r*PX_ROW_STRIDE + xp*PX_XP_STRIDE + ci*2)
            = __float2half(v);
    }

    // warp tile: mq = M position (32 px), nq = N half (32 och)
    const int mq    = wid & 7;            // 0..7
    const int nq    = wid >> 3;           // 0 or 1
    const int yrow  = mq >> 2;            // 0 or 1
    const int xbase = (mq & 3) << 5;      // 0,32,64,96
    const int y     = y0 + yrow;
    const int obase = nq << 5;            // 0 or 32

    // A ldmatrix lane offset (rows 0-15 = k-lo 16B, rows 16-31 = k-hi)
    const u32 a_lane = (u32)((lane & 15)*PX_XP_STRIDE + ((lane >> 4) << 4));
    // B ldmatrix lane offset: grp0 = nt0 k-lo, grp1 = nt0 k-hi, grp2/3 = nt1
    const int lrow = lane & 7, lgrp = lane >> 3;
    const u32 b_lane = (u32)(((lgrp >> 1)*8 + lrow)*W_O_STRIDE + (lgrp & 1)*16);

    float accF[2][4][4], accD[2][4][4];
#pragma unroll
    for (int mt = 0; mt < 2; ++mt)
#pragma unroll
        for (int n = 0; n < 4; ++n)
#pragma unroll
            for (int j = 0; j < 4; ++j) {
                accF[mt][n][j] = 0.f;
                if (DUAL) accD[mt][n][j] = 0.f;
            }

#pragma unroll 1
    for (int ky = 0; ky < 3; ++ky) {
        const int bi = ky & 1;
        if (ky < 2) stageW(ky+1, bi^1);
        if (ky < 2) cp_wait<1>(); else cp_wait<0>();
        __syncthreads();

#pragma unroll
        for (int kx = 0; kx < 3; ++kx) {
            const u32 abase = smb + OFF_PX
                            + (u32)((ky + yrow)*PX_ROW_STRIDE)
                            + (u32)((kx + xbase)*PX_XP_STRIDE)
                            + a_lane;
            const u32 wbase = smb + OFF_W + (u32)bi*W_BUF_STRIDE
                            + (u32)(kx*W_KX_STRIDE)
                            + (u32)(obase*W_O_STRIDE) + b_lane;
#pragma unroll
            for (int kk = 0; kk < 4; ++kk) {
                u32 Ah[2][4];
                ldmat4(Ah[0], abase + kk*32);
                ldmat4(Ah[1], abase + 16*PX_XP_STRIDE + kk*32);
#pragma unroll
                for (int ntp = 0; ntp < 2; ++ntp) {
                    const u32 wb = wbase + (u32)(ntp*16*W_O_STRIDE + kk*32);
                    const int n0 = ntp*2, n1 = n0 + 1;
                    if (DUAL) {
                        u32 Bh[4], Bm[4];
                        ldmat4(Bh, wb);
                        ldmat4(Bm, wb + W_KIND_STRIDE);
                        mma16816(accF[0][n0], Ah[0], Bh[0], Bh[1]);
                        mma16816(accF[0][n1], Ah[0], Bh[2], Bh[3]);
                        mma16816(accF[1][n0], Ah[1], Bh[0], Bh[1]);
                        mma16816(accF[1][n1], Ah[1], Bh[2], Bh[3]);
                        mma16816(accD[0][n0], Ah[0], Bm[0], Bm[1]);
                        mma16816(accD[0][n1], Ah[0], Bm[2], Bm[3]);
                        mma16816(accD[1][n0], Ah[1], Bm[0], Bm[1]);
                        mma16816(accD[1][n1], Ah[1], Bm[2], Bm[3]);
                    } else {
                        u32 Bh[4];
                        ldmat4(Bh, wb);
                        mma16816(accF[0][n0], Ah[0], Bh[0], Bh[1]);
                        mma16816(accF[0][n1], Ah[0], Bh[2], Bh[3]);
                        mma16816(accF[1][n0], Ah[1], Bh[0], Bh[1]);
                        mma16816(accF[1][n1], Ah[1], Bh[2], Bh[3]);
                    }
                }
            }
        }
        __syncthreads();
    }

    // ---- fused gate + ReLU epilogue ----
    const int g  = lane >> 2;
    const int t4 = lane & 3;
    float* ob = g_feat[layer] + b*IMG + y*Wn;

#pragma unroll
    for (int mt = 0; mt < 2; ++mt) {
        const int xA = xbase + mt*16 + g;
        const int xB = xA + 8;
        const float spA = spa[b*HWn + y*Wn + xA];
        const float spB = spa[b*HWn + y*Wn + xB];
#pragma unroll
        for (int nt = 0; nt < 4; ++nt) {
            const int o0 = obase + nt*8 + 2*t4, o1 = o0 + 1;
            float r0, r1, r2, r3;
            if (!DUAL) {
                r0 = accF[mt][nt][0] * (s_ms[o0]*spA + s_md[o0]);
                r1 = accF[mt][nt][1] * (s_ms[o1]*spA + s_md[o1]);
                r2 = accF[mt][nt][2] * (s_ms[o0]*spB + s_md[o0]);
                r3 = accF[mt][nt][3] * (s_ms[o1]*spB + s_md[o1]);
            } else {
                r0 = accD[mt][nt][0]*s_md[o0]*(1.f-spA) + accF[mt][nt][0]*spA;
                r1 = accD[mt][nt][1]*s_md[o1]*(1.f-spA) + accF[mt][nt][1]*spA;
                r2 = accD[mt][nt][2]*s_md[o0]*(1.f-spB) + accF[mt][nt][2]*spB;
                r3 = accD[mt][nt][3]*s_md[o1]*(1.f-spB) + accF[mt][nt][3]*spB;
            }
            ob[o0*HWn + xA] = fmaxf(r0, 0.f);
            ob[o1*HWn + xA] = fmaxf(r1, 0.f);
            ob[o0*HWn + xB] = fmaxf(r2, 0.f);
            ob[o1*HWn + xB] = fmaxf(r3, 0.f);
        }
    }
}

// ---------------------------------------------------------------------------
// Final 1x1 conv over the concat, pixel-paired f32x2, cp.async-prefetched cat.
// ---------------------------------------------------------------------------
__global__ void __launch_bounds__(256)
final_kernel(const float* __restrict__ wc, const float* __restrict__ bc,
             float* __restrict__ outp)
{
    __shared__ u64 s_wcd[16*64];                     // [kk][o] dup'd
    __shared__ __align__(16) float s_cat[2][16*256]; // [buf][kk][px]

    const int blk = blockIdx.x;
    const int b   = blk >> 6;
    const int p0  = (blk & 63) * 256;
    const int tid = threadIdx.x;
    const int og  = tid >> 5;
    const int pg  = tid & 31;
    const int o0  = og << 3;

    const u32 wsh  = (u32)__cvta_generic_to_shared(s_wcd) + (u32)o0*8u;
    const u32 cat0 = (u32)__cvta_generic_to_shared(&s_cat[0][0]);

    auto stage_cat = [&](int k0, int bufi){
        const float* src = g_feat[k0 >> 6] + (b*Cn + (k0 & 63))*HWn + p0;
        const u32 dst = cat0 + (u32)bufi*16384;
#pragma unroll
        for (int it = 0; it < 4; ++it) {
            int idx = tid + it*256;           // 1024 x 16B
            int kk = idx >> 6, c4 = idx & 63;
            cp16(dst + (u32)(kk*1024 + c4*16), src + kk*HWn + c4*4);
        }
        cp_commit();
    };

    u64 acc[8][4];
#pragma unroll
    for (int u = 0; u < 8; ++u)
#pragma unroll
        for (int j = 0; j < 4; ++j) acc[u][j] = 0ull;

    stage_cat(0, 0);
    for (int k0 = 0; k0 < 256; k0 += 16) {
        const int bufi = (k0 >> 4) & 1;
        __syncthreads();                      // prior reads of s_wcd/s_cat done
        if (k0 < 240) stage_cat(k0 + 16, bufi^1);
        for (int idx = tid; idx < 16*64; idx += 256) {
            int kk = idx >> 6, o = idx & 63;
            s_wcd[kk*64 + o] = dup2(wc[o*256 + k0 + kk]);
        }
        if (k0 < 240) cp_wait<1>(); else cp_wait<0>();
        __syncthreads();

        const u32 csh = cat0 + (u32)bufi*16384 + (u32)pg*8u;
#pragma unroll
        for (int kk = 0; kk < 16; ++kk) {
            u64 wv[8];
            ldsw(wv[0], wv[1], wsh + kk*512);
            ldsw(wv[2], wv[3], wsh + kk*512 + 16);
            ldsw(wv[4], wv[5], wsh + kk*512 + 32);
            ldsw(wv[6], wv[7], wsh + kk*512 + 48);
            u64 cv[4];
#pragma unroll
            for (int j = 0; j < 4; ++j)
                cv[j] = ldsu64(csh + kk*1024 + j*256);
#pragma unroll
            for (int u = 0; u < 8; ++u)
#pragma unroll
                for (int j = 0; j < 4; ++j)
                    acc[u][j] = ffma2(wv[u], cv[j], acc[u][j]);
        }
    }

#pragma unroll
    for (int u = 0; u < 8; ++u) {
        const int o = o0 + u;
        const u64 b2 = dup2(bc[o]);
        float* q = outp + (b*Cn + o)*HWn + p0;
#pragma unroll
        for (int j = 0; j < 4; ++j)
            *(u64*)(q + 2*(pg + 32*j)) = fadd2(acc[u][j], b2);
    }
}

// ---------------------------------------------------------------------------
extern "C" void kernel_launch(void* const* d_in, const int* in_sizes, int n_in,
                              void* d_out, int out_size)
{
    const float* x0  = (const float*)d_in[0];
    const float* spa = (const float*)d_in[1];
    const float* gum = (const float*)d_in[2];
    const float* par = (const float*)d_in[3];
    const float* w0  = (const float*)d_in[4];
    const float* w1  = (const float*)d_in[5];
    const float* w2  = (const float*)d_in[6];
    const float* w3  = (const float*)d_in[7];
    const float* wc  = (const float*)d_in[8];
    const float* bc  = (const float*)d_in[9];

    float* outp = (float*)d_out;
    float* tail = outp + (out_size - 512);   // ch_mask (1,64,4,2) after main out

    cudaFuncSetAttribute(conv_mma<false>,
                         cudaFuncAttributeMaxDynamicSharedMemorySize, SMEM_MMA);
    cudaFuncSetAttribute(conv_mma<true>,
                         cudaFuncAttributeMaxDynamicSharedMemorySize, SMEM_MMA);

    mask_kernel<<<1, 64>>>(gum, par, tail);
    prep_kernel<<<(4*9*Cn*Cn + 255)/256, 256>>>(w0, w1, w2, w3);

    dim3 grid(Hn/2, Bn);    // (y-pair, batch) = 64 x 16 = 1024 CTAs
    conv_mma<false><<<grid, 512, SMEM_MMA>>>(x0, spa, 0);
    conv_mma<true ><<<grid, 512, SMEM_MMA>>>(x0, spa, 1);
    conv_mma<true ><<<grid, 512, SMEM_MMA>>>(x0, spa, 2);
    conv_mma<true ><<<grid, 512, SMEM_MMA>>>(x0, spa, 3);

    final_kernel<<<Bn*64, 256>>>(wc, bc, outp);
}

// round 13
// speedup vs baseline: 6.3565x; 1.7765x over previous
#include <cuda_runtime.h>
#include <cuda_fp16.h>
#include <math.h>
#include <stdint.h>

typedef unsigned long long u64;
typedef unsigned int u32;

#define Bn 16
#define Cn 64
#define Hn 128
#define Wn 128
#define HWn (Hn*Wn)
#define IMG (Cn*HWn)

// scratch
__device__ float g_feat[4][Bn*IMG];
__device__ float g_md[4][Cn];
__device__ float g_ms[4][Cn];
// fp16 weights: [layer][tap][kind: 0=w, 1=w*md_ci][o*64+ci]
__device__ __half g_wt[4][9][2][Cn*Cn];
// fp16 NHWC features (layers 0..2), consumed by the next conv layer's A staging
__device__ __half g16[3][(u64)Bn*HWn*Cn];

// ---------------- smem layout for conv_mma (bytes) ---------------------------
// input: single fp16 plane, [row 0..3][xp 0..129][ci 0..63], 144B per xp
#define PX_XP_STRIDE 144
#define PX_ROW_STRIDE (130*PX_XP_STRIDE)       // 18720
#define OFF_PX 0
#define PX_BYTES (4*PX_ROW_STRIDE)             // 74880
// weights double-buffered per-ky: [buf][kx 0..2][kind 0..1][o], 144B per o
#define OFF_W  PX_BYTES
#define W_O_STRIDE 144
#define W_KIND_STRIDE (64*W_O_STRIDE)          // 9216
#define W_KX_STRIDE (2*W_KIND_STRIDE)          // 18432
#define W_BUF_STRIDE (3*W_KX_STRIDE)           // 55296
#define OFF_MD (OFF_W + 2*W_BUF_STRIDE)        // 185472
#define OFF_MS (OFF_MD + 256)
#define SMEM_MMA (OFF_MS + 256)                // 185984

// ---------------- warp-mma helpers (baseline PTX, no 'a' features) -----------
__device__ __forceinline__ void mma16816(float* c, const u32* a, u32 b0, u32 b1){
    asm("mma.sync.aligned.m16n8k16.row.col.f32.f16.f16.f32 "
        "{%0,%1,%2,%3},{%4,%5,%6,%7},{%8,%9},{%0,%1,%2,%3};"
        : "+f"(c[0]),"+f"(c[1]),"+f"(c[2]),"+f"(c[3])
        : "r"(a[0]),"r"(a[1]),"r"(a[2]),"r"(a[3]), "r"(b0),"r"(b1));
}
__device__ __forceinline__ void ldmat4(u32* r, u32 addr){
    asm volatile("ldmatrix.sync.aligned.m8n8.x4.shared.b16 {%0,%1,%2,%3},[%4];"
                 : "=r"(r[0]),"=r"(r[1]),"=r"(r[2]),"=r"(r[3]) : "r"(addr));
}
__device__ __forceinline__ void cp16(u32 dst, const void* src){
    asm volatile("cp.async.cg.shared.global [%0], [%1], 16;"
                 :: "r"(dst), "l"(src) : "memory");
}
__device__ __forceinline__ void cp_commit(){
    asm volatile("cp.async.commit_group;" ::: "memory");
}
template<int N>
__device__ __forceinline__ void cp_wait(){
    asm volatile("cp.async.wait_group %0;" :: "n"(N) : "memory");
}

// ---------------- f32x2 helpers (final 1x1 kernel) ---------------------------
__device__ __forceinline__ u64 dup2(float x){
    u64 r; asm("mov.b64 %0,{%1,%1};" : "=l"(r) : "f"(x)); return r;
}
__device__ __forceinline__ u64 ffma2(u64 a, u64 b, u64 c){
    u64 d; asm("fma.rn.f32x2 %0,%1,%2,%3;" : "=l"(d) : "l"(a), "l"(b), "l"(c)); return d;
}
__device__ __forceinline__ u64 fadd2(u64 a, u64 b){
    u64 d; asm("add.rn.f32x2 %0,%1,%2;" : "=l"(d) : "l"(a), "l"(b)); return d;
}
__device__ __forceinline__ void ldsw(u64&a, u64&b, u32 addr){
    asm volatile("ld.shared.v2.u64 {%0,%1},[%2];" : "=l"(a),"=l"(b) : "r"(addr));
}
__device__ __forceinline__ u64 ldsu64(u32 addr){
    u64 r; asm volatile("ld.shared.b64 %0,[%1];" : "=l"(r) : "r"(addr)); return r;
}

// ---------------------------------------------------------------------------
// Gumbel-softmax channel mask
// ---------------------------------------------------------------------------
__global__ void mask_kernel(const float* __restrict__ gum,
                            const float* __restrict__ par,
                            float* __restrict__ out_tail)
{
    int c = threadIdx.x;
    if (c >= Cn) return;
#pragma unroll
    for (int l = 0; l < 4; ++l) {
        int i0 = c*8 + l*2;
        float g0 = -logf(-logf(gum[i0]));
        float g1 = -logf(-logf(gum[i0+1]));
        float l0 = par[i0]   + g0;
        float l1 = par[i0+1] + g1;
        float e  = expf(l1 - l0);
        float m0 = 1.0f/(1.0f+e);
        float m1 = e/(1.0f+e);
        g_md[l][c] = m0;
        g_ms[l][c] = m1;
        out_tail[i0]   = m0;
        out_tail[i0+1] = m1;
    }
}

// ---------------------------------------------------------------------------
// Weight prep: fp16 W and W*md_ci, layout [o][ci] per tap.
// ---------------------------------------------------------------------------
__global__ void prep_kernel(const float* __restrict__ w0, const float* __restrict__ w1,
                            const float* __restrict__ w2, const float* __restrict__ w3)
{
    int idx = blockIdx.x*256 + threadIdx.x;   // 4*9*4096 total
    if (idx >= 4*9*Cn*Cn) return;
    int l  = idx / (9*Cn*Cn);
    int r  = idx - l*(9*Cn*Cn);
    int t  = r / (Cn*Cn);
    int oc = r - t*(Cn*Cn);
    int o = oc >> 6, ci = oc & 63;
    const float* ws = (l==0) ? w0 : (l==1) ? w1 : (l==2) ? w2 : w3;
    float v = ws[(o*Cn + ci)*9 + t];
    g_wt[l][t][0][oc] = __float2half(v);
    g_wt[l][t][1][oc] = __float2half(v * g_md[l][ci]);
}

// ---------------------------------------------------------------------------
// Warp-MMA conv layer: mma.sync m16n8k16 fp16 (single A plane).
// Layers >=1 stage A via cp.async from fp16 NHWC g16 (no cvt, no STS scatter);
// layer 0 converts x0 fp32 NCHW on the fly. Per-ky weight staging, 6 syncs.
// Warp tile M32 x N32. CTA = (y-pair, b): M=256 px, N=64, K=64ci x 9 taps.
//  DUAL=false: out = relu( F * (ms_o*spa + md_o) )
//  DUAL=true : out = relu( D * md_o*(1-spa) + F*spa ), D = A x (W*diag(md))
// ---------------------------------------------------------------------------
template<bool DUAL>
__global__ void __launch_bounds__(512, 1)
conv_mma(const float* __restrict__ x0, const float* __restrict__ spa, int layer)
{
    extern __shared__ __align__(128) char sm[];
    const u32 smb  = (u32)__cvta_generic_to_shared(sm);
    const int tid  = threadIdx.x;
    const int lane = tid & 31;
    const int wid  = tid >> 5;

    const int y0 = blockIdx.x * 2;
    const int b  = blockIdx.y;
    const int kinds = DUAL ? 2 : 1;

    float* s_md = (float*)(sm + OFF_MD);
    float* s_ms = (float*)(sm + OFF_MS);
    if (tid < Cn) { s_md[tid] = g_md[layer][tid]; s_ms[tid] = g_ms[layer][tid]; }

    // weight stager: ky row (3 taps) -> buffer bi, 16B cp.async chunks
    auto stageW = [&](int ky, int bi){
        const u32 dst0 = smb + OFF_W + (u32)bi*W_BUF_STRIDE;
        const int n16 = 3 * kinds * 512;
#pragma unroll 1
        for (int idx = tid; idx < n16; idx += 512) {
            int kx   = idx / (kinds*512);
            int rem  = idx - kx*(kinds*512);
            int kind = rem >> 9, i = rem & 511;
            int o = i >> 3, seg = i & 7;
            cp16(dst0 + (u32)(kx*W_KX_STRIDE + kind*W_KIND_STRIDE
                              + o*W_O_STRIDE + seg*16),
                 (const char*)&g_wt[layer][3*ky+kx][kind][0] + o*128 + seg*16);
        }
        cp_commit();
    };

    stageW(0, 0);   // cp.async group 0

    // ---- stage input: 4 halo rows (y0-1 .. y0+2), single fp16 plane --------
    if (layer == 0) {
        const float* inb = x0 + b*IMG;
#pragma unroll 4
        for (int idx = tid; idx < 4*Cn*130; idx += 512) {
            int r   = idx / (Cn*130);
            int rem = idx - r*(Cn*130);
            int ci  = rem / 130;
            int xp  = rem - ci*130;
            int yy = y0 - 1 + r;
            int x  = xp - 1;
            float v = 0.f;
            if ((unsigned)yy < Hn && (unsigned)x < Wn) v = inb[ci*HWn + yy*Wn + x];
            *(__half*)(sm + OFF_PX + r*PX_ROW_STRIDE + xp*PX_XP_STRIDE + ci*2)
                = __float2half(v);
        }
    } else {
        const __half* src16 = g16[layer-1] + (u64)b*((u64)HWn*Cn);
        // zero the x-halo columns (xp=0 and xp=129), 4 rows x 128B each
        if (tid < 128) {
            int r = tid >> 5, col = (tid >> 4) & 1, i = tid & 15;
            *(u64*)(sm + OFF_PX + r*PX_ROW_STRIDE
                    + (col ? 129*PX_XP_STRIDE : 0) + i*8) = 0;
        }
#pragma unroll
        for (int r = 0; r < 4; ++r) {
            const int yy = y0 - 1 + r;
            if ((unsigned)yy < Hn) {
                const __half* rowsrc = src16 + (u64)yy*Wn*Cn;
#pragma unroll
                for (int it = 0; it < 2; ++it) {
                    int idx = tid + it*512;        // 1024 chunks: 128 px x 8 seg
                    int px = idx >> 3, seg = idx & 7;
                    cp16(smb + OFF_PX + (u32)(r*PX_ROW_STRIDE
                             + (px+1)*PX_XP_STRIDE + seg*16),
                         (const char*)(rowsrc + px*Cn) + seg*16);
                }
            } else {
                // zero full row (used 128B of each 144B slot)
#pragma unroll 1
                for (int i = tid; i < 130*16; i += 512)
                    *(u64*)(sm + OFF_PX + r*PX_ROW_STRIDE
                            + (i >> 4)*PX_XP_STRIDE + (i & 15)*8) = 0;
            }
        }
        cp_commit();    // cp.async group 1 (input)
    }

    // warp tile: mq = M position (32 px), nq = N half (32 och)
    const int mq    = wid & 7;            // 0..7
    const int nq    = wid >> 3;           // 0 or 1
    const int yrow  = mq >> 2;            // 0 or 1
    const int xbase = (mq & 3) << 5;      // 0,32,64,96
    const int y     = y0 + yrow;
    const int obase = nq << 5;            // 0 or 32

    // A ldmatrix lane offset (rows 0-15 = k-lo 16B, rows 16-31 = k-hi)
    const u32 a_lane = (u32)((lane & 15)*PX_XP_STRIDE + ((lane >> 4) << 4));
    // B ldmatrix lane offset: grp0 = nt0 k-lo, grp1 = nt0 k-hi, grp2/3 = nt1
    const int lrow = lane & 7, lgrp = lane >> 3;
    const u32 b_lane = (u32)(((lgrp >> 1)*8 + lrow)*W_O_STRIDE + (lgrp & 1)*16);

    float accF[2][4][4], accD[2][4][4];
#pragma unroll
    for (int mt = 0; mt < 2; ++mt)
#pragma unroll
        for (int n = 0; n < 4; ++n)
#pragma unroll
            for (int j = 0; j < 4; ++j) {
                accF[mt][n][j] = 0.f;
                if (DUAL) accD[mt][n][j] = 0.f;
            }

#pragma unroll 1
    for (int ky = 0; ky < 3; ++ky) {
        const int bi = ky & 1;
        if (ky < 2) stageW(ky+1, bi^1);
        if (ky < 2) cp_wait<1>(); else cp_wait<0>();
        __syncthreads();

#pragma unroll
        for (int kx = 0; kx < 3; ++kx) {
            const u32 abase = smb + OFF_PX
                            + (u32)((ky + yrow)*PX_ROW_STRIDE)
                            + (u32)((kx + xbase)*PX_XP_STRIDE)
                            + a_lane;
            const u32 wbase = smb + OFF_W + (u32)bi*W_BUF_STRIDE
                            + (u32)(kx*W_KX_STRIDE)
                            + (u32)(obase*W_O_STRIDE) + b_lane;
#pragma unroll
            for (int kk = 0; kk < 4; ++kk) {
                u32 Ah[2][4];
                ldmat4(Ah[0], abase + kk*32);
                ldmat4(Ah[1], abase + 16*PX_XP_STRIDE + kk*32);
#pragma unroll
                for (int ntp = 0; ntp < 2; ++ntp) {
                    const u32 wb = wbase + (u32)(ntp*16*W_O_STRIDE + kk*32);
                    const int n0 = ntp*2, n1 = n0 + 1;
                    if (DUAL) {
                        u32 Bh[4], Bm[4];
                        ldmat4(Bh, wb);
                        ldmat4(Bm, wb + W_KIND_STRIDE);
                        mma16816(accF[0][n0], Ah[0], Bh[0], Bh[1]);
                        mma16816(accF[0][n1], Ah[0], Bh[2], Bh[3]);
                        mma16816(accF[1][n0], Ah[1], Bh[0], Bh[1]);
                        mma16816(accF[1][n1], Ah[1], Bh[2], Bh[3]);
                        mma16816(accD[0][n0], Ah[0], Bm[0], Bm[1]);
                        mma16816(accD[0][n1], Ah[0], Bm[2], Bm[3]);
                        mma16816(accD[1][n0], Ah[1], Bm[0], Bm[1]);
                        mma16816(accD[1][n1], Ah[1], Bm[2], Bm[3]);
                    } else {
                        u32 Bh[4];
                        ldmat4(Bh, wb);
                        mma16816(accF[0][n0], Ah[0], Bh[0], Bh[1]);
                        mma16816(accF[0][n1], Ah[0], Bh[2], Bh[3]);
                        mma16816(accF[1][n0], Ah[1], Bh[0], Bh[1]);
                        mma16816(accF[1][n1], Ah[1], Bh[2], Bh[3]);
                    }
                }
            }
        }
        __syncthreads();
    }

    // ---- fused gate + ReLU epilogue: fp32 NCHW (for final) + fp16 NHWC ----
    const int g  = lane >> 2;
    const int t4 = lane & 3;
    float* ob = g_feat[layer] + b*IMG + y*Wn;
    __half* o16 = (layer < 3) ? (g16[layer] + ((u64)b*HWn + (u64)y*Wn)*Cn) : 0;

#pragma unroll
    for (int mt = 0; mt < 2; ++mt) {
        const int xA = xbase + mt*16 + g;
        const int xB = xA + 8;
        const float spA = spa[b*HWn + y*Wn + xA];
        const float spB = spa[b*HWn + y*Wn + xB];
#pragma unroll
        for (int nt = 0; nt < 4; ++nt) {
            const int o0 = obase + nt*8 + 2*t4, o1 = o0 + 1;
            float r0, r1, r2, r3;
            if (!DUAL) {
                r0 = accF[mt][nt][0] * (s_ms[o0]*spA + s_md[o0]);
                r1 = accF[mt][nt][1] * (s_ms[o1]*spA + s_md[o1]);
                r2 = accF[mt][nt][2] * (s_ms[o0]*spB + s_md[o0]);
                r3 = accF[mt][nt][3] * (s_ms[o1]*spB + s_md[o1]);
            } else {
                r0 = accD[mt][nt][0]*s_md[o0]*(1.f-spA) + accF[mt][nt][0]*spA;
                r1 = accD[mt][nt][1]*s_md[o1]*(1.f-spA) + accF[mt][nt][1]*spA;
                r2 = accD[mt][nt][2]*s_md[o0]*(1.f-spB) + accF[mt][nt][2]*spB;
                r3 = accD[mt][nt][3]*s_md[o1]*(1.f-spB) + accF[mt][nt][3]*spB;
            }
            r0 = fmaxf(r0, 0.f); r1 = fmaxf(r1, 0.f);
            r2 = fmaxf(r2, 0.f); r3 = fmaxf(r3, 0.f);
            ob[o0*HWn + xA] = r0;
            ob[o1*HWn + xA] = r1;
            ob[o0*HWn + xB] = r2;
            ob[o1*HWn + xB] = r3;
            if (layer < 3) {
                *(__half2*)(o16 + (u64)xA*Cn + o0) = __floats2half2_rn(r0, r1);
                *(__half2*)(o16 + (u64)xB*Cn + o0) = __floats2half2_rn(r2, r3);
            }
        }
    }
}

// ---------------------------------------------------------------------------
// Final 1x1 conv over the concat, pixel-paired f32x2, cp.async-prefetched cat.
// ---------------------------------------------------------------------------
__global__ void __launch_bounds__(256)
final_kernel(const float* __restrict__ wc, const float* __restrict__ bc,
             float* __restrict__ outp)
{
    __shared__ u64 s_wcd[16*64];                     // [kk][o] dup'd
    __shared__ __align__(16) float s_cat[2][16*256]; // [buf][kk][px]

    const int blk = blockIdx.x;
    const int b   = blk >> 6;
    const int p0  = (blk & 63) * 256;
    const int tid = threadIdx.x;
    const int og  = tid >> 5;
    const int pg  = tid & 31;
    const int o0  = og << 3;

    const u32 wsh  = (u32)__cvta_generic_to_shared(s_wcd) + (u32)o0*8u;
    const u32 cat0 = (u32)__cvta_generic_to_shared(&s_cat[0][0]);

    auto stage_cat = [&](int k0, int bufi){
        const float* src = g_feat[k0 >> 6] + (b*Cn + (k0 & 63))*HWn + p0;
        const u32 dst = cat0 + (u32)bufi*16384;
#pragma unroll
        for (int it = 0; it < 4; ++it) {
            int idx = tid + it*256;           // 1024 x 16B
            int kk = idx >> 6, c4 = idx & 63;
            cp16(dst + (u32)(kk*1024 + c4*16), src + kk*HWn + c4*4);
        }
        cp_commit();
    };

    u64 acc[8][4];
#pragma unroll
    for (int u = 0; u < 8; ++u)
#pragma unroll
        for (int j = 0; j < 4; ++j) acc[u][j] = 0ull;

    stage_cat(0, 0);
    for (int k0 = 0; k0 < 256; k0 += 16) {
        const int bufi = (k0 >> 4) & 1;
        __syncthreads();                      // prior reads of s_wcd/s_cat done
        if (k0 < 240) stage_cat(k0 + 16, bufi^1);
        for (int idx = tid; idx < 16*64; idx += 256) {
            int kk = idx >> 6, o = idx & 63;
            s_wcd[kk*64 + o] = dup2(wc[o*256 + k0 + kk]);
        }
        if (k0 < 240) cp_wait<1>(); else cp_wait<0>();
        __syncthreads();

        const u32 csh = cat0 + (u32)bufi*16384 + (u32)pg*8u;
#pragma unroll
        for (int kk = 0; kk < 16; ++kk) {
            u64 wv[8];
            ldsw(wv[0], wv[1], wsh + kk*512);
            ldsw(wv[2], wv[3], wsh + kk*512 + 16);
            ldsw(wv[4], wv[5], wsh + kk*512 + 32);
            ldsw(wv[6], wv[7], wsh + kk*512 + 48);
            u64 cv[4];
#pragma unroll
            for (int j = 0; j < 4; ++j)
                cv[j] = ldsu64(csh + kk*1024 + j*256);
#pragma unroll
            for (int u = 0; u < 8; ++u)
#pragma unroll
                for (int j = 0; j < 4; ++j)
                    acc[u][j] = ffma2(wv[u], cv[j], acc[u][j]);
        }
    }

#pragma unroll
    for (int u = 0; u < 8; ++u) {
        const int o = o0 + u;
        const u64 b2 = dup2(bc[o]);
        float* q = outp + (b*Cn + o)*HWn + p0;
#pragma unroll
        for (int j = 0; j < 4; ++j)
            *(u64*)(q + 2*(pg + 32*j)) = fadd2(acc[u][j], b2);
    }
}

// ---------------------------------------------------------------------------
extern "C" void kernel_launch(void* const* d_in, const int* in_sizes, int n_in,
                              void* d_out, int out_size)
{
    const float* x0  = (const float*)d_in[0];
    const float* spa = (const float*)d_in[1];
    const float* gum = (const float*)d_in[2];
    const float* par = (const float*)d_in[3];
    const float* w0  = (const float*)d_in[4];
    const float* w1  = (const float*)d_in[5];
    const float* w2  = (const float*)d_in[6];
    const float* w3  = (const float*)d_in[7];
    const float* wc  = (const float*)d_in[8];
    const float* bc  = (const float*)d_in[9];

    float* outp = (float*)d_out;
    float* tail = outp + (out_size - 512);   // ch_mask (1,64,4,2) after main out

    cudaFuncSetAttribute(conv_mma<false>,
                         cudaFuncAttributeMaxDynamicSharedMemorySize, SMEM_MMA);
    cudaFuncSetAttribute(conv_mma<true>,
                         cudaFuncAttributeMaxDynamicSharedMemorySize, SMEM_MMA);

    mask_kernel<<<1, 64>>>(gum, par, tail);
    prep_kernel<<<(4*9*Cn*Cn + 255)/256, 256>>>(w0, w1, w2, w3);

    dim3 grid(Hn/2, Bn);    // (y-pair, batch) = 64 x 16 = 1024 CTAs
    conv_mma<false><<<grid, 512, SMEM_MMA>>>(x0, spa, 0);
    conv_mma<true ><<<grid, 512, SMEM_MMA>>>(x0, spa, 1);
    conv_mma<true ><<<grid, 512, SMEM_MMA>>>(x0, spa, 2);
    conv_mma<true ><<<grid, 512, SMEM_MMA>>>(x0, spa, 3);

    final_kernel<<<Bn*64, 256>>>(wc, bc, outp);
}

// round 14
// speedup vs baseline: 9.7413x; 1.5325x over previous
#include <cuda_runtime.h>
#include <cuda_fp16.h>
#include <math.h>
#include <stdint.h>

typedef unsigned long long u64;
typedef unsigned int u32;

#define Bn 16
#define Cn 64
#define Hn 128
#define Wn 128
#define HWn (Hn*Wn)
#define IMG (Cn*HWn)

// scratch
__device__ float g_md[4][Cn];
__device__ float g_ms[4][Cn];
// fp16 weights: [layer][tap][kind: 0=w, 1=w*md_ci][o*64+ci]
__device__ __half g_wt[4][9][2][Cn*Cn];
// fp16 wc for final 1x1: [o][k=256]
__device__ __half g_wc[64*256];
// fp16 NHWC features: input (converted x0) + 4 conv layer outputs
__device__ __half g16in[(u64)Bn*HWn*Cn];
__device__ __half g16[4][(u64)Bn*HWn*Cn];

// ---------------- smem layout for conv_mma (bytes) ---------------------------
#define PX_XP_STRIDE 144
#define PX_ROW_STRIDE (130*PX_XP_STRIDE)       // 18720
#define OFF_PX 0
#define PX_BYTES (4*PX_ROW_STRIDE)             // 74880
#define OFF_W  PX_BYTES
#define W_O_STRIDE 144
#define W_KIND_STRIDE (64*W_O_STRIDE)          // 9216
#define W_KX_STRIDE (2*W_KIND_STRIDE)          // 18432
#define W_BUF_STRIDE (3*W_KX_STRIDE)           // 55296
#define OFF_MD (OFF_W + 2*W_BUF_STRIDE)        // 185472
#define OFF_MS (OFF_MD + 256)
#define SMEM_MMA (OFF_MS + 256)                // 185984

// ---------------- smem layout for final_mma (bytes) --------------------------
#define FA_PX_STRIDE 144
#define FA_BUF_STRIDE (256*FA_PX_STRIDE)       // 36864
#define F_OFF_A 0
#define F_OFF_B (2*FA_BUF_STRIDE)              // 73728
#define FB_O_STRIDE 528
#define SMEM_FIN (F_OFF_B + 64*FB_O_STRIDE)    // 107520

// ---------------- warp-mma helpers (baseline PTX, no 'a' features) -----------
__device__ __forceinline__ void mma16816(float* c, const u32* a, u32 b0, u32 b1){
    asm("mma.sync.aligned.m16n8k16.row.col.f32.f16.f16.f32 "
        "{%0,%1,%2,%3},{%4,%5,%6,%7},{%8,%9},{%0,%1,%2,%3};"
        : "+f"(c[0]),"+f"(c[1]),"+f"(c[2]),"+f"(c[3])
        : "r"(a[0]),"r"(a[1]),"r"(a[2]),"r"(a[3]), "r"(b0),"r"(b1));
}
__device__ __forceinline__ void ldmat4(u32* r, u32 addr){
    asm volatile("ldmatrix.sync.aligned.m8n8.x4.shared.b16 {%0,%1,%2,%3},[%4];"
                 : "=r"(r[0]),"=r"(r[1]),"=r"(r[2]),"=r"(r[3]) : "r"(addr));
}
__device__ __forceinline__ void cp16(u32 dst, const void* src){
    asm volatile("cp.async.cg.shared.global [%0], [%1], 16;"
                 :: "r"(dst), "l"(src) : "memory");
}
__device__ __forceinline__ void cp_commit(){
    asm volatile("cp.async.commit_group;" ::: "memory");
}
template<int N>
__device__ __forceinline__ void cp_wait(){
    asm volatile("cp.async.wait_group %0;" :: "n"(N) : "memory");
}

// ---------------------------------------------------------------------------
// Gumbel-softmax channel mask
// ---------------------------------------------------------------------------
__global__ void mask_kernel(const float* __restrict__ gum,
                            const float* __restrict__ par,
                            float* __restrict__ out_tail)
{
    int c = threadIdx.x;
    if (c >= Cn) return;
#pragma unroll
    for (int l = 0; l < 4; ++l) {
        int i0 = c*8 + l*2;
        float g0 = -logf(-logf(gum[i0]));
        float g1 = -logf(-logf(gum[i0+1]));
        float l0 = par[i0]   + g0;
        float l1 = par[i0+1] + g1;
        float e  = expf(l1 - l0);
        float m0 = 1.0f/(1.0f+e);
        float m1 = e/(1.0f+e);
        g_md[l][c] = m0;
        g_ms[l][c] = m1;
        out_tail[i0]   = m0;
        out_tail[i0+1] = m1;
    }
}

// ---------------------------------------------------------------------------
// Weight prep: fp16 W and W*md_ci per tap, plus fp16 wc for the final 1x1.
// ---------------------------------------------------------------------------
__global__ void prep_kernel(const float* __restrict__ w0, const float* __restrict__ w1,
                            const float* __restrict__ w2, const float* __restrict__ w3,
                            const float* __restrict__ wc)
{
    int idx = blockIdx.x*256 + threadIdx.x;
    if (idx < 4*9*Cn*Cn) {
        int l  = idx / (9*Cn*Cn);
        int r  = idx - l*(9*Cn*Cn);
        int t  = r / (Cn*Cn);
        int oc = r - t*(Cn*Cn);
        int ci = oc & 63;
        const float* ws = (l==0) ? w0 : (l==1) ? w1 : (l==2) ? w2 : w3;
        float v = ws[(oc >> 6)*(Cn*9) + ci*9 + t];
        g_wt[l][t][0][oc] = __float2half(v);
        g_wt[l][t][1][oc] = __float2half(v * g_md[l][ci]);
    } else {
        int i2 = idx - 4*9*Cn*Cn;
        if (i2 < 64*256) g_wc[i2] = __float2half(wc[i2]);
    }
}

// ---------------------------------------------------------------------------
// x0 NCHW fp32 -> NHWC fp16 (one image row per CTA)
// ---------------------------------------------------------------------------
__global__ void __launch_bounds__(256)
cvt_kernel(const float* __restrict__ x0)
{
    __shared__ __half s[128*65];
    const int y = blockIdx.x, b = blockIdx.y;
    const int tid = threadIdx.x;
#pragma unroll
    for (int it = 0; it < 32; ++it) {
        int idx = tid + it*256;
        int ci = idx >> 7, x = idx & 127;
        s[x*65 + ci] = __float2half(x0[(b*Cn + ci)*HWn + y*Wn + x]);
    }
    __syncthreads();
    __half* dst = g16in + ((u64)b*HWn + (u64)y*Wn)*Cn;
#pragma unroll
    for (int it = 0; it < 32; ++it) {
        int idx = tid + it*256;
        int x = idx >> 6, ci = idx & 63;
        dst[(u64)x*Cn + ci] = s[x*65 + ci];
    }
}

// ---------------------------------------------------------------------------
// Warp-MMA conv layer: mma.sync m16n8k16 fp16, cp.async NHWC A staging,
// per-ky double-buffered weights. Warp tile M32 x N32.
// CTA = (y-pair, b): M=256 px, N=64, K=64ci x 9 taps. Output: fp16 NHWC only.
//  DUAL=false: out = relu( F * (ms_o*spa + md_o) )
//  DUAL=true : out = relu( D * md_o*(1-spa) + F*spa ), D = A x (W*diag(md))
// ---------------------------------------------------------------------------
template<bool DUAL>
__global__ void __launch_bounds__(512, 1)
conv_mma(const float* __restrict__ spa, int layer)
{
    extern __shared__ __align__(128) char sm[];
    const u32 smb  = (u32)__cvta_generic_to_shared(sm);
    const int tid  = threadIdx.x;
    const int lane = tid & 31;
    const int wid  = tid >> 5;

    const int y0 = blockIdx.x * 2;
    const int b  = blockIdx.y;
    const int kinds = DUAL ? 2 : 1;

    float* s_md = (float*)(sm + OFF_MD);
    float* s_ms = (float*)(sm + OFF_MS);
    if (tid < Cn) { s_md[tid] = g_md[layer][tid]; s_ms[tid] = g_ms[layer][tid]; }

    auto stageW = [&](int ky, int bi){
        const u32 dst0 = smb + OFF_W + (u32)bi*W_BUF_STRIDE;
        const int n16 = 3 * kinds * 512;
#pragma unroll 1
        for (int idx = tid; idx < n16; idx += 512) {
            int kx   = idx / (kinds*512);
            int rem  = idx - kx*(kinds*512);
            int kind = rem >> 9, i = rem & 511;
            int o = i >> 3, seg = i & 7;
            cp16(dst0 + (u32)(kx*W_KX_STRIDE + kind*W_KIND_STRIDE
                              + o*W_O_STRIDE + seg*16),
                 (const char*)&g_wt[layer][3*ky+kx][kind][0] + o*128 + seg*16);
        }
        cp_commit();
    };

    stageW(0, 0);   // group 0

    // ---- stage input: 4 halo rows (y0-1 .. y0+2), fp16 NHWC via cp.async ---
    {
        const __half* src16 = (layer == 0)
            ? (g16in + (u64)b*((u64)HWn*Cn))
            : (g16[layer-1] + (u64)b*((u64)HWn*Cn));
        if (tid < 128) {
            int r = tid >> 5, col = (tid >> 4) & 1, i = tid & 15;
            *(u64*)(sm + OFF_PX + r*PX_ROW_STRIDE
                    + (col ? 129*PX_XP_STRIDE : 0) + i*8) = 0;
        }
#pragma unroll
        for (int r = 0; r < 4; ++r) {
            const int yy = y0 - 1 + r;
            if ((unsigned)yy < Hn) {
                const __half* rowsrc = src16 + (u64)yy*Wn*Cn;
#pragma unroll
                for (int it = 0; it < 2; ++it) {
                    int idx = tid + it*512;
                    int px = idx >> 3, seg = idx & 7;
                    cp16(smb + OFF_PX + (u32)(r*PX_ROW_STRIDE
                             + (px+1)*PX_XP_STRIDE + seg*16),
                         (const char*)(rowsrc + px*Cn) + seg*16);
                }
            } else {
#pragma unroll 1
                for (int i = tid; i < 130*16; i += 512)
                    *(u64*)(sm + OFF_PX + r*PX_ROW_STRIDE
                            + (i >> 4)*PX_XP_STRIDE + (i & 15)*8) = 0;
            }
        }
        cp_commit();    // group 1 (input)
    }

    const int mq    = wid & 7;
    const int nq    = wid >> 3;
    const int yrow  = mq >> 2;
    const int xbase = (mq & 3) << 5;
    const int y     = y0 + yrow;
    const int obase = nq << 5;

    const u32 a_lane = (u32)((lane & 15)*PX_XP_STRIDE + ((lane >> 4) << 4));
    const int lrow = lane & 7, lgrp = lane >> 3;
    const u32 b_lane = (u32)(((lgrp >> 1)*8 + lrow)*W_O_STRIDE + (lgrp & 1)*16);

    float accF[2][4][4], accD[2][4][4];
#pragma unroll
    for (int mt = 0; mt < 2; ++mt)
#pragma unroll
        for (int n = 0; n < 4; ++n)
#pragma unroll
            for (int j = 0; j < 4; ++j) {
                accF[mt][n][j] = 0.f;
                if (DUAL) accD[mt][n][j] = 0.f;
            }

#pragma unroll 1
    for (int ky = 0; ky < 3; ++ky) {
        const int bi = ky & 1;
        if (ky < 2) stageW(ky+1, bi^1);
        if (ky < 2) cp_wait<1>(); else cp_wait<0>();
        __syncthreads();

#pragma unroll
        for (int kx = 0; kx < 3; ++kx) {
            const u32 abase = smb + OFF_PX
                            + (u32)((ky + yrow)*PX_ROW_STRIDE)
                            + (u32)((kx + xbase)*PX_XP_STRIDE)
                            + a_lane;
            const u32 wbase = smb + OFF_W + (u32)bi*W_BUF_STRIDE
                            + (u32)(kx*W_KX_STRIDE)
                            + (u32)(obase*W_O_STRIDE) + b_lane;
#pragma unroll
            for (int kk = 0; kk < 4; ++kk) {
                u32 Ah[2][4];
                ldmat4(Ah[0], abase + kk*32);
                ldmat4(Ah[1], abase + 16*PX_XP_STRIDE + kk*32);
#pragma unroll
                for (int ntp = 0; ntp < 2; ++ntp) {
                    const u32 wb = wbase + (u32)(ntp*16*W_O_STRIDE + kk*32);
                    const int n0 = ntp*2, n1 = n0 + 1;
                    if (DUAL) {
                        u32 Bh[4], Bm[4];
                        ldmat4(Bh, wb);
                        ldmat4(Bm, wb + W_KIND_STRIDE);
                        mma16816(accF[0][n0], Ah[0], Bh[0], Bh[1]);
                        mma16816(accF[0][n1], Ah[0], Bh[2], Bh[3]);
                        mma16816(accF[1][n0], Ah[1], Bh[0], Bh[1]);
                        mma16816(accF[1][n1], Ah[1], Bh[2], Bh[3]);
                        mma16816(accD[0][n0], Ah[0], Bm[0], Bm[1]);
                        mma16816(accD[0][n1], Ah[0], Bm[2], Bm[3]);
                        mma16816(accD[1][n0], Ah[1], Bm[0], Bm[1]);
                        mma16816(accD[1][n1], Ah[1], Bm[2], Bm[3]);
                    } else {
                        u32 Bh[4];
                        ldmat4(Bh, wb);
                        mma16816(accF[0][n0], Ah[0], Bh[0], Bh[1]);
                        mma16816(accF[0][n1], Ah[0], Bh[2], Bh[3]);
                        mma16816(accF[1][n0], Ah[1], Bh[0], Bh[1]);
                        mma16816(accF[1][n1], Ah[1], Bh[2], Bh[3]);
                    }
                }
            }
        }
        __syncthreads();
    }

    // ---- fused gate + ReLU epilogue: fp16 NHWC only ----
    const int g  = lane >> 2;
    const int t4 = lane & 3;
    __half* o16 = g16[layer] + ((u64)b*HWn + (u64)y*Wn)*Cn;

#pragma unroll
    for (int mt = 0; mt < 2; ++mt) {
        const int xA = xbase + mt*16 + g;
        const int xB = xA + 8;
        const float spA = spa[b*HWn + y*Wn + xA];
        const float spB = spa[b*HWn + y*Wn + xB];
#pragma unroll
        for (int nt = 0; nt < 4; ++nt) {
            const int o0 = obase + nt*8 + 2*t4, o1 = o0 + 1;
            float r0, r1, r2, r3;
            if (!DUAL) {
                r0 = accF[mt][nt][0] * (s_ms[o0]*spA + s_md[o0]);
                r1 = accF[mt][nt][1] * (s_ms[o1]*spA + s_md[o1]);
                r2 = accF[mt][nt][2] * (s_ms[o0]*spB + s_md[o0]);
                r3 = accF[mt][nt][3] * (s_ms[o1]*spB + s_md[o1]);
            } else {
                r0 = accD[mt][nt][0]*s_md[o0]*(1.f-spA) + accF[mt][nt][0]*spA;
                r1 = accD[mt][nt][1]*s_md[o1]*(1.f-spA) + accF[mt][nt][1]*spA;
                r2 = accD[mt][nt][2]*s_md[o0]*(1.f-spB) + accF[mt][nt][2]*spB;
                r3 = accD[mt][nt][3]*s_md[o1]*(1.f-spB) + accF[mt][nt][3]*spB;
            }
            r0 = fmaxf(r0, 0.f); r1 = fmaxf(r1, 0.f);
            r2 = fmaxf(r2, 0.f); r3 = fmaxf(r3, 0.f);
            *(__half2*)(o16 + (u64)xA*Cn + o0) = __floats2half2_rn(r0, r1);
            *(__half2*)(o16 + (u64)xB*Cn + o0) = __floats2half2_rn(r2, r3);
        }
    }
}

// ---------------------------------------------------------------------------
// Final 1x1 conv on tensor cores: out[b,o,px] = bc[o] + sum_l sum_ci
//   wc[o, l*64+ci] * g16[l][b,px,ci].   M=256 px, N=64, K=256.
// CTA = (px-block, b), 512 threads, warp tile M32 x N32.
// ---------------------------------------------------------------------------
__global__ void __launch_bounds__(512, 1)
final_mma(const float* __restrict__ bc, float* __restrict__ outp)
{
    extern __shared__ __align__(128) char sm[];
    const u32 smb  = (u32)__cvta_generic_to_shared(sm);
    const int tid  = threadIdx.x;
    const int lane = tid & 31;
    const int wid  = tid >> 5;

    const int px0 = blockIdx.x * 256;
    const int b   = blockIdx.y;

    // stage B (wc fp16): 64 o x 512B rows, padded stride 528   -> group 0
#pragma unroll
    for (int it = 0; it < 4; ++it) {
        int idx = tid + it*512;          // 2048 chunks
        int o = idx >> 5, seg = idx & 31;
        cp16(smb + F_OFF_B + (u32)(o*FB_O_STRIDE + seg*16),
             (const char*)(g_wc + o*256) + seg*16);
    }
    cp_commit();

    auto stageA = [&](int l, int bi){
        const __half* src = g16[l] + ((u64)b*HWn + (u64)px0)*Cn;
        const u32 dst = smb + F_OFF_A + (u32)bi*FA_BUF_STRIDE;
#pragma unroll
        for (int it = 0; it < 4; ++it) {
            int idx = tid + it*512;      // 2048 chunks: 256 px x 8 seg
            int px = idx >> 3, seg = idx & 7;
            cp16(dst + (u32)(px*FA_PX_STRIDE + seg*16),
                 (const char*)(src + (u64)px*Cn) + seg*16);
        }
        cp_commit();
    };
    stageA(0, 0);    // group 1

    const int mq = wid & 7;              // M32 tile index
    const int nq = wid >> 3;             // N half
    const int obase = nq << 5;

    const u32 a_lane = (u32)((lane & 15)*FA_PX_STRIDE + ((lane >> 4) << 4));
    const int lrow = lane & 7, lgrp = lane >> 3;
    const u32 b_lane = (u32)(((lgrp >> 1)*8 + lrow)*FB_O_STRIDE + (lgrp & 1)*16);

    float acc[2][4][4];
#pragma unroll
    for (int mt = 0; mt < 2; ++mt)
#pragma unroll
        for (int n = 0; n < 4; ++n)
#pragma unroll
            for (int j = 0; j < 4; ++j) acc[mt][n][j] = 0.f;

#pragma unroll 1
    for (int l = 0; l < 4; ++l) {
        const int bi = l & 1;
        if (l < 3) stageA(l+1, bi^1);
        if (l < 3) cp_wait<1>(); else cp_wait<0>();
        __syncthreads();

        const u32 abase = smb + F_OFF_A + (u32)bi*FA_BUF_STRIDE
                        + (u32)(mq*32*FA_PX_STRIDE) + a_lane;
        const u32 wbase = smb + F_OFF_B + (u32)(obase*FB_O_STRIDE)
                        + (u32)(l*128) + b_lane;
#pragma unroll
        for (int kk = 0; kk < 4; ++kk) {
            u32 Ah[2][4];
            ldmat4(Ah[0], abase + kk*32);
            ldmat4(Ah[1], abase + 16*FA_PX_STRIDE + kk*32);
#pragma unroll
            for (int ntp = 0; ntp < 2; ++ntp) {
                const u32 wb = wbase + (u32)(ntp*16*FB_O_STRIDE + kk*32);
                const int n0 = ntp*2, n1 = n0 + 1;
                u32 Bh[4];
                ldmat4(Bh, wb);
                mma16816(acc[0][n0], Ah[0], Bh[0], Bh[1]);
                mma16816(acc[0][n1], Ah[0], Bh[2], Bh[3]);
                mma16816(acc[1][n0], Ah[1], Bh[0], Bh[1]);
                mma16816(acc[1][n1], Ah[1], Bh[2], Bh[3]);
            }
        }
        __syncthreads();
    }

    // epilogue: + bias, fp32 NCHW out
    const int g  = lane >> 2;
    const int t4 = lane & 3;
    float* ob = outp + (u64)b*IMG + px0;

#pragma unroll
    for (int mt = 0; mt < 2; ++mt) {
        const int xA = mq*32 + mt*16 + g;
        const int xB = xA + 8;
#pragma unroll
        for (int nt = 0; nt < 4; ++nt) {
            const int o0 = obase + nt*8 + 2*t4, o1 = o0 + 1;
            ob[o0*HWn + xA] = acc[mt][nt][0] + bc[o0];
            ob[o1*HWn + xA] = acc[mt][nt][1] + bc[o1];
            ob[o0*HWn + xB] = acc[mt][nt][2] + bc[o0];
            ob[o1*HWn + xB] = acc[mt][nt][3] + bc[o1];
        }
    }
}

// ---------------------------------------------------------------------------
extern "C" void kernel_launch(void* const* d_in, const int* in_sizes, int n_in,
                              void* d_out, int out_size)
{
    const float* x0  = (const float*)d_in[0];
    const float* spa = (const float*)d_in[1];
    const float* gum = (const float*)d_in[2];
    const float* par = (const float*)d_in[3];
    const float* w0  = (const float*)d_in[4];
    const float* w1  = (const float*)d_in[5];
    const float* w2  = (const float*)d_in[6];
    const float* w3  = (const float*)d_in[7];
    const float* wc  = (const float*)d_in[8];
    const float* bc  = (const float*)d_in[9];

    float* outp = (float*)d_out;
    float* tail = outp + (out_size - 512);   // ch_mask (1,64,4,2) after main out

    cudaFuncSetAttribute(conv_mma<false>,
                         cudaFuncAttributeMaxDynamicSharedMemorySize, SMEM_MMA);
    cudaFuncSetAttribute(conv_mma<true>,
                         cudaFuncAttributeMaxDynamicSharedMemorySize, SMEM_MMA);
    cudaFuncSetAttribute(final_mma,
                         cudaFuncAttributeMaxDynamicSharedMemorySize, SMEM_FIN);

    mask_kernel<<<1, 64>>>(gum, par, tail);
    prep_kernel<<<(4*9*Cn*Cn + 64*256 + 255)/256, 256>>>(w0, w1, w2, w3, wc);
    cvt_kernel<<<dim3(Hn, Bn), 256>>>(x0);

    dim3 grid(Hn/2, Bn);    // (y-pair, batch) = 64 x 16 = 1024 CTAs
    conv_mma<false><<<grid, 512, SMEM_MMA>>>(spa, 0);
    conv_mma<true ><<<grid, 512, SMEM_MMA>>>(spa, 1);
    conv_mma<true ><<<grid, 512, SMEM_MMA>>>(spa, 2);
    conv_mma<true ><<<grid, 512, SMEM_MMA>>>(spa, 3);

    final_mma<<<dim3(HWn/256, Bn), 512, SMEM_FIN>>>(bc, outp);
}